// round 13
// baseline (speedup 1.0000x reference)
#include <cuda_runtime.h>
#include <cuda_bf16.h>
#include <math.h>
#include <stdint.h>

// ---------------- problem constants ----------------
#define BD     8          // batch
#define HEADS  8
#define DH     32         // dim head
#define CDIM   256        // model dim
#define FFI    1024       // ff inner
#define HW     4096       // 64*64 pixels
#define WID    64
#define NBH    64         // BD*HEADS
#define NKEY   256        // TOP_H * TOP_W

// ---------------- scratch (device globals: no allocs allowed) ----------------
__device__ float g_xn  [(long)BD*CDIM*HW];   // LN(x); reused for ff2 output
__device__ float g_qkv [(long)BD*768*HW];
__device__ float g_attn[(long)BD*CDIM*HW];
__device__ float g_cat [(long)BD*512*HW];
__device__ float g_ao  [(long)BD*CDIM*HW];
__device__ float g_h   [(long)BD*FFI*HW];
__device__ float g_hg  [(long)BD*FFI*HW];
__device__ float g_kg  [NBH*DH*16*WID];
__device__ float g_vg  [NBH*DH*16*WID];
__device__ uint32_t g_kf [NBH*NKEY*16];      // bf16x2 packed
__device__ uint32_t g_vf [NBH*NKEY*16];
__device__ float g_qp  [NBH*DH];
__device__ float g_kh  [NBH*DH*WID];
__device__ int   g_topH[NBH*16];
__device__ int   g_topW[NBH*16];

// ---------------- channel layernorm (per pixel over 256 channels) ----------------
__global__ __launch_bounds__(256) void ln_kernel(const float* __restrict__ x,
                                                 const float* __restrict__ g,
                                                 const float* __restrict__ be,
                                                 float* __restrict__ out)
{
    int gp = blockIdx.x * 256 + threadIdx.x;           // 0..32767
    int b = gp >> 12, p = gp & 4095;
    const float* base = x + (long)b * CDIM * HW + p;
    float s = 0.f, s2 = 0.f;
    #pragma unroll 8
    for (int c = 0; c < CDIM; c++) { float v = base[(long)c * HW]; s += v; s2 += v * v; }
    float mean = s * (1.f / CDIM);
    float var  = s2 * (1.f / CDIM) - mean * mean;
    float inv  = rsqrtf(var + 1e-5f);
    float* ob = out + (long)b * CDIM * HW + p;
    #pragma unroll 8
    for (int c = 0; c < CDIM; c++) {
        float v = base[(long)c * HW];
        ob[(long)c * HW] = (v - mean) * inv * g[c] + be[c];
    }
}

// ---------------- TF32 tensor-core GEMM, fragment-packed + double-buffered --------
// C[z] = A(MxK) * B[z](KxN) (+bias)(+res).  A row-major shared across batch;
// B/C/res batched by stride.  M,N %128==0, K %16==0.
// 128x128 block tile, 8 warps (2x4), 64x32 warp tile, m16n8k8 tf32 mma.
// S3=1: 3xTF32 (bb+bs+sb) near-fp32 accuracy.  S3=0: single-pass TF32.

__device__ __forceinline__ uint32_t f2tf(float x)
{
    uint32_t r;
    asm("cvt.rna.tf32.f32 %0, %1;" : "=r"(r) : "f"(x));
    return r;
}

#define MMA_TF32(c, a0, a1, a2, a3, b0, b1) \
    asm volatile("mma.sync.aligned.m16n8k8.row.col.f32.tf32.tf32.f32 " \
        "{%0,%1,%2,%3}, {%4,%5,%6,%7}, {%8,%9}, {%0,%1,%2,%3};" \
        : "+f"((c)[0]), "+f"((c)[1]), "+f"((c)[2]), "+f"((c)[3]) \
        : "r"(a0), "r"(a1), "r"(a2), "r"(a3), "r"(b0), "r"(b1))

#define AFRAG_STRIDE 132     // 128 words + pad
#define BFRAG_STRIDE 66      // 64 words + pad
#define AWORDS (16 * AFRAG_STRIDE)
#define BWORDS (32 * BFRAG_STRIDE)
#define TGEMM_SMEM(S3) (2 * ((S3) ? 2 : 1) * (AWORDS + BWORDS) * 4)

template <int S3>
__global__ __launch_bounds__(256) void tgemm_kernel(
    const float* __restrict__ A, const float* __restrict__ B, float* __restrict__ C,
    int M, int N, int K, long strideB, long strideC,
    const float* __restrict__ bias, const float* __restrict__ res, long strideRes)
{
    constexpr int STAGE = (S3 ? 2 : 1) * (AWORDS + BWORDS);
    extern __shared__ uint32_t sh[];
    int tid = threadIdx.x;
    int lane = tid & 31, warp = tid >> 5;
    int bx = blockIdx.x * 128, by = blockIdx.y * 128;
    const float* Bp = B + (long)blockIdx.z * strideB;
    float*       Cp = C + (long)blockIdx.z * strideC;

    float acc[4][4][4];
    #pragma unroll
    for (int i = 0; i < 4; i++)
        #pragma unroll
        for (int j = 0; j < 4; j++)
            #pragma unroll
            for (int k = 0; k < 4; k++) acc[i][j][k] = 0.f;

    int sA0f = tid >> 5, sA0l = tid & 31;
    int sA1f = (tid + 256) >> 5, sA1l = tid & 31;
    long aOff0 = (long)(by + (sA0f >> 1) * 16 + (sA0l >> 2)) * K + (sA0f & 1) * 8 + (sA0l & 3);
    long aOff1 = (long)(by + (sA1f >> 1) * 16 + (sA1l >> 2)) * K + (sA1f & 1) * 8 + (sA1l & 3);
    int bK0 = tid >> 5, bN0 = (tid & 31) * 4;
    int bK1 = (tid + 256) >> 5, bN1 = (tid & 31) * 4;

    float pa[8];
    float4 pb[2];

    {
        const float* ap0 = A + aOff0; const float* ap1 = A + aOff1;
        pa[0] = ap0[0]; pa[1] = ap0[8 * K]; pa[2] = ap0[4]; pa[3] = ap0[8 * K + 4];
        pa[4] = ap1[0]; pa[5] = ap1[8 * K]; pa[6] = ap1[4]; pa[7] = ap1[8 * K + 4];
        pb[0] = *(const float4*)(Bp + (long)bK0 * N + bx + bN0);
        pb[1] = *(const float4*)(Bp + (long)bK1 * N + bx + bN1);
    }

    int nIter = K >> 4;

    // stage helper (macro-free lambda)
    auto stage = [&](uint32_t* base) {
        uint32_t* AsB = base;
        uint32_t* AsS = base + AWORDS;
        uint32_t* BsB = base + (S3 ? 2 : 1) * AWORDS;
        uint32_t* BsS = BsB + BWORDS;
        #pragma unroll
        for (int u = 0; u < 2; u++) {
            int f = u ? sA1f : sA0f, ls = u ? sA1l : sA0l;
            uint32_t bg[4], sm[4];
            #pragma unroll
            for (int j = 0; j < 4; j++) {
                float v = pa[u * 4 + j];
                bg[j] = f2tf(v);
                if (S3) sm[j] = f2tf(v - __uint_as_float(bg[j]));
            }
            *(uint4*)&AsB[f * AFRAG_STRIDE + ls * 4] = make_uint4(bg[0], bg[1], bg[2], bg[3]);
            if (S3)
                *(uint4*)&AsS[f * AFRAG_STRIDE + ls * 4] = make_uint4(sm[0], sm[1], sm[2], sm[3]);
            int kb = u ? bK1 : bK0, nb = u ? bN1 : bN0;
            float bv[4] = { pb[u].x, pb[u].y, pb[u].z, pb[u].w };
            #pragma unroll
            for (int j = 0; j < 4; j++) {
                int n = nb + j;
                int fB = (n >> 3) * 2 + (kb >> 3);
                int bl = ((n & 7) << 2) | (kb & 3);
                int rg = (kb >> 2) & 1;
                uint32_t big = f2tf(bv[j]);
                BsB[fB * BFRAG_STRIDE + bl * 2 + rg] = big;
                if (S3)
                    BsS[fB * BFRAG_STRIDE + bl * 2 + rg] = f2tf(bv[j] - __uint_as_float(big));
            }
        }
    };

    stage(sh);
    __syncthreads();

    int wmt = (warp >> 2) * 4;
    int wnt = (warp & 3) * 4;

    for (int it = 0; it < nIter; it++) {
        if (it + 1 < nIter) {
            int k0 = (it + 1) << 4;
            const float* ap0 = A + aOff0 + k0; const float* ap1 = A + aOff1 + k0;
            pa[0] = ap0[0]; pa[1] = ap0[8 * K]; pa[2] = ap0[4]; pa[3] = ap0[8 * K + 4];
            pa[4] = ap1[0]; pa[5] = ap1[8 * K]; pa[6] = ap1[4]; pa[7] = ap1[8 * K + 4];
            pb[0] = *(const float4*)(Bp + (long)(k0 + bK0) * N + bx + bN0);
            pb[1] = *(const float4*)(Bp + (long)(k0 + bK1) * N + bx + bN1);
        }
        {
            uint32_t* base = sh + (it & 1) * STAGE;
            const uint32_t* AsB = base;
            const uint32_t* AsS = base + AWORDS;
            const uint32_t* BsB = base + (S3 ? 2 : 1) * AWORDS;
            const uint32_t* BsS = BsB + BWORDS;
            #pragma unroll
            for (int ks = 0; ks < 2; ks++) {
                uint2 bB[4], bS[4];
                #pragma unroll
                for (int nt = 0; nt < 4; nt++) {
                    int fB = (wnt + nt) * 2 + ks;
                    bB[nt] = *(const uint2*)&BsB[fB * BFRAG_STRIDE + lane * 2];
                    if (S3) bS[nt] = *(const uint2*)&BsS[fB * BFRAG_STRIDE + lane * 2];
                }
                #pragma unroll
                for (int mt = 0; mt < 4; mt++) {
                    int fA = (wmt + mt) * 2 + ks;
                    uint4 aB = *(const uint4*)&AsB[fA * AFRAG_STRIDE + lane * 4];
                    #pragma unroll
                    for (int nt = 0; nt < 4; nt++)
                        MMA_TF32(acc[mt][nt], aB.x, aB.y, aB.z, aB.w, bB[nt].x, bB[nt].y);
                    if (S3) {
                        uint4 aS = *(const uint4*)&AsS[fA * AFRAG_STRIDE + lane * 4];
                        #pragma unroll
                        for (int nt = 0; nt < 4; nt++)
                            MMA_TF32(acc[mt][nt], aB.x, aB.y, aB.z, aB.w, bS[nt].x, bS[nt].y);
                        #pragma unroll
                        for (int nt = 0; nt < 4; nt++)
                            MMA_TF32(acc[mt][nt], aS.x, aS.y, aS.z, aS.w, bB[nt].x, bB[nt].y);
                    }
                }
            }
        }
        if (it + 1 < nIter) stage(sh + ((it + 1) & 1) * STAGE);
        __syncthreads();
    }

    int wm = (warp >> 2) * 64, wn = (warp & 3) * 32;
    int mr = lane >> 2, qc = (lane & 3) * 2;
    #pragma unroll
    for (int mt = 0; mt < 4; mt++) {
        int r0 = by + wm + mt * 16 + mr;
        float bb0 = bias ? bias[r0] : 0.f;
        float bb1 = bias ? bias[r0 + 8] : 0.f;
        #pragma unroll
        for (int nt = 0; nt < 4; nt++) {
            int c = bx + wn + nt * 8 + qc;
            long o0 = (long)r0 * N + c;
            long o1 = (long)(r0 + 8) * N + c;
            float2 v0 = make_float2(acc[mt][nt][0] + bb0, acc[mt][nt][1] + bb0);
            float2 v1 = make_float2(acc[mt][nt][2] + bb1, acc[mt][nt][3] + bb1);
            if (res) {
                const float* rp = res + (long)blockIdx.z * strideRes;
                v0.x += rp[o0]; v0.y += rp[o0 + 1];
                v1.x += rp[o1]; v1.y += rp[o1 + 1];
            }
            *(float2*)&Cp[o0] = v0;
            *(float2*)&Cp[o1] = v1;
        }
    }
}

// ---------------- l2-normalize q,k rows (along W=64) in place ----------------
__global__ __launch_bounds__(256) void l2norm_kernel(float* __restrict__ qkv)
{
    int gt = blockIdx.x * 256 + threadIdx.x;
    int warp = gt >> 5, lane = gt & 31;
    if (warp >= BD * 512 * WID) return;
    int b = warp / (512 * WID);
    int rem = warp % (512 * WID);
    float* p = qkv + (long)b * 768 * HW + (long)rem * WID;
    float v0 = p[lane], v1 = p[lane + 32];
    float s = v0 * v0 + v1 * v1;
    #pragma unroll
    for (int o = 16; o > 0; o >>= 1) s += __shfl_xor_sync(0xffffffffu, s, o);
    float scale = 1.f / fmaxf(sqrtf(s), 1e-12f);
    p[lane] = v0 * scale; p[lane + 32] = v1 * scale;
}

// ---------------- q_probe[bh][d] = sum over all pixels of normalized q ----------------
__global__ __launch_bounds__(256) void qprobe_kernel(const float* __restrict__ qkv,
                                                     float* __restrict__ qp)
{
    __shared__ float sm[8];
    int c = blockIdx.x;                     // 0..2047 = bh*32+d
    int bh = c >> 5, d = c & 31, b = bh >> 3, hh = bh & 7;
    const float4* p = (const float4*)(qkv + (long)b * 768 * HW + (long)(hh * 32 + d) * HW);
    float s = 0.f;
    #pragma unroll
    for (int i = 0; i < 4; i++) {
        float4 v = p[threadIdx.x + i * 256];
        s += v.x + v.y + v.z + v.w;
    }
    #pragma unroll
    for (int o = 16; o > 0; o >>= 1) s += __shfl_xor_sync(0xffffffffu, s, o);
    if ((threadIdx.x & 31) == 0) sm[threadIdx.x >> 5] = s;
    __syncthreads();
    if (threadIdx.x == 0) { float t = 0; for (int i = 0; i < 8; i++) t += sm[i]; qp[c] = t; }
}

// ---------------- k_height[bh][d][h] = sum over w of normalized k ----------------
__global__ __launch_bounds__(256) void kheight_kernel(const float* __restrict__ qkv,
                                                      float* __restrict__ kh)
{
    int gt = blockIdx.x * 256 + threadIdx.x;
    int warp = gt >> 5, lane = gt & 31;
    if (warp >= NBH * DH * WID) return;
    int h = warp & 63; int rest = warp >> 6; int d = rest & 31; int bh = rest >> 5;
    int b = bh >> 3, hh = bh & 7;
    const float* p = qkv + (long)b * 768 * HW + (long)(256 + hh * 32 + d) * HW + h * WID;
    float s = p[lane] + p[lane + 32];
    #pragma unroll
    for (int o = 16; o > 0; o >>= 1) s += __shfl_xor_sync(0xffffffffu, s, o);
    if (lane == 0) kh[warp] = s;
}

// ---------------- score_r + top-16 rows (set only; order irrelevant downstream) ---------
__global__ void toph_kernel(const float* __restrict__ qp, const float* __restrict__ kh,
                            int* __restrict__ topH)
{
    __shared__ float sc[64]; __shared__ float qs[32];
    int bh = blockIdx.x, t = threadIdx.x;                  // 64 threads
    if (t < 32) qs[t] = qp[bh * 32 + t];
    __syncthreads();
    float s = 0.f;
    #pragma unroll
    for (int d = 0; d < 32; d++) s += qs[d] * kh[((bh * 32 + d) << 6) + t];
    sc[t] = s;
    __syncthreads();
    if (t == 0) {
        for (int it = 0; it < 16; it++) {
            float best = -3.4e38f; int bi = 0;
            for (int h = 0; h < 64; h++) if (sc[h] > best) { best = sc[h]; bi = h; }
            topH[bh * 16 + it] = bi; sc[bi] = -3.4e38f;
        }
    }
}

// ---------------- gather selected rows of k,v -> kg/vg [bh][d][16][64] -----------------
__global__ __launch_bounds__(256) void gather_rows_kernel(const float* __restrict__ qkv,
                                                          const int* __restrict__ topH,
                                                          float* __restrict__ kg,
                                                          float* __restrict__ vg)
{
    long i = (long)blockIdx.x * 256 + threadIdx.x;          // 64*32*16*64
    int w = i & 63; long r = i >> 6; int t = (int)(r & 15); r >>= 4;
    int d = (int)(r & 31); int bh = (int)(r >> 5);
    int b = bh >> 3, hh = bh & 7;
    int h = topH[bh * 16 + t];
    long base = (long)b * 768 * HW + (long)(hh * 32 + d) * HW + (long)h * WID + w;
    kg[i] = qkv[base + 256L * HW];
    vg[i] = qkv[base + 512L * HW];
}

// ---------------- score_c + top-16 columns ----------------
__global__ void topw_kernel(const float* __restrict__ qp, const float* __restrict__ kg,
                            int* __restrict__ topW)
{
    __shared__ float sc[64]; __shared__ float qs[32];
    int bh = blockIdx.x, t = threadIdx.x;                  // t = w, 64 threads
    if (t < 32) qs[t] = qp[bh * 32 + t];
    __syncthreads();
    float s = 0.f;
    for (int d = 0; d < 32; d++) {
        float colsum = 0.f;
        #pragma unroll
        for (int i = 0; i < 16; i++)
            colsum += kg[(((long)(bh * 32 + d) * 16) + i) * 64 + t];
        s += qs[d] * colsum;
    }
    sc[t] = s;
    __syncthreads();
    if (t == 0) {
        for (int it = 0; it < 16; it++) {
            float best = -3.4e38f; int bi = 0;
            for (int w = 0; w < 64; w++) if (sc[w] > best) { best = sc[w]; bi = w; }
            topW[bh * 16 + it] = bi; sc[bi] = -3.4e38f;
        }
    }
}

// ---------------- build kf/vf [bh][j][d2] as bf16x2, j = i*16 + jw ----------------
__global__ __launch_bounds__(256) void build_kv_kernel(const float* __restrict__ kg,
                                                       const float* __restrict__ vg,
                                                       const int* __restrict__ topW,
                                                       uint32_t* __restrict__ kf,
                                                       uint32_t* __restrict__ vf)
{
    int i = blockIdx.x * 256 + threadIdx.x;   // 64*256*16 = 262144
    int d2 = i & 15; int j = (i >> 4) & 255; int bh = i >> 12;
    int ti = j >> 4, jw = j & 15;
    int w = topW[bh * 16 + jw];
    long src = (((long)(bh * 32 + 2 * d2) * 16) + ti) * 64 + w;
    __nv_bfloat162 kk = __floats2bfloat162_rn(kg[src], kg[src + 1024]);
    __nv_bfloat162 vv = __floats2bfloat162_rn(vg[src], vg[src + 1024]);
    kf[i] = *(uint32_t*)&kk;
    vf[i] = *(uint32_t*)&vv;
}

// ---------------- fused sparse attention: softmax(Q Kf^T) Vf, bf16 K/V ----------------
__device__ __forceinline__ float2 bf2f(uint32_t u)
{
    __nv_bfloat162 h = *reinterpret_cast<__nv_bfloat162*>(&u);
    return __bfloat1622float2(h);
}

__global__ __launch_bounds__(128) void attn_kernel(const float* __restrict__ qkv,
                                                   const uint32_t* __restrict__ kf,
                                                   const uint32_t* __restrict__ vf,
                                                   float* __restrict__ out)
{
    __shared__ uint32_t kfs[128 * 16];
    __shared__ uint32_t vfs[128 * 16];
    int bh = blockIdx.y;
    int b = bh >> 3, hh = bh & 7;
    int p = blockIdx.x * 128 + threadIdx.x;
    const float* qb = qkv + (long)b * 768 * HW + (long)(hh * 32) * HW + p;
    float q[32], acc[32];
    #pragma unroll
    for (int d = 0; d < 32; d++) { q[d] = qb[(long)d * HW]; acc[d] = 0.f; }
    float l = 0.f;
    for (int ch = 0; ch < 2; ch++) {
        const uint4* kc = (const uint4*)(kf + ((long)bh * NKEY + ch * 128) * 16);
        const uint4* vc = (const uint4*)(vf + ((long)bh * NKEY + ch * 128) * 16);
        #pragma unroll
        for (int i = 0; i < 4; i++) {
            ((uint4*)kfs)[threadIdx.x + i * 128] = kc[threadIdx.x + i * 128];
            ((uint4*)vfs)[threadIdx.x + i * 128] = vc[threadIdx.x + i * 128];
        }
        __syncthreads();
        for (int j = 0; j < 128; j++) {
            const uint32_t* kk = &kfs[j * 16];
            float s = 0.f;
            #pragma unroll
            for (int d2 = 0; d2 < 16; d2++) {
                float2 f = bf2f(kk[d2]);
                s = fmaf(f.x, q[2 * d2], s);
                s = fmaf(f.y, q[2 * d2 + 1], s);
            }
            float e = __expf(s);
            l += e;
            const uint32_t* vv = &vfs[j * 16];
            #pragma unroll
            for (int d2 = 0; d2 < 16; d2++) {
                float2 f = bf2f(vv[d2]);
                acc[2 * d2]     = fmaf(e, f.x, acc[2 * d2]);
                acc[2 * d2 + 1] = fmaf(e, f.y, acc[2 * d2 + 1]);
            }
        }
        __syncthreads();
    }
    float inv = 1.f / l;
    float* ob = out + (long)b * CDIM * HW + (long)(hh * 32) * HW + p;
    #pragma unroll
    for (int d = 0; d < 32; d++) ob[(long)d * HW] = acc[d] * inv;
}

// ---------------- depthwise 3x3 SAME (small branch, writes into cat) ----------------
__global__ __launch_bounds__(256) void dwconv_kernel(const float* __restrict__ in,
                                                     const float* __restrict__ w,
                                                     const float* __restrict__ bias,
                                                     float* __restrict__ out,
                                                     int C, long inBS, long outBS, int chanOff)
{
    int idx = blockIdx.x;
    int yt = idx & 15; idx >>= 4;
    int c = idx % C; int b = idx / C;
    int x = threadIdx.x & 63;
    int y = yt * 4 + (threadIdx.x >> 6);
    const float* ip = in + (long)b * inBS + (long)c * HW;
    const float* wp = w + c * 9;
    float s = bias[c];
    #pragma unroll
    for (int dy = 0; dy < 3; dy++) {
        int yy = y + dy - 1;
        if (yy < 0 || yy > 63) continue;
        #pragma unroll
        for (int dx = 0; dx < 3; dx++) {
            int xx = x + dx - 1;
            if (xx < 0 || xx > 63) continue;
            s += wp[dy * 3 + dx] * ip[yy * 64 + xx];
        }
    }
    out[(long)b * outBS + (long)(chanOff + c) * HW + y * 64 + x] = s;
}

// ---------------- gelu ----------------
__device__ __forceinline__ float gelu_exact(float u)
{
    return 0.5f * u * (1.f + erff(u * 0.7071067811865476f));
}

// ---------------- fused dwconv3x3 + instnorm + gelu + add:  h = hg + gelu(IN(dw(hg)))
// one block per (b,c) row; channel tile staged in smem.
__global__ __launch_bounds__(256) void dwin_kernel(const float* __restrict__ hg,
                                                   const float* __restrict__ w,
                                                   const float* __restrict__ bias,
                                                   float* __restrict__ out)
{
    __shared__ float tile[HW];
    __shared__ float red[16];
    long row = blockIdx.x;
    int c = (int)(row & (FFI - 1));
    int t = threadIdx.x;
    const float4* src = (const float4*)(hg + row * HW);
    #pragma unroll
    for (int i = 0; i < 4; i++) ((float4*)tile)[t + i * 256] = src[t + i * 256];
    float wr[9];
    #pragma unroll
    for (int i = 0; i < 9; i++) wr[i] = w[c * 9 + i];
    float bb = bias[c];
    __syncthreads();

    float r[16];
    float s = 0.f, s2 = 0.f;
    #pragma unroll
    for (int i = 0; i < 16; i++) {
        int px = t + i * 256;
        int y = px >> 6, x = px & 63;
        float a = bb;
        #pragma unroll
        for (int dy = 0; dy < 3; dy++) {
            int yy = y + dy - 1;
            if (yy < 0 || yy > 63) continue;
            #pragma unroll
            for (int dx = 0; dx < 3; dx++) {
                int xx = x + dx - 1;
                if (xx < 0 || xx > 63) continue;
                a += wr[dy * 3 + dx] * tile[yy * 64 + xx];
            }
        }
        r[i] = a; s += a; s2 += a * a;
    }
    #pragma unroll
    for (int o = 16; o > 0; o >>= 1) {
        s  += __shfl_xor_sync(0xffffffffu, s, o);
        s2 += __shfl_xor_sync(0xffffffffu, s2, o);
    }
    if ((t & 31) == 0) { red[t >> 5] = s; red[8 + (t >> 5)] = s2; }
    __syncthreads();
    if (t == 0) {
        float a = 0.f, b2 = 0.f;
        for (int i = 0; i < 8; i++) { a += red[i]; b2 += red[8 + i]; }
        red[0] = a; red[8] = b2;
    }
    __syncthreads();
    float mean = red[0] * (1.f / HW);
    float var  = red[8] * (1.f / HW) - mean * mean;
    float inv  = rsqrtf(var + 1e-5f);
    float* ob = out + row * HW;
    #pragma unroll
    for (int i = 0; i < 16; i++) {
        int px = t + i * 256;
        ob[px] = tile[px] + gelu_exact((r[i] - mean) * inv);
    }
}

// ---------------- instance norm (+gelu) ----------------
template <int MODE>  // 0: norm; 1: gelu(norm)
__global__ __launch_bounds__(256) void instnorm_kernel(const float* __restrict__ in,
                                                       float* __restrict__ out)
{
    __shared__ float sm[16];
    long row = blockIdx.x;
    const float4* p = (const float4*)(in + row * HW);
    int t = threadIdx.x;
    float4 v[4];
    float s = 0.f, s2 = 0.f;
    #pragma unroll
    for (int i = 0; i < 4; i++) {
        v[i] = p[t + i * 256];
        s  += v[i].x + v[i].y + v[i].z + v[i].w;
        s2 += v[i].x * v[i].x + v[i].y * v[i].y + v[i].z * v[i].z + v[i].w * v[i].w;
    }
    #pragma unroll
    for (int o = 16; o > 0; o >>= 1) {
        s  += __shfl_xor_sync(0xffffffffu, s, o);
        s2 += __shfl_xor_sync(0xffffffffu, s2, o);
    }
    if ((t & 31) == 0) { sm[t >> 5] = s; sm[8 + (t >> 5)] = s2; }
    __syncthreads();
    if (t == 0) {
        float a = 0.f, b2 = 0.f;
        for (int i = 0; i < 8; i++) { a += sm[i]; b2 += sm[8 + i]; }
        sm[0] = a; sm[8] = b2;
    }
    __syncthreads();
    float mean = sm[0] * (1.f / HW);
    float var  = sm[8] * (1.f / HW) - mean * mean;
    float inv  = rsqrtf(var + 1e-5f);
    float4* op = (float4*)(out + row * HW);
    #pragma unroll
    for (int i = 0; i < 4; i++) {
        float4 u = v[i];
        u.x = (u.x - mean) * inv; u.y = (u.y - mean) * inv;
        u.z = (u.z - mean) * inv; u.w = (u.w - mean) * inv;
        if (MODE >= 1) {
            u.x = gelu_exact(u.x); u.y = gelu_exact(u.y);
            u.z = gelu_exact(u.z); u.w = gelu_exact(u.w);
        }
        op[t + i * 256] = u;
    }
}

// ---------------- host launcher ----------------
extern "C" void kernel_launch(void* const* d_in, const int* in_sizes, int n_in,
                              void* d_out, int out_size)
{
    (void)in_sizes; (void)n_in; (void)out_size;
    const float* x      = (const float*)d_in[0];
    const float* ln_g   = (const float*)d_in[1];
    const float* ln_b   = (const float*)d_in[2];
    const float* w_qkv  = (const float*)d_in[3];
    const float* w_out  = (const float*)d_in[4];
    const float* b_out  = (const float*)d_in[5];
    const float* w_dw   = (const float*)d_in[6];
    const float* b_dw   = (const float*)d_in[7];
    const float* w_comb = (const float*)d_in[8];
    const float* b_comb = (const float*)d_in[9];
    const float* w_ff1  = (const float*)d_in[10];
    const float* b_ff1  = (const float*)d_in[11];
    const float* w_ffdw = (const float*)d_in[12];
    const float* b_ffdw = (const float*)d_in[13];
    const float* w_ff2  = (const float*)d_in[14];
    const float* b_ff2  = (const float*)d_in[15];
    float* out = (float*)d_out;

    void *p;
    cudaGetSymbolAddress(&p, g_xn);   float* xn   = (float*)p;
    cudaGetSymbolAddress(&p, g_qkv);  float* qkv  = (float*)p;
    cudaGetSymbolAddress(&p, g_attn); float* attn = (float*)p;
    cudaGetSymbolAddress(&p, g_cat);  float* cat  = (float*)p;
    cudaGetSymbolAddress(&p, g_ao);   float* ao   = (float*)p;
    cudaGetSymbolAddress(&p, g_h);    float* h    = (float*)p;
    cudaGetSymbolAddress(&p, g_hg);   float* hg   = (float*)p;
    cudaGetSymbolAddress(&p, g_kg);   float* kg   = (float*)p;
    cudaGetSymbolAddress(&p, g_vg);   float* vg   = (float*)p;
    cudaGetSymbolAddress(&p, g_kf);   uint32_t* kf = (uint32_t*)p;
    cudaGetSymbolAddress(&p, g_vf);   uint32_t* vf = (uint32_t*)p;
    cudaGetSymbolAddress(&p, g_qp);   float* qp   = (float*)p;
    cudaGetSymbolAddress(&p, g_kh);   float* kh   = (float*)p;
    cudaGetSymbolAddress(&p, g_topH); int*   topH = (int*)p;
    cudaGetSymbolAddress(&p, g_topW); int*   topW = (int*)p;

    cudaFuncSetAttribute(tgemm_kernel<1>, cudaFuncAttributeMaxDynamicSharedMemorySize,
                         TGEMM_SMEM(1));
    cudaFuncSetAttribute(tgemm_kernel<0>, cudaFuncAttributeMaxDynamicSharedMemorySize,
                         TGEMM_SMEM(0));

    // 1. channel layernorm
    ln_kernel<<<128, 256>>>(x, ln_g, ln_b, xn);
    // 2. qkv projection (3xTF32: protects downstream top-k selection)
    tgemm_kernel<1><<<dim3(32, 6, BD), 256, TGEMM_SMEM(1)>>>(w_qkv, xn, qkv, 768, HW, 256,
                                           (long)CDIM * HW, (long)768 * HW,
                                           nullptr, nullptr, 0);
    // 3. l2-normalize q,k along W (in place)
    l2norm_kernel<<<32768, 256>>>(qkv);
    // 4. probes + top-k selection
    qprobe_kernel<<<2048, 256>>>(qkv, qp);
    kheight_kernel<<<16384, 256>>>(qkv, kh);
    toph_kernel<<<64, 64>>>(qp, kh, topH);
    gather_rows_kernel<<<8192, 256>>>(qkv, topH, kg, vg);
    topw_kernel<<<64, 64>>>(qp, kg, topW);
    build_kv_kernel<<<1024, 256>>>(kg, vg, topW, kf, vf);
    // 5. fused sparse attention (bf16 K/V)
    attn_kernel<<<dim3(32, NBH), 128>>>(qkv, kf, vf, attn);
    // 6. out-proj into concat buffer rows [0,256)
    tgemm_kernel<1><<<dim3(32, 2, BD), 256, TGEMM_SMEM(1)>>>(w_out, attn, cat, 256, HW, 256,
                                           (long)CDIM * HW, (long)512 * HW,
                                           b_out, nullptr, 0);
    // 7. dwconv branch into concat buffer rows [256,512)
    dwconv_kernel<<<BD * 256 * 16, 256>>>(x, w_dw, b_dw, cat, 256,
                                          (long)CDIM * HW, (long)512 * HW, 256);
    // 8. combine (K=512) + bias + residual x
    tgemm_kernel<1><<<dim3(32, 2, BD), 256, TGEMM_SMEM(1)>>>(w_comb, cat, ao, 256, HW, 512,
                                           (long)512 * HW, (long)CDIM * HW,
                                           b_comb, x, (long)CDIM * HW);
    // 9. ff1 (single-pass TF32)
    tgemm_kernel<0><<<dim3(32, 8, BD), 256, TGEMM_SMEM(0)>>>(w_ff1, ao, h, FFI, HW, 256,
                                           (long)CDIM * HW, (long)FFI * HW,
                                           b_ff1, nullptr, 0);
    // 10. hg = gelu(instnorm(h))
    instnorm_kernel<1><<<BD * FFI, 256>>>(h, hg);
    // 11+12. h = hg + gelu(instnorm(dwconv(hg)))  -- fused
    dwin_kernel<<<BD * FFI, 256>>>(hg, w_ffdw, b_ffdw, h);
    // 13. ff2 (single-pass TF32; reuse xn buffer for output)
    tgemm_kernel<0><<<dim3(32, 2, BD), 256, TGEMM_SMEM(0)>>>(w_ff2, h, xn, 256, HW, 1024,
                                           (long)FFI * HW, (long)CDIM * HW,
                                           b_ff2, nullptr, 0);
    // 14. final instance norm -> d_out
    instnorm_kernel<0><<<BD * CDIM, 256>>>(xn, out);
}

// round 14
// speedup vs baseline: 1.1995x; 1.1995x over previous
#include <cuda_runtime.h>
#include <cuda_bf16.h>
#include <math.h>
#include <stdint.h>

// ---------------- problem constants ----------------
#define BD     8          // batch
#define HEADS  8
#define DH     32         // dim head
#define CDIM   256        // model dim
#define FFI    1024       // ff inner
#define HW     4096       // 64*64 pixels
#define WID    64
#define NBH    64         // BD*HEADS
#define NKEY   256        // TOP_H * TOP_W

// ---------------- scratch (device globals: no allocs allowed) ----------------
__device__ float g_xn  [(long)BD*CDIM*HW];   // LN(x); reused for ff2 output
__device__ float g_qkv [(long)BD*768*HW];
__device__ float g_attn[(long)BD*CDIM*HW];
__device__ float g_cat [(long)BD*512*HW];
__device__ float g_ao  [(long)BD*CDIM*HW];
__device__ float g_h   [(long)BD*FFI*HW];
__device__ float g_hg  [(long)BD*FFI*HW];
__device__ float g_kg  [NBH*DH*16*WID];
__device__ float g_vg  [NBH*DH*16*WID];
__device__ uint32_t g_kf [NBH*NKEY*16];      // bf16x2 packed
__device__ uint32_t g_vf [NBH*NKEY*16];
__device__ float g_qp  [NBH*DH];
__device__ float g_kh  [NBH*DH*WID];
__device__ int   g_topH[NBH*16];
__device__ int   g_topW[NBH*16];

// ---------------- channel layernorm (per pixel over 256 channels) ----------------
__global__ __launch_bounds__(256) void ln_kernel(const float* __restrict__ x,
                                                 const float* __restrict__ g,
                                                 const float* __restrict__ be,
                                                 float* __restrict__ out)
{
    int gp = blockIdx.x * 256 + threadIdx.x;           // 0..32767
    int b = gp >> 12, p = gp & 4095;
    const float* base = x + (long)b * CDIM * HW + p;
    float s = 0.f, s2 = 0.f;
    #pragma unroll 8
    for (int c = 0; c < CDIM; c++) { float v = base[(long)c * HW]; s += v; s2 += v * v; }
    float mean = s * (1.f / CDIM);
    float var  = s2 * (1.f / CDIM) - mean * mean;
    float inv  = rsqrtf(var + 1e-5f);
    float* ob = out + (long)b * CDIM * HW + p;
    #pragma unroll 8
    for (int c = 0; c < CDIM; c++) {
        float v = base[(long)c * HW];
        ob[(long)c * HW] = (v - mean) * inv * g[c] + be[c];
    }
}

// =====================================================================
// bf16x3 tensor-core GEMM (m16n8k16): near-fp32 accuracy, 3 mma / k16.
// C[z] = A(MxK) * B[z](KxN) (+bias)(+res).  M,N %128==0, K %16==0.
// 128x128 block tile, 8 warps (2x4), 64x32 warp tile.
// =====================================================================

__device__ __forceinline__ void bfsplit2(float x0, float x1,
                                         uint32_t& big, uint32_t& sml)
{
    __nv_bfloat162 b = __floats2bfloat162_rn(x0, x1);
    float2 bf = __bfloat1622float2(b);
    __nv_bfloat162 s = __floats2bfloat162_rn(x0 - bf.x, x1 - bf.y);
    big = *reinterpret_cast<uint32_t*>(&b);
    sml = *reinterpret_cast<uint32_t*>(&s);
}

#define MMA_BF16(c, a0, a1, a2, a3, b0, b1) \
    asm volatile("mma.sync.aligned.m16n8k16.row.col.f32.bf16.bf16.f32 " \
        "{%0,%1,%2,%3}, {%4,%5,%6,%7}, {%8,%9}, {%0,%1,%2,%3};" \
        : "+f"((c)[0]), "+f"((c)[1]), "+f"((c)[2]), "+f"((c)[3]) \
        : "r"(a0), "r"(a1), "r"(a2), "r"(a3), "r"(b0), "r"(b1))

#define BG_AFS 132                         // 128 words + pad per A frag
#define BG_BFS 66                          // 64 words + pad per B frag
#define BG_AW  (8 * BG_AFS)                // 1056
#define BG_BW  (16 * BG_BFS)               // 1056
#define BG_STAGE (2 * BG_AW + 2 * BG_BW)   // 4224 words
#define BGEMM_SMEM (2 * BG_STAGE * 4)      // 33792 B

__global__ __launch_bounds__(256) void bgemm_kernel(
    const float* __restrict__ A, const float* __restrict__ B, float* __restrict__ C,
    int M, int N, int K, long strideB, long strideC,
    const float* __restrict__ bias, const float* __restrict__ res, long strideRes)
{
    extern __shared__ uint32_t sh[];
    int tid = threadIdx.x;
    int lane = tid & 31, warp = tid >> 5;
    int bx = blockIdx.x * 128, by = blockIdx.y * 128;
    const float* Bp = B + (long)blockIdx.z * strideB;
    float*       Cp = C + (long)blockIdx.z * strideC;

    float acc[4][4][4];
    #pragma unroll
    for (int i = 0; i < 4; i++)
        #pragma unroll
        for (int j = 0; j < 4; j++)
            #pragma unroll
            for (int k = 0; k < 4; k++) acc[i][j][k] = 0.f;

    // A slot: thread -> (frag af 0..7, lane als); covers A rows by..by+127, k 0..15
    int af = tid >> 5, als = tid & 31;
    long aRow = by + af * 16 + (als >> 2);
    int  aK   = (als & 3) * 2;
    const float* aBase = A + aRow * K + aK;
    // B slots: thread handles slots tid and tid+256 -> frags fn0, fn0+8
    int bls = tid & 31;
    int bn0 = bx + (tid >> 5) * 8 + (bls >> 2);
    int bn1 = bn0 + 64;                       // frag fn+8 -> n += 64
    int bK  = (bls & 3) * 2;

    float2 pa[4];
    float  pbv[2][4];

    // prefetch tile 0
    {
        pa[0] = *(const float2*)(aBase);                 // (row0, k0..k0+1)
        pa[1] = *(const float2*)(aBase + 8);             // (row0, k0+8)
        pa[2] = *(const float2*)(aBase + 8 * K);         // (row0+8, k0)
        pa[3] = *(const float2*)(aBase + 8 * K + 8);     // (row0+8, k0+8)
        #pragma unroll
        for (int u = 0; u < 2; u++) {
            int n = u ? bn1 : bn0;
            pbv[u][0] = Bp[(long)(bK)     * N + n];
            pbv[u][1] = Bp[(long)(bK + 1) * N + n];
            pbv[u][2] = Bp[(long)(bK + 8) * N + n];
            pbv[u][3] = Bp[(long)(bK + 9) * N + n];
        }
    }

    int nIter = K >> 4;

    auto stage = [&](uint32_t* base) {
        uint32_t* AsB = base;
        uint32_t* AsS = base + BG_AW;
        uint32_t* BsB = base + 2 * BG_AW;
        uint32_t* BsS = BsB + BG_BW;
        // A: regs a0=(r,k) a1=(r+8,k) a2=(r,k+8) a3=(r+8,k+8)
        uint32_t a0b, a0s, a1b, a1s, a2b, a2s, a3b, a3s;
        bfsplit2(pa[0].x, pa[0].y, a0b, a0s);
        bfsplit2(pa[2].x, pa[2].y, a1b, a1s);
        bfsplit2(pa[1].x, pa[1].y, a2b, a2s);
        bfsplit2(pa[3].x, pa[3].y, a3b, a3s);
        *(uint4*)&AsB[af * BG_AFS + als * 4] = make_uint4(a0b, a1b, a2b, a3b);
        *(uint4*)&AsS[af * BG_AFS + als * 4] = make_uint4(a0s, a1s, a2s, a3s);
        #pragma unroll
        for (int u = 0; u < 2; u++) {
            int fn = (tid >> 5) + u * 8;
            uint32_t b0b, b0s, b1b, b1s;
            bfsplit2(pbv[u][0], pbv[u][1], b0b, b0s);
            bfsplit2(pbv[u][2], pbv[u][3], b1b, b1s);
            *(uint2*)&BsB[fn * BG_BFS + bls * 2] = make_uint2(b0b, b1b);
            *(uint2*)&BsS[fn * BG_BFS + bls * 2] = make_uint2(b0s, b1s);
        }
    };

    stage(sh);
    __syncthreads();

    int wmt = (warp >> 2) * 4;   // A frag base
    int wnt = (warp & 3) * 4;    // B frag base

    for (int it = 0; it < nIter; it++) {
        if (it + 1 < nIter) {
            int k0 = (it + 1) << 4;
            const float* ap = aBase + k0;
            pa[0] = *(const float2*)(ap);
            pa[1] = *(const float2*)(ap + 8);
            pa[2] = *(const float2*)(ap + 8 * K);
            pa[3] = *(const float2*)(ap + 8 * K + 8);
            #pragma unroll
            for (int u = 0; u < 2; u++) {
                int n = u ? bn1 : bn0;
                pbv[u][0] = Bp[(long)(k0 + bK)     * N + n];
                pbv[u][1] = Bp[(long)(k0 + bK + 1) * N + n];
                pbv[u][2] = Bp[(long)(k0 + bK + 8) * N + n];
                pbv[u][3] = Bp[(long)(k0 + bK + 9) * N + n];
            }
        }
        {
            uint32_t* base = sh + (it & 1) * BG_STAGE;
            const uint32_t* AsB = base;
            const uint32_t* AsS = base + BG_AW;
            const uint32_t* BsB = base + 2 * BG_AW;
            const uint32_t* BsS = BsB + BG_BW;
            uint2 bB[4], bS[4];
            #pragma unroll
            for (int nt = 0; nt < 4; nt++) {
                bB[nt] = *(const uint2*)&BsB[(wnt + nt) * BG_BFS + lane * 2];
                bS[nt] = *(const uint2*)&BsS[(wnt + nt) * BG_BFS + lane * 2];
            }
            #pragma unroll
            for (int mt = 0; mt < 4; mt++) {
                uint4 aB = *(const uint4*)&AsB[(wmt + mt) * BG_AFS + lane * 4];
                uint4 aS = *(const uint4*)&AsS[(wmt + mt) * BG_AFS + lane * 4];
                #pragma unroll
                for (int nt = 0; nt < 4; nt++)
                    MMA_BF16(acc[mt][nt], aB.x, aB.y, aB.z, aB.w, bB[nt].x, bB[nt].y);
                #pragma unroll
                for (int nt = 0; nt < 4; nt++)
                    MMA_BF16(acc[mt][nt], aB.x, aB.y, aB.z, aB.w, bS[nt].x, bS[nt].y);
                #pragma unroll
                for (int nt = 0; nt < 4; nt++)
                    MMA_BF16(acc[mt][nt], aS.x, aS.y, aS.z, aS.w, bB[nt].x, bB[nt].y);
            }
        }
        if (it + 1 < nIter) stage(sh + ((it + 1) & 1) * BG_STAGE);
        __syncthreads();
    }

    int wm = (warp >> 2) * 64, wn = (warp & 3) * 32;
    int mr = lane >> 2, qc = (lane & 3) * 2;
    #pragma unroll
    for (int mt = 0; mt < 4; mt++) {
        int r0 = by + wm + mt * 16 + mr;
        float bb0 = bias ? bias[r0] : 0.f;
        float bb1 = bias ? bias[r0 + 8] : 0.f;
        #pragma unroll
        for (int nt = 0; nt < 4; nt++) {
            int c = bx + wn + nt * 8 + qc;
            long o0 = (long)r0 * N + c;
            long o1 = (long)(r0 + 8) * N + c;
            float2 v0 = make_float2(acc[mt][nt][0] + bb0, acc[mt][nt][1] + bb0);
            float2 v1 = make_float2(acc[mt][nt][2] + bb1, acc[mt][nt][3] + bb1);
            if (res) {
                const float* rp = res + (long)blockIdx.z * strideRes;
                v0.x += rp[o0]; v0.y += rp[o0 + 1];
                v1.x += rp[o1]; v1.y += rp[o1 + 1];
            }
            *(float2*)&Cp[o0] = v0;
            *(float2*)&Cp[o1] = v1;
        }
    }
}

// =====================================================================
// single-pass TF32 GEMM (ff1/ff2; instance-norm downstream damps error)
// =====================================================================

__device__ __forceinline__ uint32_t f2tf(float x)
{
    uint32_t r;
    asm("cvt.rna.tf32.f32 %0, %1;" : "=r"(r) : "f"(x));
    return r;
}

#define MMA_TF32(c, a0, a1, a2, a3, b0, b1) \
    asm volatile("mma.sync.aligned.m16n8k8.row.col.f32.tf32.tf32.f32 " \
        "{%0,%1,%2,%3}, {%4,%5,%6,%7}, {%8,%9}, {%0,%1,%2,%3};" \
        : "+f"((c)[0]), "+f"((c)[1]), "+f"((c)[2]), "+f"((c)[3]) \
        : "r"(a0), "r"(a1), "r"(a2), "r"(a3), "r"(b0), "r"(b1))

#define AFRAG_STRIDE 132
#define BFRAG_STRIDE 66
#define AWORDS (16 * AFRAG_STRIDE)
#define BWORDS (32 * BFRAG_STRIDE)
#define TGEMM_STAGE (AWORDS + BWORDS)
#define TGEMM_SMEM (2 * TGEMM_STAGE * 4)

__global__ __launch_bounds__(256) void tgemm_kernel(
    const float* __restrict__ A, const float* __restrict__ B, float* __restrict__ C,
    int M, int N, int K, long strideB, long strideC,
    const float* __restrict__ bias, const float* __restrict__ res, long strideRes)
{
    extern __shared__ uint32_t sh[];
    int tid = threadIdx.x;
    int lane = tid & 31, warp = tid >> 5;
    int bx = blockIdx.x * 128, by = blockIdx.y * 128;
    const float* Bp = B + (long)blockIdx.z * strideB;
    float*       Cp = C + (long)blockIdx.z * strideC;

    float acc[4][4][4];
    #pragma unroll
    for (int i = 0; i < 4; i++)
        #pragma unroll
        for (int j = 0; j < 4; j++)
            #pragma unroll
            for (int k = 0; k < 4; k++) acc[i][j][k] = 0.f;

    int sA0f = tid >> 5, sA0l = tid & 31;
    int sA1f = (tid + 256) >> 5, sA1l = tid & 31;
    long aOff0 = (long)(by + (sA0f >> 1) * 16 + (sA0l >> 2)) * K + (sA0f & 1) * 8 + (sA0l & 3);
    long aOff1 = (long)(by + (sA1f >> 1) * 16 + (sA1l >> 2)) * K + (sA1f & 1) * 8 + (sA1l & 3);
    int bK0 = tid >> 5, bN0 = (tid & 31) * 4;
    int bK1 = (tid + 256) >> 5, bN1 = (tid & 31) * 4;

    float pa[8];
    float4 pb[2];

    {
        const float* ap0 = A + aOff0; const float* ap1 = A + aOff1;
        pa[0] = ap0[0]; pa[1] = ap0[8 * K]; pa[2] = ap0[4]; pa[3] = ap0[8 * K + 4];
        pa[4] = ap1[0]; pa[5] = ap1[8 * K]; pa[6] = ap1[4]; pa[7] = ap1[8 * K + 4];
        pb[0] = *(const float4*)(Bp + (long)bK0 * N + bx + bN0);
        pb[1] = *(const float4*)(Bp + (long)bK1 * N + bx + bN1);
    }

    int nIter = K >> 4;

    auto stage = [&](uint32_t* base) {
        uint32_t* AsB = base;
        uint32_t* BsB = base + AWORDS;
        #pragma unroll
        for (int u = 0; u < 2; u++) {
            int f = u ? sA1f : sA0f, ls = u ? sA1l : sA0l;
            uint32_t bg[4];
            #pragma unroll
            for (int j = 0; j < 4; j++) bg[j] = f2tf(pa[u * 4 + j]);
            *(uint4*)&AsB[f * AFRAG_STRIDE + ls * 4] = make_uint4(bg[0], bg[1], bg[2], bg[3]);
            int kb = u ? bK1 : bK0, nb = u ? bN1 : bN0;
            float bv[4] = { pb[u].x, pb[u].y, pb[u].z, pb[u].w };
            #pragma unroll
            for (int j = 0; j < 4; j++) {
                int n = nb + j;
                int fB = (n >> 3) * 2 + (kb >> 3);
                int bl = ((n & 7) << 2) | (kb & 3);
                int rg = (kb >> 2) & 1;
                BsB[fB * BFRAG_STRIDE + bl * 2 + rg] = f2tf(bv[j]);
            }
        }
    };

    stage(sh);
    __syncthreads();

    int wmt = (warp >> 2) * 4;
    int wnt = (warp & 3) * 4;

    for (int it = 0; it < nIter; it++) {
        if (it + 1 < nIter) {
            int k0 = (it + 1) << 4;
            const float* ap0 = A + aOff0 + k0; const float* ap1 = A + aOff1 + k0;
            pa[0] = ap0[0]; pa[1] = ap0[8 * K]; pa[2] = ap0[4]; pa[3] = ap0[8 * K + 4];
            pa[4] = ap1[0]; pa[5] = ap1[8 * K]; pa[6] = ap1[4]; pa[7] = ap1[8 * K + 4];
            pb[0] = *(const float4*)(Bp + (long)(k0 + bK0) * N + bx + bN0);
            pb[1] = *(const float4*)(Bp + (long)(k0 + bK1) * N + bx + bN1);
        }
        {
            uint32_t* base = sh + (it & 1) * TGEMM_STAGE;
            const uint32_t* AsB = base;
            const uint32_t* BsB = base + AWORDS;
            #pragma unroll
            for (int ks = 0; ks < 2; ks++) {
                uint2 bB[4];
                #pragma unroll
                for (int nt = 0; nt < 4; nt++) {
                    int fB = (wnt + nt) * 2 + ks;
                    bB[nt] = *(const uint2*)&BsB[fB * BFRAG_STRIDE + lane * 2];
                }
                #pragma unroll
                for (int mt = 0; mt < 4; mt++) {
                    int fA = (wmt + mt) * 2 + ks;
                    uint4 aB = *(const uint4*)&AsB[fA * AFRAG_STRIDE + lane * 4];
                    #pragma unroll
                    for (int nt = 0; nt < 4; nt++)
                        MMA_TF32(acc[mt][nt], aB.x, aB.y, aB.z, aB.w, bB[nt].x, bB[nt].y);
                }
            }
        }
        if (it + 1 < nIter) stage(sh + ((it + 1) & 1) * TGEMM_STAGE);
        __syncthreads();
    }

    int wm = (warp >> 2) * 64, wn = (warp & 3) * 32;
    int mr = lane >> 2, qc = (lane & 3) * 2;
    #pragma unroll
    for (int mt = 0; mt < 4; mt++) {
        int r0 = by + wm + mt * 16 + mr;
        float bb0 = bias ? bias[r0] : 0.f;
        float bb1 = bias ? bias[r0 + 8] : 0.f;
        #pragma unroll
        for (int nt = 0; nt < 4; nt++) {
            int c = bx + wn + nt * 8 + qc;
            long o0 = (long)r0 * N + c;
            long o1 = (long)(r0 + 8) * N + c;
            float2 v0 = make_float2(acc[mt][nt][0] + bb0, acc[mt][nt][1] + bb0);
            float2 v1 = make_float2(acc[mt][nt][2] + bb1, acc[mt][nt][3] + bb1);
            if (res) {
                const float* rp = res + (long)blockIdx.z * strideRes;
                v0.x += rp[o0]; v0.y += rp[o0 + 1];
                v1.x += rp[o1]; v1.y += rp[o1 + 1];
            }
            *(float2*)&Cp[o0] = v0;
            *(float2*)&Cp[o1] = v1;
        }
    }
}

// ---------------- l2-normalize q,k rows (along W=64) in place ----------------
__global__ __launch_bounds__(256) void l2norm_kernel(float* __restrict__ qkv)
{
    int gt = blockIdx.x * 256 + threadIdx.x;
    int warp = gt >> 5, lane = gt & 31;
    if (warp >= BD * 512 * WID) return;
    int b = warp / (512 * WID);
    int rem = warp % (512 * WID);
    float* p = qkv + (long)b * 768 * HW + (long)rem * WID;
    float v0 = p[lane], v1 = p[lane + 32];
    float s = v0 * v0 + v1 * v1;
    #pragma unroll
    for (int o = 16; o > 0; o >>= 1) s += __shfl_xor_sync(0xffffffffu, s, o);
    float scale = 1.f / fmaxf(sqrtf(s), 1e-12f);
    p[lane] = v0 * scale; p[lane + 32] = v1 * scale;
}

// ---------------- q_probe[bh][d] = sum over all pixels of normalized q ----------------
__global__ __launch_bounds__(256) void qprobe_kernel(const float* __restrict__ qkv,
                                                     float* __restrict__ qp)
{
    __shared__ float sm[8];
    int c = blockIdx.x;                     // 0..2047 = bh*32+d
    int bh = c >> 5, d = c & 31, b = bh >> 3, hh = bh & 7;
    const float4* p = (const float4*)(qkv + (long)b * 768 * HW + (long)(hh * 32 + d) * HW);
    float s = 0.f;
    #pragma unroll
    for (int i = 0; i < 4; i++) {
        float4 v = p[threadIdx.x + i * 256];
        s += v.x + v.y + v.z + v.w;
    }
    #pragma unroll
    for (int o = 16; o > 0; o >>= 1) s += __shfl_xor_sync(0xffffffffu, s, o);
    if ((threadIdx.x & 31) == 0) sm[threadIdx.x >> 5] = s;
    __syncthreads();
    if (threadIdx.x == 0) { float t = 0; for (int i = 0; i < 8; i++) t += sm[i]; qp[c] = t; }
}

// ---------------- k_height[bh][d][h] = sum over w of normalized k ----------------
__global__ __launch_bounds__(256) void kheight_kernel(const float* __restrict__ qkv,
                                                      float* __restrict__ kh)
{
    int gt = blockIdx.x * 256 + threadIdx.x;
    int warp = gt >> 5, lane = gt & 31;
    if (warp >= NBH * DH * WID) return;
    int h = warp & 63; int rest = warp >> 6; int d = rest & 31; int bh = rest >> 5;
    int b = bh >> 3, hh = bh & 7;
    const float* p = qkv + (long)b * 768 * HW + (long)(256 + hh * 32 + d) * HW + h * WID;
    float s = p[lane] + p[lane + 32];
    #pragma unroll
    for (int o = 16; o > 0; o >>= 1) s += __shfl_xor_sync(0xffffffffu, s, o);
    if (lane == 0) kh[warp] = s;
}

// ---------------- score_r + top-16 rows (set only; order irrelevant downstream) ---------
__global__ void toph_kernel(const float* __restrict__ qp, const float* __restrict__ kh,
                            int* __restrict__ topH)
{
    __shared__ float sc[64]; __shared__ float qs[32];
    int bh = blockIdx.x, t = threadIdx.x;                  // 64 threads
    if (t < 32) qs[t] = qp[bh * 32 + t];
    __syncthreads();
    float s = 0.f;
    #pragma unroll
    for (int d = 0; d < 32; d++) s += qs[d] * kh[((bh * 32 + d) << 6) + t];
    sc[t] = s;
    __syncthreads();
    if (t == 0) {
        for (int it = 0; it < 16; it++) {
            float best = -3.4e38f; int bi = 0;
            for (int h = 0; h < 64; h++) if (sc[h] > best) { best = sc[h]; bi = h; }
            topH[bh * 16 + it] = bi; sc[bi] = -3.4e38f;
        }
    }
}

// ---------------- gather selected rows of k,v -> kg/vg [bh][d][16][64] -----------------
__global__ __launch_bounds__(256) void gather_rows_kernel(const float* __restrict__ qkv,
                                                          const int* __restrict__ topH,
                                                          float* __restrict__ kg,
                                                          float* __restrict__ vg)
{
    long i = (long)blockIdx.x * 256 + threadIdx.x;          // 64*32*16*64
    int w = i & 63; long r = i >> 6; int t = (int)(r & 15); r >>= 4;
    int d = (int)(r & 31); int bh = (int)(r >> 5);
    int b = bh >> 3, hh = bh & 7;
    int h = topH[bh * 16 + t];
    long base = (long)b * 768 * HW + (long)(hh * 32 + d) * HW + (long)h * WID + w;
    kg[i] = qkv[base + 256L * HW];
    vg[i] = qkv[base + 512L * HW];
}

// ---------------- score_c + top-16 columns ----------------
__global__ void topw_kernel(const float* __restrict__ qp, const float* __restrict__ kg,
                            int* __restrict__ topW)
{
    __shared__ float sc[64]; __shared__ float qs[32];
    int bh = blockIdx.x, t = threadIdx.x;                  // t = w, 64 threads
    if (t < 32) qs[t] = qp[bh * 32 + t];
    __syncthreads();
    float s = 0.f;
    for (int d = 0; d < 32; d++) {
        float colsum = 0.f;
        #pragma unroll
        for (int i = 0; i < 16; i++)
            colsum += kg[(((long)(bh * 32 + d) * 16) + i) * 64 + t];
        s += qs[d] * colsum;
    }
    sc[t] = s;
    __syncthreads();
    if (t == 0) {
        for (int it = 0; it < 16; it++) {
            float best = -3.4e38f; int bi = 0;
            for (int w = 0; w < 64; w++) if (sc[w] > best) { best = sc[w]; bi = w; }
            topW[bh * 16 + it] = bi; sc[bi] = -3.4e38f;
        }
    }
}

// ---------------- build kf/vf [bh][j][d2] as bf16x2, j = i*16 + jw ----------------
__global__ __launch_bounds__(256) void build_kv_kernel(const float* __restrict__ kg,
                                                       const float* __restrict__ vg,
                                                       const int* __restrict__ topW,
                                                       uint32_t* __restrict__ kf,
                                                       uint32_t* __restrict__ vf)
{
    int i = blockIdx.x * 256 + threadIdx.x;   // 64*256*16 = 262144
    int d2 = i & 15; int j = (i >> 4) & 255; int bh = i >> 12;
    int ti = j >> 4, jw = j & 15;
    int w = topW[bh * 16 + jw];
    long src = (((long)(bh * 32 + 2 * d2) * 16) + ti) * 64 + w;
    __nv_bfloat162 kk = __floats2bfloat162_rn(kg[src], kg[src + 1024]);
    __nv_bfloat162 vv = __floats2bfloat162_rn(vg[src], vg[src + 1024]);
    kf[i] = *(uint32_t*)&kk;
    vf[i] = *(uint32_t*)&vv;
}

// ---------------- fused sparse attention: softmax(Q Kf^T) Vf, bf16 K/V ----------------
__device__ __forceinline__ float2 bf2f(uint32_t u)
{
    __nv_bfloat162 h = *reinterpret_cast<__nv_bfloat162*>(&u);
    return __bfloat1622float2(h);
}

__global__ __launch_bounds__(128) void attn_kernel(const float* __restrict__ qkv,
                                                   const uint32_t* __restrict__ kf,
                                                   const uint32_t* __restrict__ vf,
                                                   float* __restrict__ out)
{
    __shared__ uint32_t kfs[128 * 16];
    __shared__ uint32_t vfs[128 * 16];
    int bh = blockIdx.y;
    int b = bh >> 3, hh = bh & 7;
    int p = blockIdx.x * 128 + threadIdx.x;
    const float* qb = qkv + (long)b * 768 * HW + (long)(hh * 32) * HW + p;
    float q[32], acc[32];
    #pragma unroll
    for (int d = 0; d < 32; d++) { q[d] = qb[(long)d * HW]; acc[d] = 0.f; }
    float l = 0.f;
    for (int ch = 0; ch < 2; ch++) {
        const uint4* kc = (const uint4*)(kf + ((long)bh * NKEY + ch * 128) * 16);
        const uint4* vc = (const uint4*)(vf + ((long)bh * NKEY + ch * 128) * 16);
        #pragma unroll
        for (int i = 0; i < 4; i++) {
            ((uint4*)kfs)[threadIdx.x + i * 128] = kc[threadIdx.x + i * 128];
            ((uint4*)vfs)[threadIdx.x + i * 128] = vc[threadIdx.x + i * 128];
        }
        __syncthreads();
        for (int j = 0; j < 128; j++) {
            const uint32_t* kk = &kfs[j * 16];
            float s = 0.f;
            #pragma unroll
            for (int d2 = 0; d2 < 16; d2++) {
                float2 f = bf2f(kk[d2]);
                s = fmaf(f.x, q[2 * d2], s);
                s = fmaf(f.y, q[2 * d2 + 1], s);
            }
            float e = __expf(s);
            l += e;
            const uint32_t* vv = &vfs[j * 16];
            #pragma unroll
            for (int d2 = 0; d2 < 16; d2++) {
                float2 f = bf2f(vv[d2]);
                acc[2 * d2]     = fmaf(e, f.x, acc[2 * d2]);
                acc[2 * d2 + 1] = fmaf(e, f.y, acc[2 * d2 + 1]);
            }
        }
        __syncthreads();
    }
    float inv = 1.f / l;
    float* ob = out + (long)b * CDIM * HW + (long)(hh * 32) * HW + p;
    #pragma unroll
    for (int d = 0; d < 32; d++) ob[(long)d * HW] = acc[d] * inv;
}

// ---------------- depthwise 3x3 SAME (small branch, writes into cat) ----------------
__global__ __launch_bounds__(256) void dwconv_kernel(const float* __restrict__ in,
                                                     const float* __restrict__ w,
                                                     const float* __restrict__ bias,
                                                     float* __restrict__ out,
                                                     int C, long inBS, long outBS, int chanOff)
{
    int idx = blockIdx.x;
    int yt = idx & 15; idx >>= 4;
    int c = idx % C; int b = idx / C;
    int x = threadIdx.x & 63;
    int y = yt * 4 + (threadIdx.x >> 6);
    const float* ip = in + (long)b * inBS + (long)c * HW;
    const float* wp = w + c * 9;
    float s = bias[c];
    #pragma unroll
    for (int dy = 0; dy < 3; dy++) {
        int yy = y + dy - 1;
        if (yy < 0 || yy > 63) continue;
        #pragma unroll
        for (int dx = 0; dx < 3; dx++) {
            int xx = x + dx - 1;
            if (xx < 0 || xx > 63) continue;
            s += wp[dy * 3 + dx] * ip[yy * 64 + xx];
        }
    }
    out[(long)b * outBS + (long)(chanOff + c) * HW + y * 64 + x] = s;
}

// ---------------- gelu ----------------
__device__ __forceinline__ float gelu_exact(float u)
{
    return 0.5f * u * (1.f + erff(u * 0.7071067811865476f));
}

// ---------------- fused dwconv3x3 + instnorm + gelu + add:  h = hg + gelu(IN(dw(hg)))
__global__ __launch_bounds__(256) void dwin_kernel(const float* __restrict__ hg,
                                                   const float* __restrict__ w,
                                                   const float* __restrict__ bias,
                                                   float* __restrict__ out)
{
    __shared__ float tile[HW];
    __shared__ float red[16];
    long row = blockIdx.x;
    int c = (int)(row & (FFI - 1));
    int t = threadIdx.x;
    const float4* src = (const float4*)(hg + row * HW);
    #pragma unroll
    for (int i = 0; i < 4; i++) ((float4*)tile)[t + i * 256] = src[t + i * 256];
    float wr[9];
    #pragma unroll
    for (int i = 0; i < 9; i++) wr[i] = w[c * 9 + i];
    float bb = bias[c];
    __syncthreads();

    float r[16];
    float s = 0.f, s2 = 0.f;
    #pragma unroll
    for (int i = 0; i < 16; i++) {
        int px = t + i * 256;
        int y = px >> 6, x = px & 63;
        float a = bb;
        #pragma unroll
        for (int dy = 0; dy < 3; dy++) {
            int yy = y + dy - 1;
            if (yy < 0 || yy > 63) continue;
            #pragma unroll
            for (int dx = 0; dx < 3; dx++) {
                int xx = x + dx - 1;
                if (xx < 0 || xx > 63) continue;
                a += wr[dy * 3 + dx] * tile[yy * 64 + xx];
            }
        }
        r[i] = a; s += a; s2 += a * a;
    }
    #pragma unroll
    for (int o = 16; o > 0; o >>= 1) {
        s  += __shfl_xor_sync(0xffffffffu, s, o);
        s2 += __shfl_xor_sync(0xffffffffu, s2, o);
    }
    if ((t & 31) == 0) { red[t >> 5] = s; red[8 + (t >> 5)] = s2; }
    __syncthreads();
    if (t == 0) {
        float a = 0.f, b2 = 0.f;
        for (int i = 0; i < 8; i++) { a += red[i]; b2 += red[8 + i]; }
        red[0] = a; red[8] = b2;
    }
    __syncthreads();
    float mean = red[0] * (1.f / HW);
    float var  = red[8] * (1.f / HW) - mean * mean;
    float inv  = rsqrtf(var + 1e-5f);
    float* ob = out + row * HW;
    #pragma unroll
    for (int i = 0; i < 16; i++) {
        int px = t + i * 256;
        ob[px] = tile[px] + gelu_exact((r[i] - mean) * inv);
    }
}

// ---------------- instance norm (+gelu) ----------------
template <int MODE>  // 0: norm; 1: gelu(norm)
__global__ __launch_bounds__(256) void instnorm_kernel(const float* __restrict__ in,
                                                       float* __restrict__ out)
{
    __shared__ float sm[16];
    long row = blockIdx.x;
    const float4* p = (const float4*)(in + row * HW);
    int t = threadIdx.x;
    float4 v[4];
    float s = 0.f, s2 = 0.f;
    #pragma unroll
    for (int i = 0; i < 4; i++) {
        v[i] = p[t + i * 256];
        s  += v[i].x + v[i].y + v[i].z + v[i].w;
        s2 += v[i].x * v[i].x + v[i].y * v[i].y + v[i].z * v[i].z + v[i].w * v[i].w;
    }
    #pragma unroll
    for (int o = 16; o > 0; o >>= 1) {
        s  += __shfl_xor_sync(0xffffffffu, s, o);
        s2 += __shfl_xor_sync(0xffffffffu, s2, o);
    }
    if ((t & 31) == 0) { sm[t >> 5] = s; sm[8 + (t >> 5)] = s2; }
    __syncthreads();
    if (t == 0) {
        float a = 0.f, b2 = 0.f;
        for (int i = 0; i < 8; i++) { a += sm[i]; b2 += sm[8 + i]; }
        sm[0] = a; sm[8] = b2;
    }
    __syncthreads();
    float mean = sm[0] * (1.f / HW);
    float var  = sm[8] * (1.f / HW) - mean * mean;
    float inv  = rsqrtf(var + 1e-5f);
    float4* op = (float4*)(out + row * HW);
    #pragma unroll
    for (int i = 0; i < 4; i++) {
        float4 u = v[i];
        u.x = (u.x - mean) * inv; u.y = (u.y - mean) * inv;
        u.z = (u.z - mean) * inv; u.w = (u.w - mean) * inv;
        if (MODE >= 1) {
            u.x = gelu_exact(u.x); u.y = gelu_exact(u.y);
            u.z = gelu_exact(u.z); u.w = gelu_exact(u.w);
        }
        op[t + i * 256] = u;
    }
}

// ---------------- host launcher ----------------
extern "C" void kernel_launch(void* const* d_in, const int* in_sizes, int n_in,
                              void* d_out, int out_size)
{
    (void)in_sizes; (void)n_in; (void)out_size;
    const float* x      = (const float*)d_in[0];
    const float* ln_g   = (const float*)d_in[1];
    const float* ln_b   = (const float*)d_in[2];
    const float* w_qkv  = (const float*)d_in[3];
    const float* w_out  = (const float*)d_in[4];
    const float* b_out  = (const float*)d_in[5];
    const float* w_dw   = (const float*)d_in[6];
    const float* b_dw   = (const float*)d_in[7];
    const float* w_comb = (const float*)d_in[8];
    const float* b_comb = (const float*)d_in[9];
    const float* w_ff1  = (const float*)d_in[10];
    const float* b_ff1  = (const float*)d_in[11];
    const float* w_ffdw = (const float*)d_in[12];
    const float* b_ffdw = (const float*)d_in[13];
    const float* w_ff2  = (const float*)d_in[14];
    const float* b_ff2  = (const float*)d_in[15];
    float* out = (float*)d_out;

    void *p;
    cudaGetSymbolAddress(&p, g_xn);   float* xn   = (float*)p;
    cudaGetSymbolAddress(&p, g_qkv);  float* qkv  = (float*)p;
    cudaGetSymbolAddress(&p, g_attn); float* attn = (float*)p;
    cudaGetSymbolAddress(&p, g_cat);  float* cat  = (float*)p;
    cudaGetSymbolAddress(&p, g_ao);   float* ao   = (float*)p;
    cudaGetSymbolAddress(&p, g_h);    float* h    = (float*)p;
    cudaGetSymbolAddress(&p, g_hg);   float* hg   = (float*)p;
    cudaGetSymbolAddress(&p, g_kg);   float* kg   = (float*)p;
    cudaGetSymbolAddress(&p, g_vg);   float* vg   = (float*)p;
    cudaGetSymbolAddress(&p, g_kf);   uint32_t* kf = (uint32_t*)p;
    cudaGetSymbolAddress(&p, g_vf);   uint32_t* vf = (uint32_t*)p;
    cudaGetSymbolAddress(&p, g_qp);   float* qp   = (float*)p;
    cudaGetSymbolAddress(&p, g_kh);   float* kh   = (float*)p;
    cudaGetSymbolAddress(&p, g_topH); int*   topH = (int*)p;
    cudaGetSymbolAddress(&p, g_topW); int*   topW = (int*)p;

    cudaFuncSetAttribute(bgemm_kernel, cudaFuncAttributeMaxDynamicSharedMemorySize,
                         BGEMM_SMEM);
    cudaFuncSetAttribute(tgemm_kernel, cudaFuncAttributeMaxDynamicSharedMemorySize,
                         TGEMM_SMEM);

    // 1. channel layernorm
    ln_kernel<<<128, 256>>>(x, ln_g, ln_b, xn);
    // 2. qkv projection (bf16x3: near-fp32, protects top-k selection)
    bgemm_kernel<<<dim3(32, 6, BD), 256, BGEMM_SMEM>>>(w_qkv, xn, qkv, 768, HW, 256,
                                           (long)CDIM * HW, (long)768 * HW,
                                           nullptr, nullptr, 0);
    // 3. l2-normalize q,k along W (in place)
    l2norm_kernel<<<32768, 256>>>(qkv);
    // 4. probes + top-k selection
    qprobe_kernel<<<2048, 256>>>(qkv, qp);
    kheight_kernel<<<16384, 256>>>(qkv, kh);
    toph_kernel<<<64, 64>>>(qp, kh, topH);
    gather_rows_kernel<<<8192, 256>>>(qkv, topH, kg, vg);
    topw_kernel<<<64, 64>>>(qp, kg, topW);
    build_kv_kernel<<<1024, 256>>>(kg, vg, topW, kf, vf);
    // 5. fused sparse attention (bf16 K/V)
    attn_kernel<<<dim3(32, NBH), 128>>>(qkv, kf, vf, attn);
    // 6. out-proj into concat buffer rows [0,256)  (bf16x3)
    bgemm_kernel<<<dim3(32, 2, BD), 256, BGEMM_SMEM>>>(w_out, attn, cat, 256, HW, 256,
                                           (long)CDIM * HW, (long)512 * HW,
                                           b_out, nullptr, 0);
    // 7. dwconv branch into concat buffer rows [256,512)
    dwconv_kernel<<<BD * 256 * 16, 256>>>(x, w_dw, b_dw, cat, 256,
                                          (long)CDIM * HW, (long)512 * HW, 256);
    // 8. combine (K=512) + bias + residual x  (bf16x3)
    bgemm_kernel<<<dim3(32, 2, BD), 256, BGEMM_SMEM>>>(w_comb, cat, ao, 256, HW, 512,
                                           (long)512 * HW, (long)CDIM * HW,
                                           b_comb, x, (long)CDIM * HW);
    // 9. ff1 (single-pass TF32)
    tgemm_kernel<<<dim3(32, 8, BD), 256, TGEMM_SMEM>>>(w_ff1, ao, h, FFI, HW, 256,
                                           (long)CDIM * HW, (long)FFI * HW,
                                           b_ff1, nullptr, 0);
    // 10. hg = gelu(instnorm(h))
    instnorm_kernel<1><<<BD * FFI, 256>>>(h, hg);
    // 11+12. h = hg + gelu(instnorm(dwconv(hg)))  -- fused
    dwin_kernel<<<BD * FFI, 256>>>(hg, w_ffdw, b_ffdw, h);
    // 13. ff2 (single-pass TF32; reuse xn buffer for output)
    tgemm_kernel<<<dim3(32, 2, BD), 256, TGEMM_SMEM>>>(w_ff2, h, xn, 256, HW, 1024,
                                           (long)FFI * HW, (long)CDIM * HW,
                                           b_ff2, nullptr, 0);
    // 14. final instance norm -> d_out
    instnorm_kernel<0><<<BD * CDIM, 256>>>(xn, out);
}

// round 15
// speedup vs baseline: 1.6492x; 1.3749x over previous
#include <cuda_runtime.h>
#include <cuda_bf16.h>
#include <math.h>
#include <stdint.h>

// ---------------- problem constants ----------------
#define BD     8          // batch
#define HEADS  8
#define DH     32         // dim head
#define CDIM   256        // model dim
#define FFI    1024       // ff inner
#define HW     4096       // 64*64 pixels
#define WID    64
#define NBH    64         // BD*HEADS
#define NKEY   256        // TOP_H * TOP_W

// ---------------- scratch (device globals: no allocs allowed) ----------------
__device__ float g_xn  [(long)BD*CDIM*HW];   // LN(x); reused for ff2 output
__device__ float g_qkv [(long)BD*768*HW];
__device__ float g_attn[(long)BD*CDIM*HW];
__device__ float g_cat [(long)BD*512*HW];
__device__ float g_ao  [(long)BD*CDIM*HW];
__device__ float g_h   [(long)BD*FFI*HW];
__device__ float g_kg  [NBH*DH*16*WID];
__device__ float g_vg  [NBH*DH*16*WID];
__device__ uint32_t g_kf [NBH*NKEY*16];      // bf16x2: [bh][key][dim-pair]
__device__ uint32_t g_vt [NBH*DH*128];       // bf16x2: [bh][dim][key-pair]
__device__ float g_qp  [NBH*DH];
__device__ float g_kh  [NBH*DH*WID];
__device__ int   g_topH[NBH*16];
__device__ int   g_topW[NBH*16];

// ---------------- channel layernorm (per pixel over 256 channels) ----------------
__global__ __launch_bounds__(256) void ln_kernel(const float* __restrict__ x,
                                                 const float* __restrict__ g,
                                                 const float* __restrict__ be,
                                                 float* __restrict__ out)
{
    int gp = blockIdx.x * 256 + threadIdx.x;           // 0..32767
    int b = gp >> 12, p = gp & 4095;
    const float* base = x + (long)b * CDIM * HW + p;
    float s = 0.f, s2 = 0.f;
    #pragma unroll 8
    for (int c = 0; c < CDIM; c++) { float v = base[(long)c * HW]; s += v; s2 += v * v; }
    float mean = s * (1.f / CDIM);
    float var  = s2 * (1.f / CDIM) - mean * mean;
    float inv  = rsqrtf(var + 1e-5f);
    float* ob = out + (long)b * CDIM * HW + p;
    #pragma unroll 8
    for (int c = 0; c < CDIM; c++) {
        float v = base[(long)c * HW];
        ob[(long)c * HW] = (v - mean) * inv * g[c] + be[c];
    }
}

// =====================================================================
// bf16x3 tensor-core GEMM (m16n8k16): near-fp32 accuracy, 3 mma / k16.
// =====================================================================

__device__ __forceinline__ void bfsplit2(float x0, float x1,
                                         uint32_t& big, uint32_t& sml)
{
    __nv_bfloat162 b = __floats2bfloat162_rn(x0, x1);
    float2 bf = __bfloat1622float2(b);
    __nv_bfloat162 s = __floats2bfloat162_rn(x0 - bf.x, x1 - bf.y);
    big = *reinterpret_cast<uint32_t*>(&b);
    sml = *reinterpret_cast<uint32_t*>(&s);
}

#define MMA_BF16(c, a0, a1, a2, a3, b0, b1) \
    asm volatile("mma.sync.aligned.m16n8k16.row.col.f32.bf16.bf16.f32 " \
        "{%0,%1,%2,%3}, {%4,%5,%6,%7}, {%8,%9}, {%0,%1,%2,%3};" \
        : "+f"((c)[0]), "+f"((c)[1]), "+f"((c)[2]), "+f"((c)[3]) \
        : "r"(a0), "r"(a1), "r"(a2), "r"(a3), "r"(b0), "r"(b1))

#define BG_AFS 132
#define BG_BFS 66
#define BG_AW  (8 * BG_AFS)
#define BG_BW  (16 * BG_BFS)
#define BG_STAGE (2 * BG_AW + 2 * BG_BW)
#define BGEMM_SMEM (2 * BG_STAGE * 4)

__global__ __launch_bounds__(256) void bgemm_kernel(
    const float* __restrict__ A, const float* __restrict__ B, float* __restrict__ C,
    int M, int N, int K, long strideB, long strideC,
    const float* __restrict__ bias, const float* __restrict__ res, long strideRes)
{
    extern __shared__ uint32_t sh[];
    int tid = threadIdx.x;
    int lane = tid & 31, warp = tid >> 5;
    int bx = blockIdx.x * 128, by = blockIdx.y * 128;
    const float* Bp = B + (long)blockIdx.z * strideB;
    float*       Cp = C + (long)blockIdx.z * strideC;

    float acc[4][4][4];
    #pragma unroll
    for (int i = 0; i < 4; i++)
        #pragma unroll
        for (int j = 0; j < 4; j++)
            #pragma unroll
            for (int k = 0; k < 4; k++) acc[i][j][k] = 0.f;

    int af = tid >> 5, als = tid & 31;
    long aRow = by + af * 16 + (als >> 2);
    int  aK   = (als & 3) * 2;
    const float* aBase = A + aRow * K + aK;
    int bls = tid & 31;
    int bn0 = bx + (tid >> 5) * 8 + (bls >> 2);
    int bn1 = bn0 + 64;
    int bK  = (bls & 3) * 2;

    float2 pa[4];
    float  pbv[2][4];

    {
        pa[0] = *(const float2*)(aBase);
        pa[1] = *(const float2*)(aBase + 8);
        pa[2] = *(const float2*)(aBase + 8 * K);
        pa[3] = *(const float2*)(aBase + 8 * K + 8);
        #pragma unroll
        for (int u = 0; u < 2; u++) {
            int n = u ? bn1 : bn0;
            pbv[u][0] = Bp[(long)(bK)     * N + n];
            pbv[u][1] = Bp[(long)(bK + 1) * N + n];
            pbv[u][2] = Bp[(long)(bK + 8) * N + n];
            pbv[u][3] = Bp[(long)(bK + 9) * N + n];
        }
    }

    int nIter = K >> 4;

    auto stage = [&](uint32_t* base) {
        uint32_t* AsB = base;
        uint32_t* AsS = base + BG_AW;
        uint32_t* BsB = base + 2 * BG_AW;
        uint32_t* BsS = BsB + BG_BW;
        uint32_t a0b, a0s, a1b, a1s, a2b, a2s, a3b, a3s;
        bfsplit2(pa[0].x, pa[0].y, a0b, a0s);
        bfsplit2(pa[2].x, pa[2].y, a1b, a1s);
        bfsplit2(pa[1].x, pa[1].y, a2b, a2s);
        bfsplit2(pa[3].x, pa[3].y, a3b, a3s);
        *(uint4*)&AsB[af * BG_AFS + als * 4] = make_uint4(a0b, a1b, a2b, a3b);
        *(uint4*)&AsS[af * BG_AFS + als * 4] = make_uint4(a0s, a1s, a2s, a3s);
        #pragma unroll
        for (int u = 0; u < 2; u++) {
            int fn = (tid >> 5) + u * 8;
            uint32_t b0b, b0s, b1b, b1s;
            bfsplit2(pbv[u][0], pbv[u][1], b0b, b0s);
            bfsplit2(pbv[u][2], pbv[u][3], b1b, b1s);
            *(uint2*)&BsB[fn * BG_BFS + bls * 2] = make_uint2(b0b, b1b);
            *(uint2*)&BsS[fn * BG_BFS + bls * 2] = make_uint2(b0s, b1s);
        }
    };

    stage(sh);
    __syncthreads();

    int wmt = (warp >> 2) * 4;
    int wnt = (warp & 3) * 4;

    for (int it = 0; it < nIter; it++) {
        if (it + 1 < nIter) {
            int k0 = (it + 1) << 4;
            const float* ap = aBase + k0;
            pa[0] = *(const float2*)(ap);
            pa[1] = *(const float2*)(ap + 8);
            pa[2] = *(const float2*)(ap + 8 * K);
            pa[3] = *(const float2*)(ap + 8 * K + 8);
            #pragma unroll
            for (int u = 0; u < 2; u++) {
                int n = u ? bn1 : bn0;
                pbv[u][0] = Bp[(long)(k0 + bK)     * N + n];
                pbv[u][1] = Bp[(long)(k0 + bK + 1) * N + n];
                pbv[u][2] = Bp[(long)(k0 + bK + 8) * N + n];
                pbv[u][3] = Bp[(long)(k0 + bK + 9) * N + n];
            }
        }
        {
            uint32_t* base = sh + (it & 1) * BG_STAGE;
            const uint32_t* AsB = base;
            const uint32_t* AsS = base + BG_AW;
            const uint32_t* BsB = base + 2 * BG_AW;
            const uint32_t* BsS = BsB + BG_BW;
            uint2 bB[4], bS[4];
            #pragma unroll
            for (int nt = 0; nt < 4; nt++) {
                bB[nt] = *(const uint2*)&BsB[(wnt + nt) * BG_BFS + lane * 2];
                bS[nt] = *(const uint2*)&BsS[(wnt + nt) * BG_BFS + lane * 2];
            }
            #pragma unroll
            for (int mt = 0; mt < 4; mt++) {
                uint4 aB = *(const uint4*)&AsB[(wmt + mt) * BG_AFS + lane * 4];
                uint4 aS = *(const uint4*)&AsS[(wmt + mt) * BG_AFS + lane * 4];
                #pragma unroll
                for (int nt = 0; nt < 4; nt++)
                    MMA_BF16(acc[mt][nt], aB.x, aB.y, aB.z, aB.w, bB[nt].x, bB[nt].y);
                #pragma unroll
                for (int nt = 0; nt < 4; nt++)
                    MMA_BF16(acc[mt][nt], aB.x, aB.y, aB.z, aB.w, bS[nt].x, bS[nt].y);
                #pragma unroll
                for (int nt = 0; nt < 4; nt++)
                    MMA_BF16(acc[mt][nt], aS.x, aS.y, aS.z, aS.w, bB[nt].x, bB[nt].y);
            }
        }
        if (it + 1 < nIter) stage(sh + ((it + 1) & 1) * BG_STAGE);
        __syncthreads();
    }

    int wm = (warp >> 2) * 64, wn = (warp & 3) * 32;
    int mr = lane >> 2, qc = (lane & 3) * 2;
    #pragma unroll
    for (int mt = 0; mt < 4; mt++) {
        int r0 = by + wm + mt * 16 + mr;
        float bb0 = bias ? bias[r0] : 0.f;
        float bb1 = bias ? bias[r0 + 8] : 0.f;
        #pragma unroll
        for (int nt = 0; nt < 4; nt++) {
            int c = bx + wn + nt * 8 + qc;
            long o0 = (long)r0 * N + c;
            long o1 = (long)(r0 + 8) * N + c;
            float2 v0 = make_float2(acc[mt][nt][0] + bb0, acc[mt][nt][1] + bb0);
            float2 v1 = make_float2(acc[mt][nt][2] + bb1, acc[mt][nt][3] + bb1);
            if (res) {
                const float* rp = res + (long)blockIdx.z * strideRes;
                v0.x += rp[o0]; v0.y += rp[o0 + 1];
                v1.x += rp[o1]; v1.y += rp[o1 + 1];
            }
            *(float2*)&Cp[o0] = v0;
            *(float2*)&Cp[o1] = v1;
        }
    }
}

// =====================================================================
// single-pass TF32 GEMM (ff1/ff2; instance-norm downstream damps error)
// =====================================================================

__device__ __forceinline__ uint32_t f2tf(float x)
{
    uint32_t r;
    asm("cvt.rna.tf32.f32 %0, %1;" : "=r"(r) : "f"(x));
    return r;
}

#define MMA_TF32(c, a0, a1, a2, a3, b0, b1) \
    asm volatile("mma.sync.aligned.m16n8k8.row.col.f32.tf32.tf32.f32 " \
        "{%0,%1,%2,%3}, {%4,%5,%6,%7}, {%8,%9}, {%0,%1,%2,%3};" \
        : "+f"((c)[0]), "+f"((c)[1]), "+f"((c)[2]), "+f"((c)[3]) \
        : "r"(a0), "r"(a1), "r"(a2), "r"(a3), "r"(b0), "r"(b1))

#define AFRAG_STRIDE 132
#define BFRAG_STRIDE 66
#define AWORDS (16 * AFRAG_STRIDE)
#define BWORDS (32 * BFRAG_STRIDE)
#define TGEMM_STAGE (AWORDS + BWORDS)
#define TGEMM_SMEM (2 * TGEMM_STAGE * 4)

__global__ __launch_bounds__(256) void tgemm_kernel(
    const float* __restrict__ A, const float* __restrict__ B, float* __restrict__ C,
    int M, int N, int K, long strideB, long strideC,
    const float* __restrict__ bias, const float* __restrict__ res, long strideRes)
{
    extern __shared__ uint32_t sh[];
    int tid = threadIdx.x;
    int lane = tid & 31, warp = tid >> 5;
    int bx = blockIdx.x * 128, by = blockIdx.y * 128;
    const float* Bp = B + (long)blockIdx.z * strideB;
    float*       Cp = C + (long)blockIdx.z * strideC;

    float acc[4][4][4];
    #pragma unroll
    for (int i = 0; i < 4; i++)
        #pragma unroll
        for (int j = 0; j < 4; j++)
            #pragma unroll
            for (int k = 0; k < 4; k++) acc[i][j][k] = 0.f;

    int sA0f = tid >> 5, sA0l = tid & 31;
    int sA1f = (tid + 256) >> 5, sA1l = tid & 31;
    long aOff0 = (long)(by + (sA0f >> 1) * 16 + (sA0l >> 2)) * K + (sA0f & 1) * 8 + (sA0l & 3);
    long aOff1 = (long)(by + (sA1f >> 1) * 16 + (sA1l >> 2)) * K + (sA1f & 1) * 8 + (sA1l & 3);
    int bK0 = tid >> 5, bN0 = (tid & 31) * 4;
    int bK1 = (tid + 256) >> 5, bN1 = (tid & 31) * 4;

    float pa[8];
    float4 pb[2];

    {
        const float* ap0 = A + aOff0; const float* ap1 = A + aOff1;
        pa[0] = ap0[0]; pa[1] = ap0[8 * K]; pa[2] = ap0[4]; pa[3] = ap0[8 * K + 4];
        pa[4] = ap1[0]; pa[5] = ap1[8 * K]; pa[6] = ap1[4]; pa[7] = ap1[8 * K + 4];
        pb[0] = *(const float4*)(Bp + (long)bK0 * N + bx + bN0);
        pb[1] = *(const float4*)(Bp + (long)bK1 * N + bx + bN1);
    }

    int nIter = K >> 4;

    auto stage = [&](uint32_t* base) {
        uint32_t* AsB = base;
        uint32_t* BsB = base + AWORDS;
        #pragma unroll
        for (int u = 0; u < 2; u++) {
            int f = u ? sA1f : sA0f, ls = u ? sA1l : sA0l;
            uint32_t bg[4];
            #pragma unroll
            for (int j = 0; j < 4; j++) bg[j] = f2tf(pa[u * 4 + j]);
            *(uint4*)&AsB[f * AFRAG_STRIDE + ls * 4] = make_uint4(bg[0], bg[1], bg[2], bg[3]);
            int kb = u ? bK1 : bK0, nb = u ? bN1 : bN0;
            float bv[4] = { pb[u].x, pb[u].y, pb[u].z, pb[u].w };
            #pragma unroll
            for (int j = 0; j < 4; j++) {
                int n = nb + j;
                int fB = (n >> 3) * 2 + (kb >> 3);
                int bl = ((n & 7) << 2) | (kb & 3);
                int rg = (kb >> 2) & 1;
                BsB[fB * BFRAG_STRIDE + bl * 2 + rg] = f2tf(bv[j]);
            }
        }
    };

    stage(sh);
    __syncthreads();

    int wmt = (warp >> 2) * 4;
    int wnt = (warp & 3) * 4;

    for (int it = 0; it < nIter; it++) {
        if (it + 1 < nIter) {
            int k0 = (it + 1) << 4;
            const float* ap0 = A + aOff0 + k0; const float* ap1 = A + aOff1 + k0;
            pa[0] = ap0[0]; pa[1] = ap0[8 * K]; pa[2] = ap0[4]; pa[3] = ap0[8 * K + 4];
            pa[4] = ap1[0]; pa[5] = ap1[8 * K]; pa[6] = ap1[4]; pa[7] = ap1[8 * K + 4];
            pb[0] = *(const float4*)(Bp + (long)(k0 + bK0) * N + bx + bN0);
            pb[1] = *(const float4*)(Bp + (long)(k0 + bK1) * N + bx + bN1);
        }
        {
            uint32_t* base = sh + (it & 1) * TGEMM_STAGE;
            const uint32_t* AsB = base;
            const uint32_t* BsB = base + AWORDS;
            #pragma unroll
            for (int ks = 0; ks < 2; ks++) {
                uint2 bB[4];
                #pragma unroll
                for (int nt = 0; nt < 4; nt++) {
                    int fB = (wnt + nt) * 2 + ks;
                    bB[nt] = *(const uint2*)&BsB[fB * BFRAG_STRIDE + lane * 2];
                }
                #pragma unroll
                for (int mt = 0; mt < 4; mt++) {
                    int fA = (wmt + mt) * 2 + ks;
                    uint4 aB = *(const uint4*)&AsB[fA * AFRAG_STRIDE + lane * 4];
                    #pragma unroll
                    for (int nt = 0; nt < 4; nt++)
                        MMA_TF32(acc[mt][nt], aB.x, aB.y, aB.z, aB.w, bB[nt].x, bB[nt].y);
                }
            }
        }
        if (it + 1 < nIter) stage(sh + ((it + 1) & 1) * TGEMM_STAGE);
        __syncthreads();
    }

    int wm = (warp >> 2) * 64, wn = (warp & 3) * 32;
    int mr = lane >> 2, qc = (lane & 3) * 2;
    #pragma unroll
    for (int mt = 0; mt < 4; mt++) {
        int r0 = by + wm + mt * 16 + mr;
        float bb0 = bias ? bias[r0] : 0.f;
        float bb1 = bias ? bias[r0 + 8] : 0.f;
        #pragma unroll
        for (int nt = 0; nt < 4; nt++) {
            int c = bx + wn + nt * 8 + qc;
            long o0 = (long)r0 * N + c;
            long o1 = (long)(r0 + 8) * N + c;
            float2 v0 = make_float2(acc[mt][nt][0] + bb0, acc[mt][nt][1] + bb0);
            float2 v1 = make_float2(acc[mt][nt][2] + bb1, acc[mt][nt][3] + bb1);
            if (res) {
                const float* rp = res + (long)blockIdx.z * strideRes;
                v0.x += rp[o0]; v0.y += rp[o0 + 1];
                v1.x += rp[o1]; v1.y += rp[o1 + 1];
            }
            *(float2*)&Cp[o0] = v0;
            *(float2*)&Cp[o1] = v1;
        }
    }
}

// ---------------- l2-normalize q,k rows (along W=64) in place ----------------
__global__ __launch_bounds__(256) void l2norm_kernel(float* __restrict__ qkv)
{
    int gt = blockIdx.x * 256 + threadIdx.x;
    int warp = gt >> 5, lane = gt & 31;
    if (warp >= BD * 512 * WID) return;
    int b = warp / (512 * WID);
    int rem = warp % (512 * WID);
    float* p = qkv + (long)b * 768 * HW + (long)rem * WID;
    float v0 = p[lane], v1 = p[lane + 32];
    float s = v0 * v0 + v1 * v1;
    #pragma unroll
    for (int o = 16; o > 0; o >>= 1) s += __shfl_xor_sync(0xffffffffu, s, o);
    float scale = 1.f / fmaxf(sqrtf(s), 1e-12f);
    p[lane] = v0 * scale; p[lane + 32] = v1 * scale;
}

// ---------------- q_probe[bh][d] = sum over all pixels of normalized q ----------------
__global__ __launch_bounds__(256) void qprobe_kernel(const float* __restrict__ qkv,
                                                     float* __restrict__ qp)
{
    __shared__ float sm[8];
    int c = blockIdx.x;                     // 0..2047 = bh*32+d
    int bh = c >> 5, d = c & 31, b = bh >> 3, hh = bh & 7;
    const float4* p = (const float4*)(qkv + (long)b * 768 * HW + (long)(hh * 32 + d) * HW);
    float s = 0.f;
    #pragma unroll
    for (int i = 0; i < 4; i++) {
        float4 v = p[threadIdx.x + i * 256];
        s += v.x + v.y + v.z + v.w;
    }
    #pragma unroll
    for (int o = 16; o > 0; o >>= 1) s += __shfl_xor_sync(0xffffffffu, s, o);
    if ((threadIdx.x & 31) == 0) sm[threadIdx.x >> 5] = s;
    __syncthreads();
    if (threadIdx.x == 0) { float t = 0; for (int i = 0; i < 8; i++) t += sm[i]; qp[c] = t; }
}

// ---------------- k_height[bh][d][h] = sum over w of normalized k ----------------
__global__ __launch_bounds__(256) void kheight_kernel(const float* __restrict__ qkv,
                                                      float* __restrict__ kh)
{
    int gt = blockIdx.x * 256 + threadIdx.x;
    int warp = gt >> 5, lane = gt & 31;
    if (warp >= NBH * DH * WID) return;
    int h = warp & 63; int rest = warp >> 6; int d = rest & 31; int bh = rest >> 5;
    int b = bh >> 3, hh = bh & 7;
    const float* p = qkv + (long)b * 768 * HW + (long)(256 + hh * 32 + d) * HW + h * WID;
    float s = p[lane] + p[lane + 32];
    #pragma unroll
    for (int o = 16; o > 0; o >>= 1) s += __shfl_xor_sync(0xffffffffu, s, o);
    if (lane == 0) kh[warp] = s;
}

// ---------------- score_r + top-16 rows ----------------
__global__ void toph_kernel(const float* __restrict__ qp, const float* __restrict__ kh,
                            int* __restrict__ topH)
{
    __shared__ float sc[64]; __shared__ float qs[32];
    int bh = blockIdx.x, t = threadIdx.x;                  // 64 threads
    if (t < 32) qs[t] = qp[bh * 32 + t];
    __syncthreads();
    float s = 0.f;
    #pragma unroll
    for (int d = 0; d < 32; d++) s += qs[d] * kh[((bh * 32 + d) << 6) + t];
    sc[t] = s;
    __syncthreads();
    if (t == 0) {
        for (int it = 0; it < 16; it++) {
            float best = -3.4e38f; int bi = 0;
            for (int h = 0; h < 64; h++) if (sc[h] > best) { best = sc[h]; bi = h; }
            topH[bh * 16 + it] = bi; sc[bi] = -3.4e38f;
        }
    }
}

// ---------------- gather selected rows of k,v -> kg/vg [bh][d][16][64] -----------------
__global__ __launch_bounds__(256) void gather_rows_kernel(const float* __restrict__ qkv,
                                                          const int* __restrict__ topH,
                                                          float* __restrict__ kg,
                                                          float* __restrict__ vg)
{
    long i = (long)blockIdx.x * 256 + threadIdx.x;          // 64*32*16*64
    int w = i & 63; long r = i >> 6; int t = (int)(r & 15); r >>= 4;
    int d = (int)(r & 31); int bh = (int)(r >> 5);
    int b = bh >> 3, hh = bh & 7;
    int h = topH[bh * 16 + t];
    long base = (long)b * 768 * HW + (long)(hh * 32 + d) * HW + (long)h * WID + w;
    kg[i] = qkv[base + 256L * HW];
    vg[i] = qkv[base + 512L * HW];
}

// ---------------- score_c + top-16 columns ----------------
__global__ void topw_kernel(const float* __restrict__ qp, const float* __restrict__ kg,
                            int* __restrict__ topW)
{
    __shared__ float sc[64]; __shared__ float qs[32];
    int bh = blockIdx.x, t = threadIdx.x;                  // t = w, 64 threads
    if (t < 32) qs[t] = qp[bh * 32 + t];
    __syncthreads();
    float s = 0.f;
    for (int d = 0; d < 32; d++) {
        float colsum = 0.f;
        #pragma unroll
        for (int i = 0; i < 16; i++)
            colsum += kg[(((long)(bh * 32 + d) * 16) + i) * 64 + t];
        s += qs[d] * colsum;
    }
    sc[t] = s;
    __syncthreads();
    if (t == 0) {
        for (int it = 0; it < 16; it++) {
            float best = -3.4e38f; int bi = 0;
            for (int w = 0; w < 64; w++) if (sc[w] > best) { best = sc[w]; bi = w; }
            topW[bh * 16 + it] = bi; sc[bi] = -3.4e38f;
        }
    }
}

// ---------------- build kf (key-major) and vt (dim-major, transposed) ----------------
__global__ __launch_bounds__(256) void build_kv_kernel(const float* __restrict__ kg,
                                                       const float* __restrict__ vg,
                                                       const int* __restrict__ topW,
                                                       uint32_t* __restrict__ kf,
                                                       uint32_t* __restrict__ vt)
{
    int i = blockIdx.x * 256 + threadIdx.x;   // 262144
    // kf[bh][j][d2] = (K[j][2d2], K[j][2d2+1])
    {
        int d2 = i & 15; int j = (i >> 4) & 255; int bh = i >> 12;
        int ti = j >> 4, jw = j & 15;
        int w = topW[bh * 16 + jw];
        long src = (((long)(bh * 32 + 2 * d2) * 16) + ti) * 64 + w;
        __nv_bfloat162 kk = __floats2bfloat162_rn(kg[src], kg[src + 1024]);
        kf[i] = *(uint32_t*)&kk;
    }
    // vt[bh][d][j2] = (V[2j2][d], V[2j2+1][d])
    {
        int j2 = i & 127; int d = (i >> 7) & 31; int bh = i >> 12;
        int jA = 2 * j2, jB = jA + 1;
        int wA = topW[bh * 16 + (jA & 15)];
        int wB = topW[bh * 16 + (jB & 15)];
        long sA = (((long)(bh * 32 + d) * 16) + (jA >> 4)) * 64 + wA;
        long sB = (((long)(bh * 32 + d) * 16) + (jB >> 4)) * 64 + wB;
        __nv_bfloat162 vv = __floats2bfloat162_rn(vg[sA], vg[sB]);
        vt[i] = *(uint32_t*)&vv;
    }
}

// ---------------- tensor-core sparse attention: softmax(Q Kf^T) Vf ----------------
// 128 q-rows per block (8 warps x m16), 256 keys in 16-key chunks.
// S frags (fp32) -> exp -> bf16 P frags (register-layout match) -> PV mma.
__global__ __launch_bounds__(256) void attn_kernel(const float* __restrict__ qkv,
                                                   const uint32_t* __restrict__ kf,
                                                   const uint32_t* __restrict__ vt,
                                                   float* __restrict__ out)
{
    __shared__ uint32_t Qs[128 * 20];   // [row][d2], stride 20 (conflict-free)
    __shared__ uint32_t Ks[256 * 20];   // [key][d2], stride 20
    __shared__ uint32_t Vs[32 * 132];   // [dim][j2], stride 132
    int bh = blockIdx.y;
    int b = bh >> 3, hh = bh & 7;
    int p0 = blockIdx.x * 128;
    int tid = threadIdx.x, lane = tid & 31, warp = tid >> 5;
    int g = lane >> 2, t4 = lane & 3;

    const uint4* ksrc = (const uint4*)(kf + (long)bh * NKEY * 16);
    #pragma unroll
    for (int i = tid; i < 1024; i += 256) {
        int j = i >> 2, q4 = i & 3;
        *(uint4*)&Ks[j * 20 + q4 * 4] = ksrc[i];
    }
    const uint4* vsrc = (const uint4*)(vt + (long)bh * 32 * 128);
    #pragma unroll
    for (int i = tid; i < 1024; i += 256) {
        int d = i >> 5, q4 = i & 31;
        *(uint4*)&Vs[d * 132 + q4 * 4] = vsrc[i];
    }
    const float* qb = qkv + (long)b * 768 * HW + (long)(hh * 32) * HW + p0;
    #pragma unroll
    for (int i = tid; i < 2048; i += 256) {
        int row = i & 127, d2 = i >> 7;
        float f0 = qb[(long)(2 * d2) * HW + row];
        float f1 = qb[(long)(2 * d2 + 1) * HW + row];
        __nv_bfloat162 hb = __floats2bfloat162_rn(f0, f1);
        Qs[row * 20 + d2] = *(uint32_t*)&hb;
    }
    __syncthreads();

    int wrow = warp * 16;
    uint32_t qa[2][4];
    #pragma unroll
    for (int ks = 0; ks < 2; ks++) {
        int base = ks * 8;
        qa[ks][0] = Qs[(wrow + g) * 20 + base + t4];
        qa[ks][1] = Qs[(wrow + 8 + g) * 20 + base + t4];
        qa[ks][2] = Qs[(wrow + g) * 20 + base + t4 + 4];
        qa[ks][3] = Qs[(wrow + 8 + g) * 20 + base + t4 + 4];
    }
    float o[4][4];
    #pragma unroll
    for (int i = 0; i < 4; i++)
        #pragma unroll
        for (int j = 0; j < 4; j++) o[i][j] = 0.f;
    float lsum0 = 0.f, lsum1 = 0.f;

    #pragma unroll
    for (int jc = 0; jc < 256; jc += 16) {
        float s0[4] = {0.f, 0.f, 0.f, 0.f}, s1[4] = {0.f, 0.f, 0.f, 0.f};
        #pragma unroll
        for (int ks = 0; ks < 2; ks++) {
            int pb = ks * 8;
            uint32_t b0 = Ks[(jc + g) * 20 + pb + t4];
            uint32_t b1 = Ks[(jc + g) * 20 + pb + t4 + 4];
            MMA_BF16(s0, qa[ks][0], qa[ks][1], qa[ks][2], qa[ks][3], b0, b1);
            uint32_t b2 = Ks[(jc + 8 + g) * 20 + pb + t4];
            uint32_t b3 = Ks[(jc + 8 + g) * 20 + pb + t4 + 4];
            MMA_BF16(s1, qa[ks][0], qa[ks][1], qa[ks][2], qa[ks][3], b2, b3);
        }
        float e00 = __expf(s0[0]), e01 = __expf(s0[1]);
        float e02 = __expf(s0[2]), e03 = __expf(s0[3]);
        float e10 = __expf(s1[0]), e11 = __expf(s1[1]);
        float e12 = __expf(s1[2]), e13 = __expf(s1[3]);
        lsum0 += e00 + e01 + e10 + e11;
        lsum1 += e02 + e03 + e12 + e13;
        __nv_bfloat162 pb0 = __floats2bfloat162_rn(e00, e01);
        __nv_bfloat162 pb1 = __floats2bfloat162_rn(e02, e03);
        __nv_bfloat162 pb2 = __floats2bfloat162_rn(e10, e11);
        __nv_bfloat162 pb3 = __floats2bfloat162_rn(e12, e13);
        uint32_t pa0 = *(uint32_t*)&pb0, pa1 = *(uint32_t*)&pb1;
        uint32_t pa2 = *(uint32_t*)&pb2, pa3 = *(uint32_t*)&pb3;
        int j2 = jc >> 1;
        #pragma unroll
        for (int nt = 0; nt < 4; nt++) {
            uint32_t vb0 = Vs[(nt * 8 + g) * 132 + j2 + t4];
            uint32_t vb1 = Vs[(nt * 8 + g) * 132 + j2 + t4 + 4];
            MMA_BF16(o[nt], pa0, pa1, pa2, pa3, vb0, vb1);
        }
    }
    lsum0 += __shfl_xor_sync(0xffffffffu, lsum0, 1);
    lsum0 += __shfl_xor_sync(0xffffffffu, lsum0, 2);
    lsum1 += __shfl_xor_sync(0xffffffffu, lsum1, 1);
    lsum1 += __shfl_xor_sync(0xffffffffu, lsum1, 2);
    float inv0 = 1.f / lsum0, inv1 = 1.f / lsum1;
    float* ob = out + (long)b * CDIM * HW + (long)(hh * 32) * HW + p0;
    int r0 = wrow + g, r1 = r0 + 8;
    #pragma unroll
    for (int nt = 0; nt < 4; nt++) {
        int d = nt * 8 + 2 * t4;
        ob[(long)d * HW + r0]       = o[nt][0] * inv0;
        ob[(long)(d + 1) * HW + r0] = o[nt][1] * inv0;
        ob[(long)d * HW + r1]       = o[nt][2] * inv1;
        ob[(long)(d + 1) * HW + r1] = o[nt][3] * inv1;
    }
}

// ---------------- depthwise 3x3 SAME (small branch, writes into cat) ----------------
__global__ __launch_bounds__(256) void dwconv_kernel(const float* __restrict__ in,
                                                     const float* __restrict__ w,
                                                     const float* __restrict__ bias,
                                                     float* __restrict__ out,
                                                     int C, long inBS, long outBS, int chanOff)
{
    int idx = blockIdx.x;
    int yt = idx & 15; idx >>= 4;
    int c = idx % C; int b = idx / C;
    int x = threadIdx.x & 63;
    int y = yt * 4 + (threadIdx.x >> 6);
    const float* ip = in + (long)b * inBS + (long)c * HW;
    const float* wp = w + c * 9;
    float s = bias[c];
    #pragma unroll
    for (int dy = 0; dy < 3; dy++) {
        int yy = y + dy - 1;
        if (yy < 0 || yy > 63) continue;
        #pragma unroll
        for (int dx = 0; dx < 3; dx++) {
            int xx = x + dx - 1;
            if (xx < 0 || xx > 63) continue;
            s += wp[dy * 3 + dx] * ip[yy * 64 + xx];
        }
    }
    out[(long)b * outBS + (long)(chanOff + c) * HW + y * 64 + x] = s;
}

// ---------------- gelu ----------------
__device__ __forceinline__ float gelu_exact(float u)
{
    return 0.5f * u * (1.f + erff(u * 0.7071067811865476f));
}

// ---------------- fused: hg=gelu(IN(h)); h = hg + gelu(IN(dw(hg)))  (in place) -----
__global__ __launch_bounds__(256) void dwin2_kernel(float* __restrict__ h,
                                                    const float* __restrict__ w,
                                                    const float* __restrict__ bias)
{
    __shared__ float tile[HW];
    __shared__ float red[16];
    long row = blockIdx.x;
    int c = (int)(row & (FFI - 1));
    int t = threadIdx.x;
    float* hp = h + row * HW;

    // pass 1: stats of h row
    float4 v[4];
    float s = 0.f, s2 = 0.f;
    #pragma unroll
    for (int i = 0; i < 4; i++) {
        v[i] = ((const float4*)hp)[t + i * 256];
        s  += v[i].x + v[i].y + v[i].z + v[i].w;
        s2 += v[i].x * v[i].x + v[i].y * v[i].y + v[i].z * v[i].z + v[i].w * v[i].w;
    }
    #pragma unroll
    for (int o = 16; o > 0; o >>= 1) {
        s  += __shfl_xor_sync(0xffffffffu, s, o);
        s2 += __shfl_xor_sync(0xffffffffu, s2, o);
    }
    if ((t & 31) == 0) { red[t >> 5] = s; red[8 + (t >> 5)] = s2; }
    __syncthreads();
    if (t == 0) {
        float a = 0.f, b2 = 0.f;
        for (int i = 0; i < 8; i++) { a += red[i]; b2 += red[8 + i]; }
        red[0] = a; red[8] = b2;
    }
    __syncthreads();
    float mean = red[0] * (1.f / HW);
    float var  = red[8] * (1.f / HW) - mean * mean;
    float inv  = rsqrtf(var + 1e-5f);

    float wr[9];
    #pragma unroll
    for (int i = 0; i < 9; i++) wr[i] = w[c * 9 + i];
    float bb = bias[c];

    // tile = hg = gelu(IN(h))
    #pragma unroll
    for (int i = 0; i < 4; i++) {
        float4 u = v[i];
        u.x = gelu_exact((u.x - mean) * inv);
        u.y = gelu_exact((u.y - mean) * inv);
        u.z = gelu_exact((u.z - mean) * inv);
        u.w = gelu_exact((u.w - mean) * inv);
        ((float4*)tile)[t + i * 256] = u;
    }
    __syncthreads();

    // dwconv on tile + stats
    float r[16];
    float q = 0.f, q2 = 0.f;
    #pragma unroll
    for (int i = 0; i < 16; i++) {
        int px = t + i * 256;
        int y = px >> 6, x = px & 63;
        float a = bb;
        #pragma unroll
        for (int dy = 0; dy < 3; dy++) {
            int yy = y + dy - 1;
            if (yy < 0 || yy > 63) continue;
            #pragma unroll
            for (int dx = 0; dx < 3; dx++) {
                int xx = x + dx - 1;
                if (xx < 0 || xx > 63) continue;
                a += wr[dy * 3 + dx] * tile[yy * 64 + xx];
            }
        }
        r[i] = a; q += a; q2 += a * a;
    }
    #pragma unroll
    for (int o = 16; o > 0; o >>= 1) {
        q  += __shfl_xor_sync(0xffffffffu, q, o);
        q2 += __shfl_xor_sync(0xffffffffu, q2, o);
    }
    if ((t & 31) == 0) { red[t >> 5] = q; red[8 + (t >> 5)] = q2; }
    __syncthreads();
    if (t == 0) {
        float a = 0.f, b2 = 0.f;
        for (int i = 0; i < 8; i++) { a += red[i]; b2 += red[8 + i]; }
        red[0] = a; red[8] = b2;
    }
    __syncthreads();
    float mean2 = red[0] * (1.f / HW);
    float var2  = red[8] * (1.f / HW) - mean2 * mean2;
    float inv2  = rsqrtf(var2 + 1e-5f);
    #pragma unroll
    for (int i = 0; i < 16; i++) {
        int px = t + i * 256;
        hp[px] = tile[px] + gelu_exact((r[i] - mean2) * inv2);
    }
}

// ---------------- instance norm (final) ----------------
__global__ __launch_bounds__(256) void instnorm_kernel(const float* __restrict__ in,
                                                       float* __restrict__ out)
{
    __shared__ float sm[16];
    long row = blockIdx.x;
    const float4* p = (const float4*)(in + row * HW);
    int t = threadIdx.x;
    float4 v[4];
    float s = 0.f, s2 = 0.f;
    #pragma unroll
    for (int i = 0; i < 4; i++) {
        v[i] = p[t + i * 256];
        s  += v[i].x + v[i].y + v[i].z + v[i].w;
        s2 += v[i].x * v[i].x + v[i].y * v[i].y + v[i].z * v[i].z + v[i].w * v[i].w;
    }
    #pragma unroll
    for (int o = 16; o > 0; o >>= 1) {
        s  += __shfl_xor_sync(0xffffffffu, s, o);
        s2 += __shfl_xor_sync(0xffffffffu, s2, o);
    }
    if ((t & 31) == 0) { sm[t >> 5] = s; sm[8 + (t >> 5)] = s2; }
    __syncthreads();
    if (t == 0) {
        float a = 0.f, b2 = 0.f;
        for (int i = 0; i < 8; i++) { a += sm[i]; b2 += sm[8 + i]; }
        sm[0] = a; sm[8] = b2;
    }
    __syncthreads();
    float mean = sm[0] * (1.f / HW);
    float var  = sm[8] * (1.f / HW) - mean * mean;
    float inv  = rsqrtf(var + 1e-5f);
    float4* op = (float4*)(out + row * HW);
    #pragma unroll
    for (int i = 0; i < 4; i++) {
        float4 u = v[i];
        u.x = (u.x - mean) * inv; u.y = (u.y - mean) * inv;
        u.z = (u.z - mean) * inv; u.w = (u.w - mean) * inv;
        op[t + i * 256] = u;
    }
}

// ---------------- host launcher ----------------
extern "C" void kernel_launch(void* const* d_in, const int* in_sizes, int n_in,
                              void* d_out, int out_size)
{
    (void)in_sizes; (void)n_in; (void)out_size;
    const float* x      = (const float*)d_in[0];
    const float* ln_g   = (const float*)d_in[1];
    const float* ln_b   = (const float*)d_in[2];
    const float* w_qkv  = (const float*)d_in[3];
    const float* w_out  = (const float*)d_in[4];
    const float* b_out  = (const float*)d_in[5];
    const float* w_dw   = (const float*)d_in[6];
    const float* b_dw   = (const float*)d_in[7];
    const float* w_comb = (const float*)d_in[8];
    const float* b_comb = (const float*)d_in[9];
    const float* w_ff1  = (const float*)d_in[10];
    const float* b_ff1  = (const float*)d_in[11];
    const float* w_ffdw = (const float*)d_in[12];
    const float* b_ffdw = (const float*)d_in[13];
    const float* w_ff2  = (const float*)d_in[14];
    const float* b_ff2  = (const float*)d_in[15];
    float* out = (float*)d_out;

    void *p;
    cudaGetSymbolAddress(&p, g_xn);   float* xn   = (float*)p;
    cudaGetSymbolAddress(&p, g_qkv);  float* qkv  = (float*)p;
    cudaGetSymbolAddress(&p, g_attn); float* attn = (float*)p;
    cudaGetSymbolAddress(&p, g_cat);  float* cat  = (float*)p;
    cudaGetSymbolAddress(&p, g_ao);   float* ao   = (float*)p;
    cudaGetSymbolAddress(&p, g_h);    float* h    = (float*)p;
    cudaGetSymbolAddress(&p, g_kg);   float* kg   = (float*)p;
    cudaGetSymbolAddress(&p, g_vg);   float* vg   = (float*)p;
    cudaGetSymbolAddress(&p, g_kf);   uint32_t* kf = (uint32_t*)p;
    cudaGetSymbolAddress(&p, g_vt);   uint32_t* vt = (uint32_t*)p;
    cudaGetSymbolAddress(&p, g_qp);   float* qp   = (float*)p;
    cudaGetSymbolAddress(&p, g_kh);   float* kh   = (float*)p;
    cudaGetSymbolAddress(&p, g_topH); int*   topH = (int*)p;
    cudaGetSymbolAddress(&p, g_topW); int*   topW = (int*)p;

    cudaFuncSetAttribute(bgemm_kernel, cudaFuncAttributeMaxDynamicSharedMemorySize,
                         BGEMM_SMEM);
    cudaFuncSetAttribute(tgemm_kernel, cudaFuncAttributeMaxDynamicSharedMemorySize,
                         TGEMM_SMEM);

    // 1. channel layernorm
    ln_kernel<<<128, 256>>>(x, ln_g, ln_b, xn);
    // 2. qkv projection (bf16x3: near-fp32, protects top-k selection)
    bgemm_kernel<<<dim3(32, 6, BD), 256, BGEMM_SMEM>>>(w_qkv, xn, qkv, 768, HW, 256,
                                           (long)CDIM * HW, (long)768 * HW,
                                           nullptr, nullptr, 0);
    // 3. l2-normalize q,k along W (in place)
    l2norm_kernel<<<32768, 256>>>(qkv);
    // 4. probes + top-k selection
    qprobe_kernel<<<2048, 256>>>(qkv, qp);
    kheight_kernel<<<16384, 256>>>(qkv, kh);
    toph_kernel<<<64, 64>>>(qp, kh, topH);
    gather_rows_kernel<<<8192, 256>>>(qkv, topH, kg, vg);
    topw_kernel<<<64, 64>>>(qp, kg, topW);
    build_kv_kernel<<<1024, 256>>>(kg, vg, topW, kf, vt);
    // 5. tensor-core sparse attention
    attn_kernel<<<dim3(32, NBH), 256>>>(qkv, kf, vt, attn);
    // 6. out-proj into concat buffer rows [0,256)  (bf16x3)
    bgemm_kernel<<<dim3(32, 2, BD), 256, BGEMM_SMEM>>>(w_out, attn, cat, 256, HW, 256,
                                           (long)CDIM * HW, (long)512 * HW,
                                           b_out, nullptr, 0);
    // 7. dwconv branch into concat buffer rows [256,512)
    dwconv_kernel<<<BD * 256 * 16, 256>>>(x, w_dw, b_dw, cat, 256,
                                          (long)CDIM * HW, (long)512 * HW, 256);
    // 8. combine (K=512) + bias + residual x  (bf16x3)
    bgemm_kernel<<<dim3(32, 2, BD), 256, BGEMM_SMEM>>>(w_comb, cat, ao, 256, HW, 512,
                                           (long)512 * HW, (long)CDIM * HW,
                                           b_comb, x, (long)CDIM * HW);
    // 9. ff1 (single-pass TF32)
    tgemm_kernel<<<dim3(32, 8, BD), 256, TGEMM_SMEM>>>(w_ff1, ao, h, FFI, HW, 256,
                                           (long)CDIM * HW, (long)FFI * HW,
                                           b_ff1, nullptr, 0);
    // 10-12. h = hg + gelu(IN(dw(hg))) with hg = gelu(IN(h)) -- fully fused, in place
    dwin2_kernel<<<BD * FFI, 256>>>(h, w_ffdw, b_ffdw);
    // 13. ff2 (single-pass TF32; reuse xn buffer for output)
    tgemm_kernel<<<dim3(32, 2, BD), 256, TGEMM_SMEM>>>(w_ff2, h, xn, 256, HW, 1024,
                                           (long)FFI * HW, (long)CDIM * HW,
                                           b_ff2, nullptr, 0);
    // 14. final instance norm -> d_out
    instnorm_kernel<<<BD * CDIM, 256>>>(xn, out);
}

// round 16
// speedup vs baseline: 1.6943x; 1.0273x over previous
#include <cuda_runtime.h>
#include <cuda_bf16.h>
#include <math.h>
#include <stdint.h>

// ---------------- problem constants ----------------
#define BD     8          // batch
#define HEADS  8
#define DH     32         // dim head
#define CDIM   256        // model dim
#define FFI    1024       // ff inner
#define HW     4096       // 64*64 pixels
#define WID    64
#define NBH    64         // BD*HEADS
#define NKEY   256        // TOP_H * TOP_W

// ---------------- scratch (device globals: no allocs allowed) ----------------
__device__ float g_xn  [(long)BD*CDIM*HW];   // LN(x); reused for ff2 output
__device__ float g_qkv [(long)BD*768*HW];
__device__ float g_attn[(long)BD*CDIM*HW];
__device__ float g_cat [(long)BD*512*HW];
__device__ float g_ao  [(long)BD*CDIM*HW];
__device__ float g_h   [(long)BD*FFI*HW];
__device__ float g_kg  [NBH*DH*16*WID];
__device__ float g_vg  [NBH*DH*16*WID];
__device__ uint32_t g_kf [NBH*NKEY*16];      // bf16x2: [bh][key][dim-pair]
__device__ uint32_t g_vt [NBH*DH*128];       // bf16x2: [bh][dim][key-pair]
__device__ float g_qp  [NBH*DH];
__device__ float g_kh  [NBH*DH*WID];
__device__ float g_qrow[NBH*DH*WID];
__device__ int   g_topH[NBH*16];
__device__ int   g_topW[NBH*16];

// ---------------- channel layernorm (per pixel over 256 channels) ----------------
__global__ __launch_bounds__(256) void ln_kernel(const float* __restrict__ x,
                                                 const float* __restrict__ g,
                                                 const float* __restrict__ be,
                                                 float* __restrict__ out)
{
    int gp = blockIdx.x * 256 + threadIdx.x;           // 0..32767
    int b = gp >> 12, p = gp & 4095;
    const float* base = x + (long)b * CDIM * HW + p;
    float s = 0.f, s2 = 0.f;
    #pragma unroll 8
    for (int c = 0; c < CDIM; c++) { float v = base[(long)c * HW]; s += v; s2 += v * v; }
    float mean = s * (1.f / CDIM);
    float var  = s2 * (1.f / CDIM) - mean * mean;
    float inv  = rsqrtf(var + 1e-5f);
    float* ob = out + (long)b * CDIM * HW + p;
    #pragma unroll 8
    for (int c = 0; c < CDIM; c++) {
        float v = base[(long)c * HW];
        ob[(long)c * HW] = (v - mean) * inv * g[c] + be[c];
    }
}

// =====================================================================
// bf16x3 tensor-core GEMM (m16n8k16): near-fp32 accuracy, 3 mma / k16.
// 2 CTAs/SM (4 warps/SMSP) to hide fragment-LDS latency.
// =====================================================================

__device__ __forceinline__ void bfsplit2(float x0, float x1,
                                         uint32_t& big, uint32_t& sml)
{
    __nv_bfloat162 b = __floats2bfloat162_rn(x0, x1);
    float2 bf = __bfloat1622float2(b);
    __nv_bfloat162 s = __floats2bfloat162_rn(x0 - bf.x, x1 - bf.y);
    big = *reinterpret_cast<uint32_t*>(&b);
    sml = *reinterpret_cast<uint32_t*>(&s);
}

#define MMA_BF16(c, a0, a1, a2, a3, b0, b1) \
    asm volatile("mma.sync.aligned.m16n8k16.row.col.f32.bf16.bf16.f32 " \
        "{%0,%1,%2,%3}, {%4,%5,%6,%7}, {%8,%9}, {%0,%1,%2,%3};" \
        : "+f"((c)[0]), "+f"((c)[1]), "+f"((c)[2]), "+f"((c)[3]) \
        : "r"(a0), "r"(a1), "r"(a2), "r"(a3), "r"(b0), "r"(b1))

#define BG_AFS 132
#define BG_BFS 66
#define BG_AW  (8 * BG_AFS)
#define BG_BW  (16 * BG_BFS)
#define BG_STAGE (2 * BG_AW + 2 * BG_BW)
#define BGEMM_SMEM (2 * BG_STAGE * 4)

__global__ __launch_bounds__(256, 2) void bgemm_kernel(
    const float* __restrict__ A, const float* __restrict__ B, float* __restrict__ C,
    int M, int N, int K, long strideB, long strideC,
    const float* __restrict__ bias, const float* __restrict__ res, long strideRes)
{
    extern __shared__ uint32_t sh[];
    int tid = threadIdx.x;
    int lane = tid & 31, warp = tid >> 5;
    int bx = blockIdx.x * 128, by = blockIdx.y * 128;
    const float* Bp = B + (long)blockIdx.z * strideB;
    float*       Cp = C + (long)blockIdx.z * strideC;

    float acc[4][4][4];
    #pragma unroll
    for (int i = 0; i < 4; i++)
        #pragma unroll
        for (int j = 0; j < 4; j++)
            #pragma unroll
            for (int k = 0; k < 4; k++) acc[i][j][k] = 0.f;

    int af = tid >> 5, als = tid & 31;
    long aRow = by + af * 16 + (als >> 2);
    int  aK   = (als & 3) * 2;
    const float* aBase = A + aRow * K + aK;
    int bls = tid & 31;
    int bn0 = bx + (tid >> 5) * 8 + (bls >> 2);
    int bn1 = bn0 + 64;
    int bK  = (bls & 3) * 2;

    float2 pa[4];
    float  pbv[2][4];

    {
        pa[0] = *(const float2*)(aBase);
        pa[1] = *(const float2*)(aBase + 8);
        pa[2] = *(const float2*)(aBase + 8 * K);
        pa[3] = *(const float2*)(aBase + 8 * K + 8);
        #pragma unroll
        for (int u = 0; u < 2; u++) {
            int n = u ? bn1 : bn0;
            pbv[u][0] = Bp[(long)(bK)     * N + n];
            pbv[u][1] = Bp[(long)(bK + 1) * N + n];
            pbv[u][2] = Bp[(long)(bK + 8) * N + n];
            pbv[u][3] = Bp[(long)(bK + 9) * N + n];
        }
    }

    int nIter = K >> 4;

    auto stage = [&](uint32_t* base) {
        uint32_t* AsB = base;
        uint32_t* AsS = base + BG_AW;
        uint32_t* BsB = base + 2 * BG_AW;
        uint32_t* BsS = BsB + BG_BW;
        uint32_t a0b, a0s, a1b, a1s, a2b, a2s, a3b, a3s;
        bfsplit2(pa[0].x, pa[0].y, a0b, a0s);
        bfsplit2(pa[2].x, pa[2].y, a1b, a1s);
        bfsplit2(pa[1].x, pa[1].y, a2b, a2s);
        bfsplit2(pa[3].x, pa[3].y, a3b, a3s);
        *(uint4*)&AsB[af * BG_AFS + als * 4] = make_uint4(a0b, a1b, a2b, a3b);
        *(uint4*)&AsS[af * BG_AFS + als * 4] = make_uint4(a0s, a1s, a2s, a3s);
        #pragma unroll
        for (int u = 0; u < 2; u++) {
            int fn = (tid >> 5) + u * 8;
            uint32_t b0b, b0s, b1b, b1s;
            bfsplit2(pbv[u][0], pbv[u][1], b0b, b0s);
            bfsplit2(pbv[u][2], pbv[u][3], b1b, b1s);
            *(uint2*)&BsB[fn * BG_BFS + bls * 2] = make_uint2(b0b, b1b);
            *(uint2*)&BsS[fn * BG_BFS + bls * 2] = make_uint2(b0s, b1s);
        }
    };

    stage(sh);
    __syncthreads();

    int wmt = (warp >> 2) * 4;
    int wnt = (warp & 3) * 4;

    for (int it = 0; it < nIter; it++) {
        if (it + 1 < nIter) {
            int k0 = (it + 1) << 4;
            const float* ap = aBase + k0;
            pa[0] = *(const float2*)(ap);
            pa[1] = *(const float2*)(ap + 8);
            pa[2] = *(const float2*)(ap + 8 * K);
            pa[3] = *(const float2*)(ap + 8 * K + 8);
            #pragma unroll
            for (int u = 0; u < 2; u++) {
                int n = u ? bn1 : bn0;
                pbv[u][0] = Bp[(long)(k0 + bK)     * N + n];
                pbv[u][1] = Bp[(long)(k0 + bK + 1) * N + n];
                pbv[u][2] = Bp[(long)(k0 + bK + 8) * N + n];
                pbv[u][3] = Bp[(long)(k0 + bK + 9) * N + n];
            }
        }
        {
            uint32_t* base = sh + (it & 1) * BG_STAGE;
            const uint32_t* AsB = base;
            const uint32_t* AsS = base + BG_AW;
            const uint32_t* BsB = base + 2 * BG_AW;
            const uint32_t* BsS = BsB + BG_BW;
            uint2 bB[4], bS[4];
            #pragma unroll
            for (int nt = 0; nt < 4; nt++) {
                bB[nt] = *(const uint2*)&BsB[(wnt + nt) * BG_BFS + lane * 2];
                bS[nt] = *(const uint2*)&BsS[(wnt + nt) * BG_BFS + lane * 2];
            }
            #pragma unroll
            for (int mt = 0; mt < 4; mt++) {
                uint4 aB = *(const uint4*)&AsB[(wmt + mt) * BG_AFS + lane * 4];
                uint4 aS = *(const uint4*)&AsS[(wmt + mt) * BG_AFS + lane * 4];
                #pragma unroll
                for (int nt = 0; nt < 4; nt++)
                    MMA_BF16(acc[mt][nt], aB.x, aB.y, aB.z, aB.w, bB[nt].x, bB[nt].y);
                #pragma unroll
                for (int nt = 0; nt < 4; nt++)
                    MMA_BF16(acc[mt][nt], aB.x, aB.y, aB.z, aB.w, bS[nt].x, bS[nt].y);
                #pragma unroll
                for (int nt = 0; nt < 4; nt++)
                    MMA_BF16(acc[mt][nt], aS.x, aS.y, aS.z, aS.w, bB[nt].x, bB[nt].y);
            }
        }
        if (it + 1 < nIter) stage(sh + ((it + 1) & 1) * BG_STAGE);
        __syncthreads();
    }

    int wm = (warp >> 2) * 64, wn = (warp & 3) * 32;
    int mr = lane >> 2, qc = (lane & 3) * 2;
    #pragma unroll
    for (int mt = 0; mt < 4; mt++) {
        int r0 = by + wm + mt * 16 + mr;
        float bb0 = bias ? bias[r0] : 0.f;
        float bb1 = bias ? bias[r0 + 8] : 0.f;
        #pragma unroll
        for (int nt = 0; nt < 4; nt++) {
            int c = bx + wn + nt * 8 + qc;
            long o0 = (long)r0 * N + c;
            long o1 = (long)(r0 + 8) * N + c;
            float2 v0 = make_float2(acc[mt][nt][0] + bb0, acc[mt][nt][1] + bb0);
            float2 v1 = make_float2(acc[mt][nt][2] + bb1, acc[mt][nt][3] + bb1);
            if (res) {
                const float* rp = res + (long)blockIdx.z * strideRes;
                v0.x += rp[o0]; v0.y += rp[o0 + 1];
                v1.x += rp[o1]; v1.y += rp[o1 + 1];
            }
            *(float2*)&Cp[o0] = v0;
            *(float2*)&Cp[o1] = v1;
        }
    }
}

// =====================================================================
// single-pass TF32 GEMM (ff1/ff2); 2 CTAs/SM.
// =====================================================================

__device__ __forceinline__ uint32_t f2tf(float x)
{
    uint32_t r;
    asm("cvt.rna.tf32.f32 %0, %1;" : "=r"(r) : "f"(x));
    return r;
}

#define MMA_TF32(c, a0, a1, a2, a3, b0, b1) \
    asm volatile("mma.sync.aligned.m16n8k8.row.col.f32.tf32.tf32.f32 " \
        "{%0,%1,%2,%3}, {%4,%5,%6,%7}, {%8,%9}, {%0,%1,%2,%3};" \
        : "+f"((c)[0]), "+f"((c)[1]), "+f"((c)[2]), "+f"((c)[3]) \
        : "r"(a0), "r"(a1), "r"(a2), "r"(a3), "r"(b0), "r"(b1))

#define AFRAG_STRIDE 132
#define BFRAG_STRIDE 66
#define AWORDS (16 * AFRAG_STRIDE)
#define BWORDS (32 * BFRAG_STRIDE)
#define TGEMM_STAGE (AWORDS + BWORDS)
#define TGEMM_SMEM (2 * TGEMM_STAGE * 4)

__global__ __launch_bounds__(256, 2) void tgemm_kernel(
    const float* __restrict__ A, const float* __restrict__ B, float* __restrict__ C,
    int M, int N, int K, long strideB, long strideC,
    const float* __restrict__ bias, const float* __restrict__ res, long strideRes)
{
    extern __shared__ uint32_t sh[];
    int tid = threadIdx.x;
    int lane = tid & 31, warp = tid >> 5;
    int bx = blockIdx.x * 128, by = blockIdx.y * 128;
    const float* Bp = B + (long)blockIdx.z * strideB;
    float*       Cp = C + (long)blockIdx.z * strideC;

    float acc[4][4][4];
    #pragma unroll
    for (int i = 0; i < 4; i++)
        #pragma unroll
        for (int j = 0; j < 4; j++)
            #pragma unroll
            for (int k = 0; k < 4; k++) acc[i][j][k] = 0.f;

    int sA0f = tid >> 5, sA0l = tid & 31;
    int sA1f = (tid + 256) >> 5, sA1l = tid & 31;
    long aOff0 = (long)(by + (sA0f >> 1) * 16 + (sA0l >> 2)) * K + (sA0f & 1) * 8 + (sA0l & 3);
    long aOff1 = (long)(by + (sA1f >> 1) * 16 + (sA1l >> 2)) * K + (sA1f & 1) * 8 + (sA1l & 3);
    int bK0 = tid >> 5, bN0 = (tid & 31) * 4;
    int bK1 = (tid + 256) >> 5, bN1 = (tid & 31) * 4;

    float pa[8];
    float4 pb[2];

    {
        const float* ap0 = A + aOff0; const float* ap1 = A + aOff1;
        pa[0] = ap0[0]; pa[1] = ap0[8 * K]; pa[2] = ap0[4]; pa[3] = ap0[8 * K + 4];
        pa[4] = ap1[0]; pa[5] = ap1[8 * K]; pa[6] = ap1[4]; pa[7] = ap1[8 * K + 4];
        pb[0] = *(const float4*)(Bp + (long)bK0 * N + bx + bN0);
        pb[1] = *(const float4*)(Bp + (long)bK1 * N + bx + bN1);
    }

    int nIter = K >> 4;

    auto stage = [&](uint32_t* base) {
        uint32_t* AsB = base;
        uint32_t* BsB = base + AWORDS;
        #pragma unroll
        for (int u = 0; u < 2; u++) {
            int f = u ? sA1f : sA0f, ls = u ? sA1l : sA0l;
            uint32_t bg[4];
            #pragma unroll
            for (int j = 0; j < 4; j++) bg[j] = f2tf(pa[u * 4 + j]);
            *(uint4*)&AsB[f * AFRAG_STRIDE + ls * 4] = make_uint4(bg[0], bg[1], bg[2], bg[3]);
            int kb = u ? bK1 : bK0, nb = u ? bN1 : bN0;
            float bv[4] = { pb[u].x, pb[u].y, pb[u].z, pb[u].w };
            #pragma unroll
            for (int j = 0; j < 4; j++) {
                int n = nb + j;
                int fB = (n >> 3) * 2 + (kb >> 3);
                int bl = ((n & 7) << 2) | (kb & 3);
                int rg = (kb >> 2) & 1;
                BsB[fB * BFRAG_STRIDE + bl * 2 + rg] = f2tf(bv[j]);
            }
        }
    };

    stage(sh);
    __syncthreads();

    int wmt = (warp >> 2) * 4;
    int wnt = (warp & 3) * 4;

    for (int it = 0; it < nIter; it++) {
        if (it + 1 < nIter) {
            int k0 = (it + 1) << 4;
            const float* ap0 = A + aOff0 + k0; const float* ap1 = A + aOff1 + k0;
            pa[0] = ap0[0]; pa[1] = ap0[8 * K]; pa[2] = ap0[4]; pa[3] = ap0[8 * K + 4];
            pa[4] = ap1[0]; pa[5] = ap1[8 * K]; pa[6] = ap1[4]; pa[7] = ap1[8 * K + 4];
            pb[0] = *(const float4*)(Bp + (long)(k0 + bK0) * N + bx + bN0);
            pb[1] = *(const float4*)(Bp + (long)(k0 + bK1) * N + bx + bN1);
        }
        {
            uint32_t* base = sh + (it & 1) * TGEMM_STAGE;
            const uint32_t* AsB = base;
            const uint32_t* BsB = base + AWORDS;
            #pragma unroll
            for (int ks = 0; ks < 2; ks++) {
                uint2 bB[4];
                #pragma unroll
                for (int nt = 0; nt < 4; nt++) {
                    int fB = (wnt + nt) * 2 + ks;
                    bB[nt] = *(const uint2*)&BsB[fB * BFRAG_STRIDE + lane * 2];
                }
                #pragma unroll
                for (int mt = 0; mt < 4; mt++) {
                    int fA = (wmt + mt) * 2 + ks;
                    uint4 aB = *(const uint4*)&AsB[fA * AFRAG_STRIDE + lane * 4];
                    #pragma unroll
                    for (int nt = 0; nt < 4; nt++)
                        MMA_TF32(acc[mt][nt], aB.x, aB.y, aB.z, aB.w, bB[nt].x, bB[nt].y);
                }
            }
        }
        if (it + 1 < nIter) stage(sh + ((it + 1) & 1) * TGEMM_STAGE);
        __syncthreads();
    }

    int wm = (warp >> 2) * 64, wn = (warp & 3) * 32;
    int mr = lane >> 2, qc = (lane & 3) * 2;
    #pragma unroll
    for (int mt = 0; mt < 4; mt++) {
        int r0 = by + wm + mt * 16 + mr;
        float bb0 = bias ? bias[r0] : 0.f;
        float bb1 = bias ? bias[r0 + 8] : 0.f;
        #pragma unroll
        for (int nt = 0; nt < 4; nt++) {
            int c = bx + wn + nt * 8 + qc;
            long o0 = (long)r0 * N + c;
            long o1 = (long)(r0 + 8) * N + c;
            float2 v0 = make_float2(acc[mt][nt][0] + bb0, acc[mt][nt][1] + bb0);
            float2 v1 = make_float2(acc[mt][nt][2] + bb1, acc[mt][nt][3] + bb1);
            if (res) {
                const float* rp = res + (long)blockIdx.z * strideRes;
                v0.x += rp[o0]; v0.y += rp[o0 + 1];
                v1.x += rp[o1]; v1.y += rp[o1 + 1];
            }
            *(float2*)&Cp[o0] = v0;
            *(float2*)&Cp[o1] = v1;
        }
    }
}

// ---------------- l2-normalize q,k rows (along W=64) in place + row sums -----------
// q rows -> qrow (per-h sums, later folded into q_probe); k rows -> kh directly.
__global__ __launch_bounds__(256) void l2norm_kernel(float* __restrict__ qkv,
                                                     float* __restrict__ qrow,
                                                     float* __restrict__ kh)
{
    int gt = blockIdx.x * 256 + threadIdx.x;
    int warp = gt >> 5, lane = gt & 31;
    if (warp >= BD * 512 * WID) return;
    int b = warp / (512 * WID);
    int rem = warp % (512 * WID);
    float* p = qkv + (long)b * 768 * HW + (long)rem * WID;
    float v0 = p[lane], v1 = p[lane + 32];
    float s = v0 * v0 + v1 * v1;
    float t = v0 + v1;
    #pragma unroll
    for (int o = 16; o > 0; o >>= 1) {
        s += __shfl_xor_sync(0xffffffffu, s, o);
        t += __shfl_xor_sync(0xffffffffu, t, o);
    }
    float scale = 1.f / fmaxf(sqrtf(s), 1e-12f);
    p[lane] = v0 * scale; p[lane + 32] = v1 * scale;
    if (lane == 0) {
        int c = rem >> 6, h = rem & 63;
        float rowsum = t * scale;
        if (c < 256) {
            int bh = b * 8 + (c >> 5), d = c & 31;
            qrow[((bh * 32 + d) << 6) | h] = rowsum;
        } else {
            int c2 = c - 256;
            int bh = b * 8 + (c2 >> 5), d = c2 & 31;
            kh[((bh * 32 + d) << 6) | h] = rowsum;
        }
    }
}

// ---------------- q_probe[c] = sum over 64 h-rows of qrow ----------------
__global__ __launch_bounds__(256) void qpsum_kernel(const float* __restrict__ qrow,
                                                    float* __restrict__ qp)
{
    int c = blockIdx.x * 256 + threadIdx.x;          // 0..2047
    const float4* p = (const float4*)(qrow + (c << 6));
    float s = 0.f;
    #pragma unroll
    for (int i = 0; i < 16; i++) {
        float4 v = p[i];
        s += v.x + v.y + v.z + v.w;
    }
    qp[c] = s;
}

// ---------------- score_r + top-16 rows ----------------
__global__ void toph_kernel(const float* __restrict__ qp, const float* __restrict__ kh,
                            int* __restrict__ topH)
{
    __shared__ float sc[64]; __shared__ float qs[32];
    int bh = blockIdx.x, t = threadIdx.x;                  // 64 threads
    if (t < 32) qs[t] = qp[bh * 32 + t];
    __syncthreads();
    float s = 0.f;
    #pragma unroll
    for (int d = 0; d < 32; d++) s += qs[d] * kh[((bh * 32 + d) << 6) + t];
    sc[t] = s;
    __syncthreads();
    if (t == 0) {
        for (int it = 0; it < 16; it++) {
            float best = -3.4e38f; int bi = 0;
            for (int h = 0; h < 64; h++) if (sc[h] > best) { best = sc[h]; bi = h; }
            topH[bh * 16 + it] = bi; sc[bi] = -3.4e38f;
        }
    }
}

// ---------------- gather selected rows of k,v -> kg/vg [bh][d][16][64] -----------------
__global__ __launch_bounds__(256) void gather_rows_kernel(const float* __restrict__ qkv,
                                                          const int* __restrict__ topH,
                                                          float* __restrict__ kg,
                                                          float* __restrict__ vg)
{
    long i = (long)blockIdx.x * 256 + threadIdx.x;          // 64*32*16*64
    int w = i & 63; long r = i >> 6; int t = (int)(r & 15); r >>= 4;
    int d = (int)(r & 31); int bh = (int)(r >> 5);
    int b = bh >> 3, hh = bh & 7;
    int h = topH[bh * 16 + t];
    long base = (long)b * 768 * HW + (long)(hh * 32 + d) * HW + (long)h * WID + w;
    kg[i] = qkv[base + 256L * HW];
    vg[i] = qkv[base + 512L * HW];
}

// ---------------- score_c + top-16 columns ----------------
__global__ void topw_kernel(const float* __restrict__ qp, const float* __restrict__ kg,
                            int* __restrict__ topW)
{
    __shared__ float sc[64]; __shared__ float qs[32];
    int bh = blockIdx.x, t = threadIdx.x;                  // t = w, 64 threads
    if (t < 32) qs[t] = qp[bh * 32 + t];
    __syncthreads();
    float s = 0.f;
    for (int d = 0; d < 32; d++) {
        float colsum = 0.f;
        #pragma unroll
        for (int i = 0; i < 16; i++)
            colsum += kg[(((long)(bh * 32 + d) * 16) + i) * 64 + t];
        s += qs[d] * colsum;
    }
    sc[t] = s;
    __syncthreads();
    if (t == 0) {
        for (int it = 0; it < 16; it++) {
            float best = -3.4e38f; int bi = 0;
            for (int w = 0; w < 64; w++) if (sc[w] > best) { best = sc[w]; bi = w; }
            topW[bh * 16 + it] = bi; sc[bi] = -3.4e38f;
        }
    }
}

// ---------------- build kf (key-major) and vt (dim-major, transposed) ----------------
__global__ __launch_bounds__(256) void build_kv_kernel(const float* __restrict__ kg,
                                                       const float* __restrict__ vg,
                                                       const int* __restrict__ topW,
                                                       uint32_t* __restrict__ kf,
                                                       uint32_t* __restrict__ vt)
{
    int i = blockIdx.x * 256 + threadIdx.x;   // 262144
    {
        int d2 = i & 15; int j = (i >> 4) & 255; int bh = i >> 12;
        int ti = j >> 4, jw = j & 15;
        int w = topW[bh * 16 + jw];
        long src = (((long)(bh * 32 + 2 * d2) * 16) + ti) * 64 + w;
        __nv_bfloat162 kk = __floats2bfloat162_rn(kg[src], kg[src + 1024]);
        kf[i] = *(uint32_t*)&kk;
    }
    {
        int j2 = i & 127; int d = (i >> 7) & 31; int bh = i >> 12;
        int jA = 2 * j2, jB = jA + 1;
        int wA = topW[bh * 16 + (jA & 15)];
        int wB = topW[bh * 16 + (jB & 15)];
        long sA = (((long)(bh * 32 + d) * 16) + (jA >> 4)) * 64 + wA;
        long sB = (((long)(bh * 32 + d) * 16) + (jB >> 4)) * 64 + wB;
        __nv_bfloat162 vv = __floats2bfloat162_rn(vg[sA], vg[sB]);
        vt[i] = *(uint32_t*)&vv;
    }
}

// ---------------- tensor-core sparse attention: softmax(Q Kf^T) Vf ----------------
__global__ __launch_bounds__(256) void attn_kernel(const float* __restrict__ qkv,
                                                   const uint32_t* __restrict__ kf,
                                                   const uint32_t* __restrict__ vt,
                                                   float* __restrict__ out)
{
    __shared__ uint32_t Qs[128 * 20];
    __shared__ uint32_t Ks[256 * 20];
    __shared__ uint32_t Vs[32 * 132];
    int bh = blockIdx.y;
    int b = bh >> 3, hh = bh & 7;
    int p0 = blockIdx.x * 128;
    int tid = threadIdx.x, lane = tid & 31, warp = tid >> 5;
    int g = lane >> 2, t4 = lane & 3;

    const uint4* ksrc = (const uint4*)(kf + (long)bh * NKEY * 16);
    #pragma unroll
    for (int i = tid; i < 1024; i += 256) {
        int j = i >> 2, q4 = i & 3;
        *(uint4*)&Ks[j * 20 + q4 * 4] = ksrc[i];
    }
    const uint4* vsrc = (const uint4*)(vt + (long)bh * 32 * 128);
    #pragma unroll
    for (int i = tid; i < 1024; i += 256) {
        int d = i >> 5, q4 = i & 31;
        *(uint4*)&Vs[d * 132 + q4 * 4] = vsrc[i];
    }
    const float* qb = qkv + (long)b * 768 * HW + (long)(hh * 32) * HW + p0;
    #pragma unroll
    for (int i = tid; i < 2048; i += 256) {
        int row = i & 127, d2 = i >> 7;
        float f0 = qb[(long)(2 * d2) * HW + row];
        float f1 = qb[(long)(2 * d2 + 1) * HW + row];
        __nv_bfloat162 hb = __floats2bfloat162_rn(f0, f1);
        Qs[row * 20 + d2] = *(uint32_t*)&hb;
    }
    __syncthreads();

    int wrow = warp * 16;
    uint32_t qa[2][4];
    #pragma unroll
    for (int ks = 0; ks < 2; ks++) {
        int base = ks * 8;
        qa[ks][0] = Qs[(wrow + g) * 20 + base + t4];
        qa[ks][1] = Qs[(wrow + 8 + g) * 20 + base + t4];
        qa[ks][2] = Qs[(wrow + g) * 20 + base + t4 + 4];
        qa[ks][3] = Qs[(wrow + 8 + g) * 20 + base + t4 + 4];
    }
    float o[4][4];
    #pragma unroll
    for (int i = 0; i < 4; i++)
        #pragma unroll
        for (int j = 0; j < 4; j++) o[i][j] = 0.f;
    float lsum0 = 0.f, lsum1 = 0.f;

    #pragma unroll
    for (int jc = 0; jc < 256; jc += 16) {
        float s0[4] = {0.f, 0.f, 0.f, 0.f}, s1[4] = {0.f, 0.f, 0.f, 0.f};
        #pragma unroll
        for (int ks = 0; ks < 2; ks++) {
            int pb = ks * 8;
            uint32_t b0 = Ks[(jc + g) * 20 + pb + t4];
            uint32_t b1 = Ks[(jc + g) * 20 + pb + t4 + 4];
            MMA_BF16(s0, qa[ks][0], qa[ks][1], qa[ks][2], qa[ks][3], b0, b1);
            uint32_t b2 = Ks[(jc + 8 + g) * 20 + pb + t4];
            uint32_t b3 = Ks[(jc + 8 + g) * 20 + pb + t4 + 4];
            MMA_BF16(s1, qa[ks][0], qa[ks][1], qa[ks][2], qa[ks][3], b2, b3);
        }
        float e00 = __expf(s0[0]), e01 = __expf(s0[1]);
        float e02 = __expf(s0[2]), e03 = __expf(s0[3]);
        float e10 = __expf(s1[0]), e11 = __expf(s1[1]);
        float e12 = __expf(s1[2]), e13 = __expf(s1[3]);
        lsum0 += e00 + e01 + e10 + e11;
        lsum1 += e02 + e03 + e12 + e13;
        __nv_bfloat162 pb0 = __floats2bfloat162_rn(e00, e01);
        __nv_bfloat162 pb1 = __floats2bfloat162_rn(e02, e03);
        __nv_bfloat162 pb2 = __floats2bfloat162_rn(e10, e11);
        __nv_bfloat162 pb3 = __floats2bfloat162_rn(e12, e13);
        uint32_t pa0 = *(uint32_t*)&pb0, pa1 = *(uint32_t*)&pb1;
        uint32_t pa2 = *(uint32_t*)&pb2, pa3 = *(uint32_t*)&pb3;
        int j2 = jc >> 1;
        #pragma unroll
        for (int nt = 0; nt < 4; nt++) {
            uint32_t vb0 = Vs[(nt * 8 + g) * 132 + j2 + t4];
            uint32_t vb1 = Vs[(nt * 8 + g) * 132 + j2 + t4 + 4];
            MMA_BF16(o[nt], pa0, pa1, pa2, pa3, vb0, vb1);
        }
    }
    lsum0 += __shfl_xor_sync(0xffffffffu, lsum0, 1);
    lsum0 += __shfl_xor_sync(0xffffffffu, lsum0, 2);
    lsum1 += __shfl_xor_sync(0xffffffffu, lsum1, 1);
    lsum1 += __shfl_xor_sync(0xffffffffu, lsum1, 2);
    float inv0 = 1.f / lsum0, inv1 = 1.f / lsum1;
    float* ob = out + (long)b * CDIM * HW + (long)(hh * 32) * HW + p0;
    int r0 = wrow + g, r1 = r0 + 8;
    #pragma unroll
    for (int nt = 0; nt < 4; nt++) {
        int d = nt * 8 + 2 * t4;
        ob[(long)d * HW + r0]       = o[nt][0] * inv0;
        ob[(long)(d + 1) * HW + r0] = o[nt][1] * inv0;
        ob[(long)d * HW + r1]       = o[nt][2] * inv1;
        ob[(long)(d + 1) * HW + r1] = o[nt][3] * inv1;
    }
}

// ---------------- depthwise 3x3 SAME (small branch, writes into cat) ----------------
__global__ __launch_bounds__(256) void dwconv_kernel(const float* __restrict__ in,
                                                     const float* __restrict__ w,
                                                     const float* __restrict__ bias,
                                                     float* __restrict__ out,
                                                     int C, long inBS, long outBS, int chanOff)
{
    int idx = blockIdx.x;
    int yt = idx & 15; idx >>= 4;
    int c = idx % C; int b = idx / C;
    int x = threadIdx.x & 63;
    int y = yt * 4 + (threadIdx.x >> 6);
    const float* ip = in + (long)b * inBS + (long)c * HW;
    const float* wp = w + c * 9;
    float s = bias[c];
    #pragma unroll
    for (int dy = 0; dy < 3; dy++) {
        int yy = y + dy - 1;
        if (yy < 0 || yy > 63) continue;
        #pragma unroll
        for (int dx = 0; dx < 3; dx++) {
            int xx = x + dx - 1;
            if (xx < 0 || xx > 63) continue;
            s += wp[dy * 3 + dx] * ip[yy * 64 + xx];
        }
    }
    out[(long)b * outBS + (long)(chanOff + c) * HW + y * 64 + x] = s;
}

// ---------------- gelu ----------------
__device__ __forceinline__ float gelu_exact(float u)
{
    return 0.5f * u * (1.f + erff(u * 0.7071067811865476f));
}

// ---------------- fused: hg=gelu(IN(h)); h = hg + gelu(IN(dw(hg)))  (in place) -----
__global__ __launch_bounds__(256) void dwin2_kernel(float* __restrict__ h,
                                                    const float* __restrict__ w,
                                                    const float* __restrict__ bias)
{
    __shared__ float tile[HW];
    __shared__ float red[16];
    long row = blockIdx.x;
    int c = (int)(row & (FFI - 1));
    int t = threadIdx.x;
    float* hp = h + row * HW;

    float4 v[4];
    float s = 0.f, s2 = 0.f;
    #pragma unroll
    for (int i = 0; i < 4; i++) {
        v[i] = ((const float4*)hp)[t + i * 256];
        s  += v[i].x + v[i].y + v[i].z + v[i].w;
        s2 += v[i].x * v[i].x + v[i].y * v[i].y + v[i].z * v[i].z + v[i].w * v[i].w;
    }
    #pragma unroll
    for (int o = 16; o > 0; o >>= 1) {
        s  += __shfl_xor_sync(0xffffffffu, s, o);
        s2 += __shfl_xor_sync(0xffffffffu, s2, o);
    }
    if ((t & 31) == 0) { red[t >> 5] = s; red[8 + (t >> 5)] = s2; }
    __syncthreads();
    if (t == 0) {
        float a = 0.f, b2 = 0.f;
        for (int i = 0; i < 8; i++) { a += red[i]; b2 += red[8 + i]; }
        red[0] = a; red[8] = b2;
    }
    __syncthreads();
    float mean = red[0] * (1.f / HW);
    float var  = red[8] * (1.f / HW) - mean * mean;
    float inv  = rsqrtf(var + 1e-5f);

    float wr[9];
    #pragma unroll
    for (int i = 0; i < 9; i++) wr[i] = w[c * 9 + i];
    float bb = bias[c];

    #pragma unroll
    for (int i = 0; i < 4; i++) {
        float4 u = v[i];
        u.x = gelu_exact((u.x - mean) * inv);
        u.y = gelu_exact((u.y - mean) * inv);
        u.z = gelu_exact((u.z - mean) * inv);
        u.w = gelu_exact((u.w - mean) * inv);
        ((float4*)tile)[t + i * 256] = u;
    }
    __syncthreads();

    float r[16];
    float q = 0.f, q2 = 0.f;
    #pragma unroll
    for (int i = 0; i < 16; i++) {
        int px = t + i * 256;
        int y = px >> 6, x = px & 63;
        float a = bb;
        #pragma unroll
        for (int dy = 0; dy < 3; dy++) {
            int yy = y + dy - 1;
            if (yy < 0 || yy > 63) continue;
            #pragma unroll
            for (int dx = 0; dx < 3; dx++) {
                int xx = x + dx - 1;
                if (xx < 0 || xx > 63) continue;
                a += wr[dy * 3 + dx] * tile[yy * 64 + xx];
            }
        }
        r[i] = a; q += a; q2 += a * a;
    }
    #pragma unroll
    for (int o = 16; o > 0; o >>= 1) {
        q  += __shfl_xor_sync(0xffffffffu, q, o);
        q2 += __shfl_xor_sync(0xffffffffu, q2, o);
    }
    if ((t & 31) == 0) { red[t >> 5] = q; red[8 + (t >> 5)] = q2; }
    __syncthreads();
    if (t == 0) {
        float a = 0.f, b2 = 0.f;
        for (int i = 0; i < 8; i++) { a += red[i]; b2 += red[8 + i]; }
        red[0] = a; red[8] = b2;
    }
    __syncthreads();
    float mean2 = red[0] * (1.f / HW);
    float var2  = red[8] * (1.f / HW) - mean2 * mean2;
    float inv2  = rsqrtf(var2 + 1e-5f);
    #pragma unroll
    for (int i = 0; i < 16; i++) {
        int px = t + i * 256;
        hp[px] = tile[px] + gelu_exact((r[i] - mean2) * inv2);
    }
}

// ---------------- instance norm (final) ----------------
__global__ __launch_bounds__(256) void instnorm_kernel(const float* __restrict__ in,
                                                       float* __restrict__ out)
{
    __shared__ float sm[16];
    long row = blockIdx.x;
    const float4* p = (const float4*)(in + row * HW);
    int t = threadIdx.x;
    float4 v[4];
    float s = 0.f, s2 = 0.f;
    #pragma unroll
    for (int i = 0; i < 4; i++) {
        v[i] = p[t + i * 256];
        s  += v[i].x + v[i].y + v[i].z + v[i].w;
        s2 += v[i].x * v[i].x + v[i].y * v[i].y + v[i].z * v[i].z + v[i].w * v[i].w;
    }
    #pragma unroll
    for (int o = 16; o > 0; o >>= 1) {
        s  += __shfl_xor_sync(0xffffffffu, s, o);
        s2 += __shfl_xor_sync(0xffffffffu, s2, o);
    }
    if ((t & 31) == 0) { sm[t >> 5] = s; sm[8 + (t >> 5)] = s2; }
    __syncthreads();
    if (t == 0) {
        float a = 0.f, b2 = 0.f;
        for (int i = 0; i < 8; i++) { a += sm[i]; b2 += sm[8 + i]; }
        sm[0] = a; sm[8] = b2;
    }
    __syncthreads();
    float mean = sm[0] * (1.f / HW);
    float var  = sm[8] * (1.f / HW) - mean * mean;
    float inv  = rsqrtf(var + 1e-5f);
    float4* op = (float4*)(out + row * HW);
    #pragma unroll
    for (int i = 0; i < 4; i++) {
        float4 u = v[i];
        u.x = (u.x - mean) * inv; u.y = (u.y - mean) * inv;
        u.z = (u.z - mean) * inv; u.w = (u.w - mean) * inv;
        op[t + i * 256] = u;
    }
}

// ---------------- host launcher ----------------
extern "C" void kernel_launch(void* const* d_in, const int* in_sizes, int n_in,
                              void* d_out, int out_size)
{
    (void)in_sizes; (void)n_in; (void)out_size;
    const float* x      = (const float*)d_in[0];
    const float* ln_g   = (const float*)d_in[1];
    const float* ln_b   = (const float*)d_in[2];
    const float* w_qkv  = (const float*)d_in[3];
    const float* w_out  = (const float*)d_in[4];
    const float* b_out  = (const float*)d_in[5];
    const float* w_dw   = (const float*)d_in[6];
    const float* b_dw   = (const float*)d_in[7];
    const float* w_comb = (const float*)d_in[8];
    const float* b_comb = (const float*)d_in[9];
    const float* w_ff1  = (const float*)d_in[10];
    const float* b_ff1  = (const float*)d_in[11];
    const float* w_ffdw = (const float*)d_in[12];
    const float* b_ffdw = (const float*)d_in[13];
    const float* w_ff2  = (const float*)d_in[14];
    const float* b_ff2  = (const float*)d_in[15];
    float* out = (float*)d_out;

    void *p;
    cudaGetSymbolAddress(&p, g_xn);   float* xn   = (float*)p;
    cudaGetSymbolAddress(&p, g_qkv);  float* qkv  = (float*)p;
    cudaGetSymbolAddress(&p, g_attn); float* attn = (float*)p;
    cudaGetSymbolAddress(&p, g_cat);  float* cat  = (float*)p;
    cudaGetSymbolAddress(&p, g_ao);   float* ao   = (float*)p;
    cudaGetSymbolAddress(&p, g_h);    float* h    = (float*)p;
    cudaGetSymbolAddress(&p, g_kg);   float* kg   = (float*)p;
    cudaGetSymbolAddress(&p, g_vg);   float* vg   = (float*)p;
    cudaGetSymbolAddress(&p, g_kf);   uint32_t* kf = (uint32_t*)p;
    cudaGetSymbolAddress(&p, g_vt);   uint32_t* vt = (uint32_t*)p;
    cudaGetSymbolAddress(&p, g_qp);   float* qp   = (float*)p;
    cudaGetSymbolAddress(&p, g_kh);   float* kh   = (float*)p;
    cudaGetSymbolAddress(&p, g_qrow); float* qrow = (float*)p;
    cudaGetSymbolAddress(&p, g_topH); int*   topH = (int*)p;
    cudaGetSymbolAddress(&p, g_topW); int*   topW = (int*)p;

    cudaFuncSetAttribute(bgemm_kernel, cudaFuncAttributeMaxDynamicSharedMemorySize,
                         BGEMM_SMEM);
    cudaFuncSetAttribute(tgemm_kernel, cudaFuncAttributeMaxDynamicSharedMemorySize,
                         TGEMM_SMEM);

    // 1. channel layernorm
    ln_kernel<<<128, 256>>>(x, ln_g, ln_b, xn);
    // 2. qkv projection (bf16x3)
    bgemm_kernel<<<dim3(32, 6, BD), 256, BGEMM_SMEM>>>(w_qkv, xn, qkv, 768, HW, 256,
                                           (long)CDIM * HW, (long)768 * HW,
                                           nullptr, nullptr, 0);
    // 3. l2-normalize q,k (in place) + emit row sums (kh direct, qrow staged)
    l2norm_kernel<<<32768, 256>>>(qkv, qrow, kh);
    // 4. probes + top-k selection
    qpsum_kernel<<<8, 256>>>(qrow, qp);
    toph_kernel<<<64, 64>>>(qp, kh, topH);
    gather_rows_kernel<<<8192, 256>>>(qkv, topH, kg, vg);
    topw_kernel<<<64, 64>>>(qp, kg, topW);
    build_kv_kernel<<<1024, 256>>>(kg, vg, topW, kf, vt);
    // 5. tensor-core sparse attention
    attn_kernel<<<dim3(32, NBH), 256>>>(qkv, kf, vt, attn);
    // 6. out-proj into concat buffer rows [0,256)  (bf16x3)
    bgemm_kernel<<<dim3(32, 2, BD), 256, BGEMM_SMEM>>>(w_out, attn, cat, 256, HW, 256,
                                           (long)CDIM * HW, (long)512 * HW,
                                           b_out, nullptr, 0);
    // 7. dwconv branch into concat buffer rows [256,512)
    dwconv_kernel<<<BD * 256 * 16, 256>>>(x, w_dw, b_dw, cat, 256,
                                          (long)CDIM * HW, (long)512 * HW, 256);
    // 8. combine (K=512) + bias + residual x  (bf16x3)
    bgemm_kernel<<<dim3(32, 2, BD), 256, BGEMM_SMEM>>>(w_comb, cat, ao, 256, HW, 512,
                                           (long)512 * HW, (long)CDIM * HW,
                                           b_comb, x, (long)CDIM * HW);
    // 9. ff1 (single-pass TF32)
    tgemm_kernel<<<dim3(32, 8, BD), 256, TGEMM_SMEM>>>(w_ff1, ao, h, FFI, HW, 256,
                                           (long)CDIM * HW, (long)FFI * HW,
                                           b_ff1, nullptr, 0);
    // 10-12. h = hg + gelu(IN(dw(hg))) with hg = gelu(IN(h)) -- fused, in place
    dwin2_kernel<<<BD * FFI, 256>>>(h, w_ffdw, b_ffdw);
    // 13. ff2 (single-pass TF32; reuse xn buffer for output)
    tgemm_kernel<<<dim3(32, 2, BD), 256, TGEMM_SMEM>>>(w_ff2, h, xn, 256, HW, 1024,
                                           (long)FFI * HW, (long)CDIM * HW,
                                           b_ff2, nullptr, 0);
    // 14. final instance norm -> d_out
    instnorm_kernel<<<BD * CDIM, 256>>>(xn, out);
}

// round 17
// speedup vs baseline: 1.9477x; 1.1496x over previous
#include <cuda_runtime.h>
#include <cuda_bf16.h>
#include <math.h>
#include <stdint.h>

// ---------------- problem constants ----------------
#define BD     8          // batch
#define HEADS  8
#define DH     32         // dim head
#define CDIM   256        // model dim
#define FFI    1024       // ff inner
#define HW     4096       // 64*64 pixels
#define WID    64
#define NBH    64         // BD*HEADS
#define NKEY   256        // TOP_H * TOP_W

// ---------------- scratch (device globals: no allocs allowed) ----------------
__device__ float g_xn  [(long)BD*CDIM*HW];   // LN(x); reused for ff2 output
__device__ float g_qkv [(long)BD*768*HW];
__device__ float g_attn[(long)BD*CDIM*HW];
__device__ float g_cat [(long)BD*512*HW];
__device__ float g_ao  [(long)BD*CDIM*HW];
__device__ float g_h   [(long)BD*FFI*HW];
__device__ float g_kg  [NBH*DH*16*WID];
__device__ float g_vg  [NBH*DH*16*WID];
__device__ uint32_t g_kf [NBH*NKEY*16];      // bf16x2: [bh][key][dim-pair]
__device__ uint32_t g_vt [NBH*DH*128];       // bf16x2: [bh][dim][key-pair]
__device__ float g_qp  [NBH*DH];
__device__ float g_kh  [NBH*DH*WID];
__device__ float g_qrow[NBH*DH*WID];
__device__ int   g_topH[NBH*16];
__device__ int   g_topW[NBH*16];

// pre-packed weight fragments (bgemm: [2][rb][kc][256] uint4; tgemm: [rb][kc][512])
__device__ uint4 g_wqkv_p [2 * 6 * 16 * 256];   // 768x256 bf16x3
__device__ uint4 g_wout_p [2 * 2 * 16 * 256];   // 256x256
__device__ uint4 g_wcomb_p[2 * 2 * 32 * 256];   // 256x512
__device__ uint4 g_wff1_p [8 * 16 * 512];       // 1024x256 tf32
__device__ uint4 g_wff2_p [2 * 64 * 512];       // 256x1024 tf32

// ---------------- helpers ----------------
__device__ __forceinline__ void bfsplit2(float x0, float x1,
                                         uint32_t& big, uint32_t& sml)
{
    __nv_bfloat162 b = __floats2bfloat162_rn(x0, x1);
    float2 bf = __bfloat1622float2(b);
    __nv_bfloat162 s = __floats2bfloat162_rn(x0 - bf.x, x1 - bf.y);
    big = *reinterpret_cast<uint32_t*>(&b);
    sml = *reinterpret_cast<uint32_t*>(&s);
}

__device__ __forceinline__ uint32_t f2tf(float x)
{
    uint32_t r;
    asm("cvt.rna.tf32.f32 %0, %1;" : "=r"(r) : "f"(x));
    return r;
}

// ---------------- weight pre-pack: bf16 big/small fragment layout ----------------
__global__ __launch_bounds__(256) void pack_bw_kernel(const float* __restrict__ W,
                                                      uint4* __restrict__ out,
                                                      int M, int K)
{
    int idx = blockIdx.x * 256 + threadIdx.x;
    int total = (M >> 7) * (K >> 4) * 256;
    if (idx >= total) return;
    int lane = idx & 31;
    int f    = (idx >> 5) & 7;
    int kc   = (idx >> 8) % (K >> 4);
    int rb   = (idx >> 8) / (K >> 4);
    long row = rb * 128 + f * 16 + (lane >> 2);
    int  k   = kc * 16 + (lane & 3) * 2;
    const float* r0 = W + row * K + k;
    const float* r1 = W + (row + 8) * K + k;
    uint32_t b0, s0, b1, s1, b2, s2, b3, s3;
    bfsplit2(r0[0], r0[1], b0, s0);
    bfsplit2(r1[0], r1[1], b1, s1);
    bfsplit2(r0[8], r0[9], b2, s2);
    bfsplit2(r1[8], r1[9], b3, s3);
    out[idx]         = make_uint4(b0, b1, b2, b3);
    out[total + idx] = make_uint4(s0, s1, s2, s3);
}

// ---------------- weight pre-pack: tf32 fragment layout ----------------
__global__ __launch_bounds__(256) void pack_tw_kernel(const float* __restrict__ W,
                                                      uint4* __restrict__ out,
                                                      int M, int K)
{
    int idx = blockIdx.x * 256 + threadIdx.x;
    int total = (M >> 7) * (K >> 4) * 512;
    if (idx >= total) return;
    int ls = idx & 31;
    int f  = (idx >> 5) & 15;
    int kc = (idx >> 9) % (K >> 4);
    int rb = (idx >> 9) / (K >> 4);
    long row = rb * 128 + (f >> 1) * 16 + (ls >> 2);
    int  k   = kc * 16 + (f & 1) * 8 + (ls & 3);
    const float* ap = W + row * K + k;
    out[idx] = make_uint4(f2tf(ap[0]), f2tf(ap[8 * (long)K]),
                          f2tf(ap[4]), f2tf(ap[8 * (long)K + 4]));
}

// ---------------- channel layernorm (per pixel over 256 channels) ----------------
__global__ __launch_bounds__(256) void ln_kernel(const float* __restrict__ x,
                                                 const float* __restrict__ g,
                                                 const float* __restrict__ be,
                                                 float* __restrict__ out)
{
    int gp = blockIdx.x * 256 + threadIdx.x;           // 0..32767
    int b = gp >> 12, p = gp & 4095;
    const float* base = x + (long)b * CDIM * HW + p;
    float s = 0.f, s2 = 0.f;
    #pragma unroll 8
    for (int c = 0; c < CDIM; c++) { float v = base[(long)c * HW]; s += v; s2 += v * v; }
    float mean = s * (1.f / CDIM);
    float var  = s2 * (1.f / CDIM) - mean * mean;
    float inv  = rsqrtf(var + 1e-5f);
    float* ob = out + (long)b * CDIM * HW + p;
    #pragma unroll 8
    for (int c = 0; c < CDIM; c++) {
        float v = base[(long)c * HW];
        ob[(long)c * HW] = (v - mean) * inv * g[c] + be[c];
    }
}

// =====================================================================
// bf16x3 tensor-core GEMM (m16n8k16), pre-packed weights.
// =====================================================================

#define MMA_BF16(c, a0, a1, a2, a3, b0, b1) \
    asm volatile("mma.sync.aligned.m16n8k16.row.col.f32.bf16.bf16.f32 " \
        "{%0,%1,%2,%3}, {%4,%5,%6,%7}, {%8,%9}, {%0,%1,%2,%3};" \
        : "+f"((c)[0]), "+f"((c)[1]), "+f"((c)[2]), "+f"((c)[3]) \
        : "r"(a0), "r"(a1), "r"(a2), "r"(a3), "r"(b0), "r"(b1))

#define BG_AFS 132
#define BG_BFS 66
#define BG_AW  (8 * BG_AFS)
#define BG_BW  (16 * BG_BFS)
#define BG_STAGE (2 * BG_AW + 2 * BG_BW)
#define BGEMM_SMEM (2 * BG_STAGE * 4)

__global__ __launch_bounds__(256, 2) void bgemm_kernel(
    const uint4* __restrict__ Apack, const float* __restrict__ B, float* __restrict__ C,
    int M, int N, int K, long strideB, long strideC,
    const float* __restrict__ bias, const float* __restrict__ res, long strideRes)
{
    extern __shared__ uint32_t sh[];
    int tid = threadIdx.x;
    int lane = tid & 31, warp = tid >> 5;
    int bx = blockIdx.x * 128;
    const float* Bp = B + (long)blockIdx.z * strideB;
    float*       Cp = C + (long)blockIdx.z * strideC;
    int aHalf = (M >> 7) * (K >> 4) * 256;

    float acc[4][4][4];
    #pragma unroll
    for (int i = 0; i < 4; i++)
        #pragma unroll
        for (int j = 0; j < 4; j++)
            #pragma unroll
            for (int k = 0; k < 4; k++) acc[i][j][k] = 0.f;

    int bls = tid & 31;
    int bn0 = bx + (tid >> 5) * 8 + (bls >> 2);
    int bn1 = bn0 + 64;
    int bK  = (bls & 3) * 2;

    uint4 pAb, pAs;
    float pbv[2][4];

    {
        const uint4* Ap = Apack + ((long)(blockIdx.y * (K >> 4)) << 8);
        pAb = Ap[tid];
        pAs = Ap[aHalf + tid];
        #pragma unroll
        for (int u = 0; u < 2; u++) {
            int n = u ? bn1 : bn0;
            pbv[u][0] = Bp[(long)(bK)     * N + n];
            pbv[u][1] = Bp[(long)(bK + 1) * N + n];
            pbv[u][2] = Bp[(long)(bK + 8) * N + n];
            pbv[u][3] = Bp[(long)(bK + 9) * N + n];
        }
    }

    int nIter = K >> 4;

    auto stage = [&](uint32_t* base) {
        uint32_t* AsB = base;
        uint32_t* AsS = base + BG_AW;
        uint32_t* BsB = base + 2 * BG_AW;
        uint32_t* BsS = BsB + BG_BW;
        *(uint4*)&AsB[(tid >> 5) * BG_AFS + (tid & 31) * 4] = pAb;
        *(uint4*)&AsS[(tid >> 5) * BG_AFS + (tid & 31) * 4] = pAs;
        #pragma unroll
        for (int u = 0; u < 2; u++) {
            int fn = (tid >> 5) + u * 8;
            uint32_t b0b, b0s, b1b, b1s;
            bfsplit2(pbv[u][0], pbv[u][1], b0b, b0s);
            bfsplit2(pbv[u][2], pbv[u][3], b1b, b1s);
            *(uint2*)&BsB[fn * BG_BFS + bls * 2] = make_uint2(b0b, b1b);
            *(uint2*)&BsS[fn * BG_BFS + bls * 2] = make_uint2(b0s, b1s);
        }
    };

    stage(sh);
    __syncthreads();

    int wmt = (warp >> 2) * 4;
    int wnt = (warp & 3) * 4;

    for (int it = 0; it < nIter; it++) {
        if (it + 1 < nIter) {
            int k0 = (it + 1) << 4;
            const uint4* Ap = Apack + ((long)(blockIdx.y * (K >> 4) + it + 1) << 8);
            pAb = Ap[tid];
            pAs = Ap[aHalf + tid];
            #pragma unroll
            for (int u = 0; u < 2; u++) {
                int n = u ? bn1 : bn0;
                pbv[u][0] = Bp[(long)(k0 + bK)     * N + n];
                pbv[u][1] = Bp[(long)(k0 + bK + 1) * N + n];
                pbv[u][2] = Bp[(long)(k0 + bK + 8) * N + n];
                pbv[u][3] = Bp[(long)(k0 + bK + 9) * N + n];
            }
        }
        {
            uint32_t* base = sh + (it & 1) * BG_STAGE;
            const uint32_t* AsB = base;
            const uint32_t* AsS = base + BG_AW;
            const uint32_t* BsB = base + 2 * BG_AW;
            const uint32_t* BsS = BsB + BG_BW;
            uint2 bB[4], bS[4];
            #pragma unroll
            for (int nt = 0; nt < 4; nt++) {
                bB[nt] = *(const uint2*)&BsB[(wnt + nt) * BG_BFS + lane * 2];
                bS[nt] = *(const uint2*)&BsS[(wnt + nt) * BG_BFS + lane * 2];
            }
            #pragma unroll
            for (int mt = 0; mt < 4; mt++) {
                uint4 aB = *(const uint4*)&AsB[(wmt + mt) * BG_AFS + lane * 4];
                uint4 aS = *(const uint4*)&AsS[(wmt + mt) * BG_AFS + lane * 4];
                #pragma unroll
                for (int nt = 0; nt < 4; nt++)
                    MMA_BF16(acc[mt][nt], aB.x, aB.y, aB.z, aB.w, bB[nt].x, bB[nt].y);
                #pragma unroll
                for (int nt = 0; nt < 4; nt++)
                    MMA_BF16(acc[mt][nt], aB.x, aB.y, aB.z, aB.w, bS[nt].x, bS[nt].y);
                #pragma unroll
                for (int nt = 0; nt < 4; nt++)
                    MMA_BF16(acc[mt][nt], aS.x, aS.y, aS.z, aS.w, bB[nt].x, bB[nt].y);
            }
        }
        if (it + 1 < nIter) stage(sh + ((it + 1) & 1) * BG_STAGE);
        __syncthreads();
    }

    int by = blockIdx.y * 128;
    int wm = (warp >> 2) * 64, wn = (warp & 3) * 32;
    int mr = lane >> 2, qc = (lane & 3) * 2;
    #pragma unroll
    for (int mt = 0; mt < 4; mt++) {
        int r0 = by + wm + mt * 16 + mr;
        float bb0 = bias ? bias[r0] : 0.f;
        float bb1 = bias ? bias[r0 + 8] : 0.f;
        #pragma unroll
        for (int nt = 0; nt < 4; nt++) {
            int c = bx + wn + nt * 8 + qc;
            long o0 = (long)r0 * N + c;
            long o1 = (long)(r0 + 8) * N + c;
            float2 v0 = make_float2(acc[mt][nt][0] + bb0, acc[mt][nt][1] + bb0);
            float2 v1 = make_float2(acc[mt][nt][2] + bb1, acc[mt][nt][3] + bb1);
            if (res) {
                const float* rp = res + (long)blockIdx.z * strideRes;
                v0.x += rp[o0]; v0.y += rp[o0 + 1];
                v1.x += rp[o1]; v1.y += rp[o1 + 1];
            }
            *(float2*)&Cp[o0] = v0;
            *(float2*)&Cp[o1] = v1;
        }
    }
}

// =====================================================================
// single-pass TF32 GEMM (ff1/ff2), pre-packed weights.
// =====================================================================

#define MMA_TF32(c, a0, a1, a2, a3, b0, b1) \
    asm volatile("mma.sync.aligned.m16n8k8.row.col.f32.tf32.tf32.f32 " \
        "{%0,%1,%2,%3}, {%4,%5,%6,%7}, {%8,%9}, {%0,%1,%2,%3};" \
        : "+f"((c)[0]), "+f"((c)[1]), "+f"((c)[2]), "+f"((c)[3]) \
        : "r"(a0), "r"(a1), "r"(a2), "r"(a3), "r"(b0), "r"(b1))

#define AFRAG_STRIDE 132
#define BFRAG_STRIDE 66
#define AWORDS (16 * AFRAG_STRIDE)
#define BWORDS (32 * BFRAG_STRIDE)
#define TGEMM_STAGE (AWORDS + BWORDS)
#define TGEMM_SMEM (2 * TGEMM_STAGE * 4)

__global__ __launch_bounds__(256, 2) void tgemm_kernel(
    const uint4* __restrict__ Apack, const float* __restrict__ B, float* __restrict__ C,
    int M, int N, int K, long strideB, long strideC,
    const float* __restrict__ bias, const float* __restrict__ res, long strideRes)
{
    extern __shared__ uint32_t sh[];
    int tid = threadIdx.x;
    int lane = tid & 31, warp = tid >> 5;
    int bx = blockIdx.x * 128;
    const float* Bp = B + (long)blockIdx.z * strideB;
    float*       Cp = C + (long)blockIdx.z * strideC;

    float acc[4][4][4];
    #pragma unroll
    for (int i = 0; i < 4; i++)
        #pragma unroll
        for (int j = 0; j < 4; j++)
            #pragma unroll
            for (int k = 0; k < 4; k++) acc[i][j][k] = 0.f;

    int sA0f = tid >> 5;
    int sA1f = (tid + 256) >> 5;
    int bK0 = tid >> 5, bN0 = (tid & 31) * 4;
    int bK1 = (tid + 256) >> 5, bN1 = (tid & 31) * 4;

    uint4 pA0, pA1;
    float4 pb[2];

    {
        const uint4* Ap = Apack + ((long)(blockIdx.y * (K >> 4)) << 9);
        pA0 = Ap[tid];
        pA1 = Ap[tid + 256];
        pb[0] = *(const float4*)(Bp + (long)bK0 * N + bx + bN0);
        pb[1] = *(const float4*)(Bp + (long)bK1 * N + bx + bN1);
    }

    int nIter = K >> 4;

    auto stage = [&](uint32_t* base) {
        uint32_t* AsB = base;
        uint32_t* BsB = base + AWORDS;
        *(uint4*)&AsB[sA0f * AFRAG_STRIDE + (tid & 31) * 4] = pA0;
        *(uint4*)&AsB[sA1f * AFRAG_STRIDE + (tid & 31) * 4] = pA1;
        #pragma unroll
        for (int u = 0; u < 2; u++) {
            int kb = u ? bK1 : bK0, nb = u ? bN1 : bN0;
            float bv[4] = { pb[u].x, pb[u].y, pb[u].z, pb[u].w };
            #pragma unroll
            for (int j = 0; j < 4; j++) {
                int n = nb + j;
                int fB = (n >> 3) * 2 + (kb >> 3);
                int bl = ((n & 7) << 2) | (kb & 3);
                int rg = (kb >> 2) & 1;
                BsB[fB * BFRAG_STRIDE + bl * 2 + rg] = f2tf(bv[j]);
            }
        }
    };

    stage(sh);
    __syncthreads();

    int wmt = (warp >> 2) * 4;
    int wnt = (warp & 3) * 4;

    for (int it = 0; it < nIter; it++) {
        if (it + 1 < nIter) {
            int k0 = (it + 1) << 4;
            const uint4* Ap = Apack + ((long)(blockIdx.y * (K >> 4) + it + 1) << 9);
            pA0 = Ap[tid];
            pA1 = Ap[tid + 256];
            pb[0] = *(const float4*)(Bp + (long)(k0 + bK0) * N + bx + bN0);
            pb[1] = *(const float4*)(Bp + (long)(k0 + bK1) * N + bx + bN1);
        }
        {
            uint32_t* base = sh + (it & 1) * TGEMM_STAGE;
            const uint32_t* AsB = base;
            const uint32_t* BsB = base + AWORDS;
            #pragma unroll
            for (int ks = 0; ks < 2; ks++) {
                uint2 bB[4];
                #pragma unroll
                for (int nt = 0; nt < 4; nt++) {
                    int fB = (wnt + nt) * 2 + ks;
                    bB[nt] = *(const uint2*)&BsB[fB * BFRAG_STRIDE + lane * 2];
                }
                #pragma unroll
                for (int mt = 0; mt < 4; mt++) {
                    int fA = (wmt + mt) * 2 + ks;
                    uint4 aB = *(const uint4*)&AsB[fA * AFRAG_STRIDE + lane * 4];
                    #pragma unroll
                    for (int nt = 0; nt < 4; nt++)
                        MMA_TF32(acc[mt][nt], aB.x, aB.y, aB.z, aB.w, bB[nt].x, bB[nt].y);
                }
            }
        }
        if (it + 1 < nIter) stage(sh + ((it + 1) & 1) * TGEMM_STAGE);
        __syncthreads();
    }

    int by = blockIdx.y * 128;
    int wm = (warp >> 2) * 64, wn = (warp & 3) * 32;
    int mr = lane >> 2, qc = (lane & 3) * 2;
    #pragma unroll
    for (int mt = 0; mt < 4; mt++) {
        int r0 = by + wm + mt * 16 + mr;
        float bb0 = bias ? bias[r0] : 0.f;
        float bb1 = bias ? bias[r0 + 8] : 0.f;
        #pragma unroll
        for (int nt = 0; nt < 4; nt++) {
            int c = bx + wn + nt * 8 + qc;
            long o0 = (long)r0 * N + c;
            long o1 = (long)(r0 + 8) * N + c;
            float2 v0 = make_float2(acc[mt][nt][0] + bb0, acc[mt][nt][1] + bb0);
            float2 v1 = make_float2(acc[mt][nt][2] + bb1, acc[mt][nt][3] + bb1);
            if (res) {
                const float* rp = res + (long)blockIdx.z * strideRes;
                v0.x += rp[o0]; v0.y += rp[o0 + 1];
                v1.x += rp[o1]; v1.y += rp[o1 + 1];
            }
            *(float2*)&Cp[o0] = v0;
            *(float2*)&Cp[o1] = v1;
        }
    }
}

// ---------------- l2-normalize q,k rows (along W=64) in place + row sums -----------
__global__ __launch_bounds__(256) void l2norm_kernel(float* __restrict__ qkv,
                                                     float* __restrict__ qrow,
                                                     float* __restrict__ kh)
{
    int gt = blockIdx.x * 256 + threadIdx.x;
    int warp = gt >> 5, lane = gt & 31;
    if (warp >= BD * 512 * WID) return;
    int b = warp / (512 * WID);
    int rem = warp % (512 * WID);
    float* p = qkv + (long)b * 768 * HW + (long)rem * WID;
    float v0 = p[lane], v1 = p[lane + 32];
    float s = v0 * v0 + v1 * v1;
    float t = v0 + v1;
    #pragma unroll
    for (int o = 16; o > 0; o >>= 1) {
        s += __shfl_xor_sync(0xffffffffu, s, o);
        t += __shfl_xor_sync(0xffffffffu, t, o);
    }
    float scale = 1.f / fmaxf(sqrtf(s), 1e-12f);
    p[lane] = v0 * scale; p[lane + 32] = v1 * scale;
    if (lane == 0) {
        int c = rem >> 6, h = rem & 63;
        float rowsum = t * scale;
        if (c < 256) {
            int bh = b * 8 + (c >> 5), d = c & 31;
            qrow[((bh * 32 + d) << 6) | h] = rowsum;
        } else {
            int c2 = c - 256;
            int bh = b * 8 + (c2 >> 5), d = c2 & 31;
            kh[((bh * 32 + d) << 6) | h] = rowsum;
        }
    }
}

// ---------------- q_probe[c] = sum over 64 h-rows of qrow ----------------
__global__ __launch_bounds__(256) void qpsum_kernel(const float* __restrict__ qrow,
                                                    float* __restrict__ qp)
{
    int c = blockIdx.x * 256 + threadIdx.x;          // 0..2047
    const float4* p = (const float4*)(qrow + (c << 6));
    float s = 0.f;
    #pragma unroll
    for (int i = 0; i < 16; i++) {
        float4 v = p[i];
        s += v.x + v.y + v.z + v.w;
    }
    qp[c] = s;
}

// ---------------- score_r + top-16 rows ----------------
__global__ void toph_kernel(const float* __restrict__ qp, const float* __restrict__ kh,
                            int* __restrict__ topH)
{
    __shared__ float sc[64]; __shared__ float qs[32];
    int bh = blockIdx.x, t = threadIdx.x;                  // 64 threads
    if (t < 32) qs[t] = qp[bh * 32 + t];
    __syncthreads();
    float s = 0.f;
    #pragma unroll
    for (int d = 0; d < 32; d++) s += qs[d] * kh[((bh * 32 + d) << 6) + t];
    sc[t] = s;
    __syncthreads();
    if (t == 0) {
        for (int it = 0; it < 16; it++) {
            float best = -3.4e38f; int bi = 0;
            for (int h = 0; h < 64; h++) if (sc[h] > best) { best = sc[h]; bi = h; }
            topH[bh * 16 + it] = bi; sc[bi] = -3.4e38f;
        }
    }
}

// ---------------- gather selected rows of k,v -> kg/vg [bh][d][16][64] -----------------
__global__ __launch_bounds__(256) void gather_rows_kernel(const float* __restrict__ qkv,
                                                          const int* __restrict__ topH,
                                                          float* __restrict__ kg,
                                                          float* __restrict__ vg)
{
    long i = (long)blockIdx.x * 256 + threadIdx.x;          // 64*32*16*64
    int w = i & 63; long r = i >> 6; int t = (int)(r & 15); r >>= 4;
    int d = (int)(r & 31); int bh = (int)(r >> 5);
    int b = bh >> 3, hh = bh & 7;
    int h = topH[bh * 16 + t];
    long base = (long)b * 768 * HW + (long)(hh * 32 + d) * HW + (long)h * WID + w;
    kg[i] = qkv[base + 256L * HW];
    vg[i] = qkv[base + 512L * HW];
}

// ---------------- score_c + top-16 columns ----------------
__global__ void topw_kernel(const float* __restrict__ qp, const float* __restrict__ kg,
                            int* __restrict__ topW)
{
    __shared__ float sc[64]; __shared__ float qs[32];
    int bh = blockIdx.x, t = threadIdx.x;                  // t = w, 64 threads
    if (t < 32) qs[t] = qp[bh * 32 + t];
    __syncthreads();
    float s = 0.f;
    for (int d = 0; d < 32; d++) {
        float colsum = 0.f;
        #pragma unroll
        for (int i = 0; i < 16; i++)
            colsum += kg[(((long)(bh * 32 + d) * 16) + i) * 64 + t];
        s += qs[d] * colsum;
    }
    sc[t] = s;
    __syncthreads();
    if (t == 0) {
        for (int it = 0; it < 16; it++) {
            float best = -3.4e38f; int bi = 0;
            for (int w = 0; w < 64; w++) if (sc[w] > best) { best = sc[w]; bi = w; }
            topW[bh * 16 + it] = bi; sc[bi] = -3.4e38f;
        }
    }
}

// ---------------- build kf (key-major) and vt (dim-major, transposed) ----------------
__global__ __launch_bounds__(256) void build_kv_kernel(const float* __restrict__ kg,
                                                       const float* __restrict__ vg,
                                                       const int* __restrict__ topW,
                                                       uint32_t* __restrict__ kf,
                                                       uint32_t* __restrict__ vt)
{
    int i = blockIdx.x * 256 + threadIdx.x;   // 262144
    {
        int d2 = i & 15; int j = (i >> 4) & 255; int bh = i >> 12;
        int ti = j >> 4, jw = j & 15;
        int w = topW[bh * 16 + jw];
        long src = (((long)(bh * 32 + 2 * d2) * 16) + ti) * 64 + w;
        __nv_bfloat162 kk = __floats2bfloat162_rn(kg[src], kg[src + 1024]);
        kf[i] = *(uint32_t*)&kk;
    }
    {
        int j2 = i & 127; int d = (i >> 7) & 31; int bh = i >> 12;
        int jA = 2 * j2, jB = jA + 1;
        int wA = topW[bh * 16 + (jA & 15)];
        int wB = topW[bh * 16 + (jB & 15)];
        long sA = (((long)(bh * 32 + d) * 16) + (jA >> 4)) * 64 + wA;
        long sB = (((long)(bh * 32 + d) * 16) + (jB >> 4)) * 64 + wB;
        __nv_bfloat162 vv = __floats2bfloat162_rn(vg[sA], vg[sB]);
        vt[i] = *(uint32_t*)&vv;
    }
}

// ---------------- tensor-core sparse attention: softmax(Q Kf^T) Vf ----------------
__global__ __launch_bounds__(256) void attn_kernel(const float* __restrict__ qkv,
                                                   const uint32_t* __restrict__ kf,
                                                   const uint32_t* __restrict__ vt,
                                                   float* __restrict__ out)
{
    __shared__ uint32_t Qs[128 * 20];
    __shared__ uint32_t Ks[256 * 20];
    __shared__ uint32_t Vs[32 * 132];
    int bh = blockIdx.y;
    int b = bh >> 3, hh = bh & 7;
    int p0 = blockIdx.x * 128;
    int tid = threadIdx.x, lane = tid & 31, warp = tid >> 5;
    int g = lane >> 2, t4 = lane & 3;

    const uint4* ksrc = (const uint4*)(kf + (long)bh * NKEY * 16);
    #pragma unroll
    for (int i = tid; i < 1024; i += 256) {
        int j = i >> 2, q4 = i & 3;
        *(uint4*)&Ks[j * 20 + q4 * 4] = ksrc[i];
    }
    const uint4* vsrc = (const uint4*)(vt + (long)bh * 32 * 128);
    #pragma unroll
    for (int i = tid; i < 1024; i += 256) {
        int d = i >> 5, q4 = i & 31;
        *(uint4*)&Vs[d * 132 + q4 * 4] = vsrc[i];
    }
    const float* qb = qkv + (long)b * 768 * HW + (long)(hh * 32) * HW + p0;
    #pragma unroll
    for (int i = tid; i < 2048; i += 256) {
        int row = i & 127, d2 = i >> 7;
        float f0 = qb[(long)(2 * d2) * HW + row];
        float f1 = qb[(long)(2 * d2 + 1) * HW + row];
        __nv_bfloat162 hb = __floats2bfloat162_rn(f0, f1);
        Qs[row * 20 + d2] = *(uint32_t*)&hb;
    }
    __syncthreads();

    int wrow = warp * 16;
    uint32_t qa[2][4];
    #pragma unroll
    for (int ks = 0; ks < 2; ks++) {
        int base = ks * 8;
        qa[ks][0] = Qs[(wrow + g) * 20 + base + t4];
        qa[ks][1] = Qs[(wrow + 8 + g) * 20 + base + t4];
        qa[ks][2] = Qs[(wrow + g) * 20 + base + t4 + 4];
        qa[ks][3] = Qs[(wrow + 8 + g) * 20 + base + t4 + 4];
    }
    float o[4][4];
    #pragma unroll
    for (int i = 0; i < 4; i++)
        #pragma unroll
        for (int j = 0; j < 4; j++) o[i][j] = 0.f;
    float lsum0 = 0.f, lsum1 = 0.f;

    #pragma unroll
    for (int jc = 0; jc < 256; jc += 16) {
        float s0[4] = {0.f, 0.f, 0.f, 0.f}, s1[4] = {0.f, 0.f, 0.f, 0.f};
        #pragma unroll
        for (int ks = 0; ks < 2; ks++) {
            int pb = ks * 8;
            uint32_t b0 = Ks[(jc + g) * 20 + pb + t4];
            uint32_t b1 = Ks[(jc + g) * 20 + pb + t4 + 4];
            MMA_BF16(s0, qa[ks][0], qa[ks][1], qa[ks][2], qa[ks][3], b0, b1);
            uint32_t b2 = Ks[(jc + 8 + g) * 20 + pb + t4];
            uint32_t b3 = Ks[(jc + 8 + g) * 20 + pb + t4 + 4];
            MMA_BF16(s1, qa[ks][0], qa[ks][1], qa[ks][2], qa[ks][3], b2, b3);
        }
        float e00 = __expf(s0[0]), e01 = __expf(s0[1]);
        float e02 = __expf(s0[2]), e03 = __expf(s0[3]);
        float e10 = __expf(s1[0]), e11 = __expf(s1[1]);
        float e12 = __expf(s1[2]), e13 = __expf(s1[3]);
        lsum0 += e00 + e01 + e10 + e11;
        lsum1 += e02 + e03 + e12 + e13;
        __nv_bfloat162 pb0 = __floats2bfloat162_rn(e00, e01);
        __nv_bfloat162 pb1 = __floats2bfloat162_rn(e02, e03);
        __nv_bfloat162 pb2 = __floats2bfloat162_rn(e10, e11);
        __nv_bfloat162 pb3 = __floats2bfloat162_rn(e12, e13);
        uint32_t pa0 = *(uint32_t*)&pb0, pa1 = *(uint32_t*)&pb1;
        uint32_t pa2 = *(uint32_t*)&pb2, pa3 = *(uint32_t*)&pb3;
        int j2 = jc >> 1;
        #pragma unroll
        for (int nt = 0; nt < 4; nt++) {
            uint32_t vb0 = Vs[(nt * 8 + g) * 132 + j2 + t4];
            uint32_t vb1 = Vs[(nt * 8 + g) * 132 + j2 + t4 + 4];
            MMA_BF16(o[nt], pa0, pa1, pa2, pa3, vb0, vb1);
        }
    }
    lsum0 += __shfl_xor_sync(0xffffffffu, lsum0, 1);
    lsum0 += __shfl_xor_sync(0xffffffffu, lsum0, 2);
    lsum1 += __shfl_xor_sync(0xffffffffu, lsum1, 1);
    lsum1 += __shfl_xor_sync(0xffffffffu, lsum1, 2);
    float inv0 = 1.f / lsum0, inv1 = 1.f / lsum1;
    float* ob = out + (long)b * CDIM * HW + (long)(hh * 32) * HW + p0;
    int r0 = wrow + g, r1 = r0 + 8;
    #pragma unroll
    for (int nt = 0; nt < 4; nt++) {
        int d = nt * 8 + 2 * t4;
        ob[(long)d * HW + r0]       = o[nt][0] * inv0;
        ob[(long)(d + 1) * HW + r0] = o[nt][1] * inv0;
        ob[(long)d * HW + r1]       = o[nt][2] * inv1;
        ob[(long)(d + 1) * HW + r1] = o[nt][3] * inv1;
    }
}

// ---------------- depthwise 3x3 SAME (small branch, writes into cat) ----------------
__global__ __launch_bounds__(256) void dwconv_kernel(const float* __restrict__ in,
                                                     const float* __restrict__ w,
                                                     const float* __restrict__ bias,
                                                     float* __restrict__ out,
                                                     int C, long inBS, long outBS, int chanOff)
{
    int idx = blockIdx.x;
    int yt = idx & 15; idx >>= 4;
    int c = idx % C; int b = idx / C;
    int x = threadIdx.x & 63;
    int y = yt * 4 + (threadIdx.x >> 6);
    const float* ip = in + (long)b * inBS + (long)c * HW;
    const float* wp = w + c * 9;
    float s = bias[c];
    #pragma unroll
    for (int dy = 0; dy < 3; dy++) {
        int yy = y + dy - 1;
        if (yy < 0 || yy > 63) continue;
        #pragma unroll
        for (int dx = 0; dx < 3; dx++) {
            int xx = x + dx - 1;
            if (xx < 0 || xx > 63) continue;
            s += wp[dy * 3 + dx] * ip[yy * 64 + xx];
        }
    }
    out[(long)b * outBS + (long)(chanOff + c) * HW + y * 64 + x] = s;
}

// ---------------- gelu ----------------
__device__ __forceinline__ float gelu_exact(float u)
{
    return 0.5f * u * (1.f + erff(u * 0.7071067811865476f));
}

// ---------------- fused: hg=gelu(IN(h)); h = hg + gelu(IN(dw(hg)))  (in place) -----
__global__ __launch_bounds__(256) void dwin2_kernel(float* __restrict__ h,
                                                    const float* __restrict__ w,
                                                    const float* __restrict__ bias)
{
    __shared__ float tile[HW];
    __shared__ float red[16];
    long row = blockIdx.x;
    int c = (int)(row & (FFI - 1));
    int t = threadIdx.x;
    float* hp = h + row * HW;

    float4 v[4];
    float s = 0.f, s2 = 0.f;
    #pragma unroll
    for (int i = 0; i < 4; i++) {
        v[i] = ((const float4*)hp)[t + i * 256];
        s  += v[i].x + v[i].y + v[i].z + v[i].w;
        s2 += v[i].x * v[i].x + v[i].y * v[i].y + v[i].z * v[i].z + v[i].w * v[i].w;
    }
    #pragma unroll
    for (int o = 16; o > 0; o >>= 1) {
        s  += __shfl_xor_sync(0xffffffffu, s, o);
        s2 += __shfl_xor_sync(0xffffffffu, s2, o);
    }
    if ((t & 31) == 0) { red[t >> 5] = s; red[8 + (t >> 5)] = s2; }
    __syncthreads();
    if (t == 0) {
        float a = 0.f, b2 = 0.f;
        for (int i = 0; i < 8; i++) { a += red[i]; b2 += red[8 + i]; }
        red[0] = a; red[8] = b2;
    }
    __syncthreads();
    float mean = red[0] * (1.f / HW);
    float var  = red[8] * (1.f / HW) - mean * mean;
    float inv  = rsqrtf(var + 1e-5f);

    float wr[9];
    #pragma unroll
    for (int i = 0; i < 9; i++) wr[i] = w[c * 9 + i];
    float bb = bias[c];

    #pragma unroll
    for (int i = 0; i < 4; i++) {
        float4 u = v[i];
        u.x = gelu_exact((u.x - mean) * inv);
        u.y = gelu_exact((u.y - mean) * inv);
        u.z = gelu_exact((u.z - mean) * inv);
        u.w = gelu_exact((u.w - mean) * inv);
        ((float4*)tile)[t + i * 256] = u;
    }
    __syncthreads();

    float r[16];
    float q = 0.f, q2 = 0.f;
    #pragma unroll
    for (int i = 0; i < 16; i++) {
        int px = t + i * 256;
        int y = px >> 6, x = px & 63;
        float a = bb;
        #pragma unroll
        for (int dy = 0; dy < 3; dy++) {
            int yy = y + dy - 1;
            if (yy < 0 || yy > 63) continue;
            #pragma unroll
            for (int dx = 0; dx < 3; dx++) {
                int xx = x + dx - 1;
                if (xx < 0 || xx > 63) continue;
                a += wr[dy * 3 + dx] * tile[yy * 64 + xx];
            }
        }
        r[i] = a; q += a; q2 += a * a;
    }
    #pragma unroll
    for (int o = 16; o > 0; o >>= 1) {
        q  += __shfl_xor_sync(0xffffffffu, q, o);
        q2 += __shfl_xor_sync(0xffffffffu, q2, o);
    }
    if ((t & 31) == 0) { red[t >> 5] = q; red[8 + (t >> 5)] = q2; }
    __syncthreads();
    if (t == 0) {
        float a = 0.f, b2 = 0.f;
        for (int i = 0; i < 8; i++) { a += red[i]; b2 += red[8 + i]; }
        red[0] = a; red[8] = b2;
    }
    __syncthreads();
    float mean2 = red[0] * (1.f / HW);
    float var2  = red[8] * (1.f / HW) - mean2 * mean2;
    float inv2  = rsqrtf(var2 + 1e-5f);
    #pragma unroll
    for (int i = 0; i < 16; i++) {
        int px = t + i * 256;
        hp[px] = tile[px] + gelu_exact((r[i] - mean2) * inv2);
    }
}

// ---------------- instance norm (final) ----------------
__global__ __launch_bounds__(256) void instnorm_kernel(const float* __restrict__ in,
                                                       float* __restrict__ out)
{
    __shared__ float sm[16];
    long row = blockIdx.x;
    const float4* p = (const float4*)(in + row * HW);
    int t = threadIdx.x;
    float4 v[4];
    float s = 0.f, s2 = 0.f;
    #pragma unroll
    for (int i = 0; i < 4; i++) {
        v[i] = p[t + i * 256];
        s  += v[i].x + v[i].y + v[i].z + v[i].w;
        s2 += v[i].x * v[i].x + v[i].y * v[i].y + v[i].z * v[i].z + v[i].w * v[i].w;
    }
    #pragma unroll
    for (int o = 16; o > 0; o >>= 1) {
        s  += __shfl_xor_sync(0xffffffffu, s, o);
        s2 += __shfl_xor_sync(0xffffffffu, s2, o);
    }
    if ((t & 31) == 0) { sm[t >> 5] = s; sm[8 + (t >> 5)] = s2; }
    __syncthreads();
    if (t == 0) {
        float a = 0.f, b2 = 0.f;
        for (int i = 0; i < 8; i++) { a += sm[i]; b2 += sm[8 + i]; }
        sm[0] = a; sm[8] = b2;
    }
    __syncthreads();
    float mean = sm[0] * (1.f / HW);
    float var  = sm[8] * (1.f / HW) - mean * mean;
    float inv  = rsqrtf(var + 1e-5f);
    float4* op = (float4*)(out + row * HW);
    #pragma unroll
    for (int i = 0; i < 4; i++) {
        float4 u = v[i];
        u.x = (u.x - mean) * inv; u.y = (u.y - mean) * inv;
        u.z = (u.z - mean) * inv; u.w = (u.w - mean) * inv;
        op[t + i * 256] = u;
    }
}

// ---------------- host launcher ----------------
extern "C" void kernel_launch(void* const* d_in, const int* in_sizes, int n_in,
                              void* d_out, int out_size)
{
    (void)in_sizes; (void)n_in; (void)out_size;
    const float* x      = (const float*)d_in[0];
    const float* ln_g   = (const float*)d_in[1];
    const float* ln_b   = (const float*)d_in[2];
    const float* w_qkv  = (const float*)d_in[3];
    const float* w_out  = (const float*)d_in[4];
    const float* b_out  = (const float*)d_in[5];
    const float* w_dw   = (const float*)d_in[6];
    const float* b_dw   = (const float*)d_in[7];
    const float* w_comb = (const float*)d_in[8];
    const float* b_comb = (const float*)d_in[9];
    const float* w_ff1  = (const float*)d_in[10];
    const float* b_ff1  = (const float*)d_in[11];
    const float* w_ffdw = (const float*)d_in[12];
    const float* b_ffdw = (const float*)d_in[13];
    const float* w_ff2  = (const float*)d_in[14];
    const float* b_ff2  = (const float*)d_in[15];
    float* out = (float*)d_out;

    void *p;
    cudaGetSymbolAddress(&p, g_xn);   float* xn   = (float*)p;
    cudaGetSymbolAddress(&p, g_qkv);  float* qkv  = (float*)p;
    cudaGetSymbolAddress(&p, g_attn); float* attn = (float*)p;
    cudaGetSymbolAddress(&p, g_cat);  float* cat  = (float*)p;
    cudaGetSymbolAddress(&p, g_ao);   float* ao   = (float*)p;
    cudaGetSymbolAddress(&p, g_h);    float* h    = (float*)p;
    cudaGetSymbolAddress(&p, g_kg);   float* kg   = (float*)p;
    cudaGetSymbolAddress(&p, g_vg);   float* vg   = (float*)p;
    cudaGetSymbolAddress(&p, g_kf);   uint32_t* kf = (uint32_t*)p;
    cudaGetSymbolAddress(&p, g_vt);   uint32_t* vt = (uint32_t*)p;
    cudaGetSymbolAddress(&p, g_qp);   float* qp   = (float*)p;
    cudaGetSymbolAddress(&p, g_kh);   float* kh   = (float*)p;
    cudaGetSymbolAddress(&p, g_qrow); float* qrow = (float*)p;
    cudaGetSymbolAddress(&p, g_topH); int*   topH = (int*)p;
    cudaGetSymbolAddress(&p, g_topW); int*   topW = (int*)p;
    cudaGetSymbolAddress(&p, g_wqkv_p);  uint4* wqkv_p  = (uint4*)p;
    cudaGetSymbolAddress(&p, g_wout_p);  uint4* wout_p  = (uint4*)p;
    cudaGetSymbolAddress(&p, g_wcomb_p); uint4* wcomb_p = (uint4*)p;
    cudaGetSymbolAddress(&p, g_wff1_p);  uint4* wff1_p  = (uint4*)p;
    cudaGetSymbolAddress(&p, g_wff2_p);  uint4* wff2_p  = (uint4*)p;

    cudaFuncSetAttribute(bgemm_kernel, cudaFuncAttributeMaxDynamicSharedMemorySize,
                         BGEMM_SMEM);
    cudaFuncSetAttribute(tgemm_kernel, cudaFuncAttributeMaxDynamicSharedMemorySize,
                         TGEMM_SMEM);

    // 0. pre-pack weights into fragment layouts (runs inside graph; deterministic)
    pack_bw_kernel<<<96, 256>>>(w_qkv,  wqkv_p,  768, 256);
    pack_bw_kernel<<<32, 256>>>(w_out,  wout_p,  256, 256);
    pack_bw_kernel<<<64, 256>>>(w_comb, wcomb_p, 256, 512);
    pack_tw_kernel<<<256, 256>>>(w_ff1, wff1_p, 1024, 256);
    pack_tw_kernel<<<256, 256>>>(w_ff2, wff2_p, 256, 1024);

    // 1. channel layernorm
    ln_kernel<<<128, 256>>>(x, ln_g, ln_b, xn);
    // 2. qkv projection (bf16x3)
    bgemm_kernel<<<dim3(32, 6, BD), 256, BGEMM_SMEM>>>(wqkv_p, xn, qkv, 768, HW, 256,
                                           (long)CDIM * HW, (long)768 * HW,
                                           nullptr, nullptr, 0);
    // 3. l2-normalize q,k (in place) + emit row sums
    l2norm_kernel<<<32768, 256>>>(qkv, qrow, kh);
    // 4. probes + top-k selection
    qpsum_kernel<<<8, 256>>>(qrow, qp);
    toph_kernel<<<64, 64>>>(qp, kh, topH);
    gather_rows_kernel<<<8192, 256>>>(qkv, topH, kg, vg);
    topw_kernel<<<64, 64>>>(qp, kg, topW);
    build_kv_kernel<<<1024, 256>>>(kg, vg, topW, kf, vt);
    // 5. tensor-core sparse attention
    attn_kernel<<<dim3(32, NBH), 256>>>(qkv, kf, vt, attn);
    // 6. out-proj into concat buffer rows [0,256)  (bf16x3)
    bgemm_kernel<<<dim3(32, 2, BD), 256, BGEMM_SMEM>>>(wout_p, attn, cat, 256, HW, 256,
                                           (long)CDIM * HW, (long)512 * HW,
                                           b_out, nullptr, 0);
    // 7. dwconv branch into concat buffer rows [256,512)
    dwconv_kernel<<<BD * 256 * 16, 256>>>(x, w_dw, b_dw, cat, 256,
                                          (long)CDIM * HW, (long)512 * HW, 256);
    // 8. combine (K=512) + bias + residual x  (bf16x3)
    bgemm_kernel<<<dim3(32, 2, BD), 256, BGEMM_SMEM>>>(wcomb_p, cat, ao, 256, HW, 512,
                                           (long)512 * HW, (long)CDIM * HW,
                                           b_comb, x, (long)CDIM * HW);
    // 9. ff1 (single-pass TF32)
    tgemm_kernel<<<dim3(32, 8, BD), 256, TGEMM_SMEM>>>(wff1_p, ao, h, FFI, HW, 256,
                                           (long)CDIM * HW, (long)FFI * HW,
                                           b_ff1, nullptr, 0);
    // 10-12. h = hg + gelu(IN(dw(hg))) with hg = gelu(IN(h)) -- fused, in place
    dwin2_kernel<<<BD * FFI, 256>>>(h, w_ffdw, b_ffdw);
    // 13. ff2 (single-pass TF32; reuse xn buffer for output)
    tgemm_kernel<<<dim3(32, 2, BD), 256, TGEMM_SMEM>>>(wff2_p, h, xn, 256, HW, 1024,
                                           (long)FFI * HW, (long)CDIM * HW,
                                           b_ff2, nullptr, 0);
    // 14. final instance norm -> d_out
    instnorm_kernel<<<BD * CDIM, 256>>>(xn, out);
}